// round 1
// baseline (speedup 1.0000x reference)
#include <cuda_runtime.h>
#include <math.h>

// ---------------- problem constants ----------------
constexpr int B_    = 8;
constexpr int S_    = 512;
constexpr int D_    = 1024;
constexpr int H_    = 16;
constexpr int DH_   = 64;
constexpr int NST_  = 32;
constexpr int L_    = 2;
constexpr int VOCAB_= 128;
constexpr int M_    = B_ * S_;   // 4096 rows

// ---------------- scratch (static device globals; no allocation) ----------------
__device__ float g_x [M_ * D_];
__device__ float g_xn[M_ * D_];
__device__ float g_q [M_ * D_];
__device__ float g_k [M_ * D_];
__device__ float g_v [M_ * D_];
__device__ float g_g [M_ * D_];
__device__ float g_o [M_ * D_];

// ---------------- embed: x = emb[tok] + pos ----------------
__global__ void embed_kernel(const int* __restrict__ tokens,
                             const float* __restrict__ emb,
                             const float* __restrict__ pos,
                             float* __restrict__ x)
{
    int idx = blockIdx.x * blockDim.x + threadIdx.x;   // over M_*D_/4
    int row = idx / (D_ / 4);
    int c4  = idx % (D_ / 4);
    int s   = row % S_;
    int tok = tokens[row];
    float4 e = reinterpret_cast<const float4*>(emb + (size_t)tok * D_)[c4];
    float4 p = reinterpret_cast<const float4*>(pos + (size_t)s   * D_)[c4];
    e.x += p.x; e.y += p.y; e.z += p.z; e.w += p.w;
    reinterpret_cast<float4*>(x)[idx] = e;
}

// ---------------- layernorm (one row per block, 256 threads) ----------------
__global__ void __launch_bounds__(256)
ln_kernel(const float* __restrict__ x,
          const float* __restrict__ gw,
          const float* __restrict__ bw,
          float* __restrict__ y)
{
    int row = blockIdx.x;
    int t   = threadIdx.x;                       // 256 threads * 4 = 1024 = D_
    float4 xv = reinterpret_cast<const float4*>(x + (size_t)row * D_)[t];

    float s  = xv.x + xv.y + xv.z + xv.w;
    float ss = xv.x*xv.x + xv.y*xv.y + xv.z*xv.z + xv.w*xv.w;

    #pragma unroll
    for (int o = 16; o; o >>= 1) {
        s  += __shfl_xor_sync(0xffffffffu, s,  o);
        ss += __shfl_xor_sync(0xffffffffu, ss, o);
    }
    __shared__ float sh_s[8], sh_ss[8];
    int w = t >> 5;
    if ((t & 31) == 0) { sh_s[w] = s; sh_ss[w] = ss; }
    __syncthreads();

    __shared__ float s_mean, s_inv;
    if (w == 0) {
        s  = (t < 8) ? sh_s[t]  : 0.f;
        ss = (t < 8) ? sh_ss[t] : 0.f;
        #pragma unroll
        for (int o = 4; o; o >>= 1) {
            s  += __shfl_xor_sync(0xffffffffu, s,  o);
            ss += __shfl_xor_sync(0xffffffffu, ss, o);
        }
        if (t == 0) {
            float mean = s * (1.f / D_);
            float var  = ss * (1.f / D_) - mean * mean;
            s_mean = mean;
            s_inv  = rsqrtf(var + 1e-5f);
        }
    }
    __syncthreads();
    float mean = s_mean, inv = s_inv;

    float4 gv = reinterpret_cast<const float4*>(gw)[t];
    float4 bv = reinterpret_cast<const float4*>(bw)[t];
    float4 out;
    out.x = (xv.x - mean) * inv * gv.x + bv.x;
    out.y = (xv.y - mean) * inv * gv.y + bv.y;
    out.z = (xv.z - mean) * inv * gv.z + bv.z;
    out.w = (xv.w - mean) * inv * gv.w + bv.w;
    reinterpret_cast<float4*>(y + (size_t)row * D_)[t] = out;
}

// ---------------- SGEMM: C[m,n] = sum_k A[m,k]*W[n,k] + bias[n] (+ res[m,n]) ----
// BM=BN=128, BK=8, 256 threads, 8x8 per thread. All dims assumed multiples.
__global__ void __launch_bounds__(256)
sgemm_nt(const float* __restrict__ A, const float* __restrict__ W,
         const float* __restrict__ bias, const float* __restrict__ res,
         float* __restrict__ C, int Mm, int Nn, int Kk)
{
    constexpr int BM = 128, BN = 128, BK = 8, TM = 8, TN = 8;
    __shared__ float As[BK][BM];
    __shared__ float Ws[BK][BN];

    const int bm = blockIdx.y * BM;
    const int bn = blockIdx.x * BN;
    const int t  = threadIdx.x;

    // loader mapping: 256 threads -> 128 rows x 2 float4 (BK=8 floats/row)
    const int lrow = t >> 1;
    const int lcol = (t & 1) * 4;

    // compute mapping: 16x16 thread grid, 8x8 microtile
    const int tm = (t >> 4) * TM;
    const int tn = (t & 15) * TN;

    float acc[TM][TN] = {};

    const float* Ap = A + (size_t)(bm + lrow) * Kk + lcol;
    const float* Wp = W + (size_t)(bn + lrow) * Kk + lcol;

    for (int k0 = 0; k0 < Kk; k0 += BK) {
        float4 a = *reinterpret_cast<const float4*>(Ap + k0);
        float4 w = *reinterpret_cast<const float4*>(Wp + k0);
        As[lcol + 0][lrow] = a.x; As[lcol + 1][lrow] = a.y;
        As[lcol + 2][lrow] = a.z; As[lcol + 3][lrow] = a.w;
        Ws[lcol + 0][lrow] = w.x; Ws[lcol + 1][lrow] = w.y;
        Ws[lcol + 2][lrow] = w.z; Ws[lcol + 3][lrow] = w.w;
        __syncthreads();

        #pragma unroll
        for (int kk = 0; kk < BK; kk++) {
            float ra[TM], rb[TN];
            float4 a0 = *reinterpret_cast<const float4*>(&As[kk][tm]);
            float4 a1 = *reinterpret_cast<const float4*>(&As[kk][tm + 4]);
            float4 b0 = *reinterpret_cast<const float4*>(&Ws[kk][tn]);
            float4 b1 = *reinterpret_cast<const float4*>(&Ws[kk][tn + 4]);
            ra[0]=a0.x; ra[1]=a0.y; ra[2]=a0.z; ra[3]=a0.w;
            ra[4]=a1.x; ra[5]=a1.y; ra[6]=a1.z; ra[7]=a1.w;
            rb[0]=b0.x; rb[1]=b0.y; rb[2]=b0.z; rb[3]=b0.w;
            rb[4]=b1.x; rb[5]=b1.y; rb[6]=b1.z; rb[7]=b1.w;
            #pragma unroll
            for (int i = 0; i < TM; i++)
                #pragma unroll
                for (int j = 0; j < TN; j++)
                    acc[i][j] = fmaf(ra[i], rb[j], acc[i][j]);
        }
        __syncthreads();
    }

    #pragma unroll
    for (int i = 0; i < TM; i++) {
        const int row = bm + tm + i;
        #pragma unroll
        for (int j = 0; j < TN; j += 4) {
            const int col = bn + tn + j;
            float4 r;
            r.x = acc[i][j + 0] + bias[col + 0];
            r.y = acc[i][j + 1] + bias[col + 1];
            r.z = acc[i][j + 2] + bias[col + 2];
            r.w = acc[i][j + 3] + bias[col + 3];
            if (res) {
                float4 rv = *reinterpret_cast<const float4*>(&res[(size_t)row * Nn + col]);
                r.x += rv.x; r.y += rv.y; r.z += rv.z; r.w += rv.w;
            }
            *reinterpret_cast<float4*>(&C[(size_t)row * Nn + col]) = r;
        }
    }
}

// ---------------- linear-attention scan + SiLU gate ----------------
// one block per (b,h); 64 threads; thread j owns state column h[:,j] (32 regs)
__global__ void __launch_bounds__(64)
scan_kernel(const float* __restrict__ Q, const float* __restrict__ K,
            const float* __restrict__ V, const float* __restrict__ G,
            const float* __restrict__ alog, float* __restrict__ O)
{
    const int bh = blockIdx.x;
    const int b  = bh / H_;
    const int h  = bh % H_;
    const int j  = threadIdx.x;

    __shared__ float sk[NST_], sq[NST_];

    float alpha[NST_];
    #pragma unroll
    for (int i = 0; i < NST_; i++)
        alpha[i] = 1.f / (1.f + expf(-alog[h * NST_ + i]));

    float hst[NST_];
    #pragma unroll
    for (int i = 0; i < NST_; i++) hst[i] = 0.f;

    size_t base = ((size_t)b * S_ * H_ + h) * DH_;
    const size_t strideS = (size_t)H_ * DH_;

    for (int s = 0; s < S_; s++) {
        if (j < NST_) { sk[j] = K[base + j]; sq[j] = Q[base + j]; }
        __syncthreads();
        const float v = V[base + j];
        float o = 0.f;
        #pragma unroll
        for (int i = 0; i < NST_; i++) {
            hst[i] = fmaf(alpha[i], hst[i], sk[i] * v);
            o = fmaf(sq[i], hst[i], o);
        }
        const float gg = G[base + j];
        O[base + j] = o * gg / (1.f + expf(-gg));
        __syncthreads();
        base += strideS;
    }
}

// ---------------- launch ----------------
extern "C" void kernel_launch(void* const* d_in, const int* in_sizes, int n_in,
                              void* d_out, int out_size)
{
    const int*   tokens   = (const int*)  d_in[0];
    const float* emb      = (const float*)d_in[1];
    const float* pos      = (const float*)d_in[2];
    const float* ln_g     = (const float*)d_in[3];
    const float* ln_b     = (const float*)d_in[4];
    const float* wq       = (const float*)d_in[5];
    const float* bq       = (const float*)d_in[6];
    const float* wk       = (const float*)d_in[7];
    const float* bk       = (const float*)d_in[8];
    const float* wv       = (const float*)d_in[9];
    const float* bv       = (const float*)d_in[10];
    const float* wg       = (const float*)d_in[11];
    const float* bg       = (const float*)d_in[12];
    const float* wo       = (const float*)d_in[13];
    const float* bo       = (const float*)d_in[14];
    const float* alogit   = (const float*)d_in[15];
    const float* fn_g     = (const float*)d_in[16];
    const float* fn_b     = (const float*)d_in[17];
    const float* head_w   = (const float*)d_in[18];
    const float* head_b   = (const float*)d_in[19];
    float*       out      = (float*)d_out;

    float *px, *pxn, *pq, *pk, *pv, *pg, *po;
    cudaGetSymbolAddress((void**)&px,  g_x);
    cudaGetSymbolAddress((void**)&pxn, g_xn);
    cudaGetSymbolAddress((void**)&pq,  g_q);
    cudaGetSymbolAddress((void**)&pk,  g_k);
    cudaGetSymbolAddress((void**)&pv,  g_v);
    cudaGetSymbolAddress((void**)&pg,  g_g);
    cudaGetSymbolAddress((void**)&po,  g_o);

    // x = emb[tokens] + pos
    embed_kernel<<<(M_ * D_ / 4) / 256, 256>>>(tokens, emb, pos, px);

    const dim3 gemm_grid(D_ / 128, M_ / 128);      // 8 x 32
    const dim3 head_grid(VOCAB_ / 128, M_ / 128);  // 1 x 32

    for (int l = 0; l < L_; l++) {
        const float* Wq = wq + (size_t)l * D_ * D_;
        const float* Wk = wk + (size_t)l * D_ * D_;
        const float* Wv = wv + (size_t)l * D_ * D_;
        const float* Wg = wg + (size_t)l * D_ * D_;
        const float* Wo = wo + (size_t)l * D_ * D_;

        ln_kernel<<<M_, 256>>>(px, ln_g + l * D_, ln_b + l * D_, pxn);

        sgemm_nt<<<gemm_grid, 256>>>(pxn, Wq, bq + l * D_, nullptr, pq, M_, D_, D_);
        sgemm_nt<<<gemm_grid, 256>>>(pxn, Wk, bk + l * D_, nullptr, pk, M_, D_, D_);
        sgemm_nt<<<gemm_grid, 256>>>(pxn, Wv, bv + l * D_, nullptr, pv, M_, D_, D_);
        sgemm_nt<<<gemm_grid, 256>>>(pxn, Wg, bg + l * D_, nullptr, pg, M_, D_, D_);

        scan_kernel<<<B_ * H_, DH_>>>(pq, pk, pv, pg, alogit + (size_t)l * H_ * NST_, po);

        // x = x + (o @ Wo^T + bo)   (in place: res = x, C = x)
        sgemm_nt<<<gemm_grid, 256>>>(po, Wo, bo + l * D_, px, px, M_, D_, D_);
    }

    ln_kernel<<<M_, 256>>>(px, fn_g, fn_b, pxn);
    sgemm_nt<<<head_grid, 256>>>(pxn, head_w, head_b, nullptr, out, M_, VOCAB_, D_);
}

// round 3
// speedup vs baseline: 1.4988x; 1.4988x over previous
#include <cuda_runtime.h>
#include <cuda_bf16.h>
#include <math.h>
#include <stdint.h>

// ---------------- problem constants ----------------
constexpr int B_    = 8;
constexpr int S_    = 512;
constexpr int D_    = 1024;
constexpr int H_    = 16;
constexpr int DH_   = 64;
constexpr int NST_  = 32;
constexpr int L_    = 2;
constexpr int VOCAB_= 128;
constexpr int M_    = B_ * S_;   // 4096
constexpr int K_    = D_;        // 1024
constexpr int BKc_  = 32;        // K per stage
constexpr int NS_   = K_ / BKc_; // 32 stages

// ---------------- scratch (static device globals) ----------------
__device__ float g_x [M_ * D_];
__device__ float g_q [M_ * D_];
__device__ float g_k [M_ * D_];
__device__ float g_v [M_ * D_];
__device__ float g_gt[M_ * D_];
__device__ __nv_bfloat16 g_xn_hi[M_ * D_], g_xn_lo[M_ * D_];
__device__ __nv_bfloat16 g_o_hi [M_ * D_], g_o_lo [M_ * D_];
__device__ __nv_bfloat16 g_wq_hi[L_*D_*D_], g_wq_lo[L_*D_*D_];
__device__ __nv_bfloat16 g_wk_hi[L_*D_*D_], g_wk_lo[L_*D_*D_];
__device__ __nv_bfloat16 g_wv_hi[L_*D_*D_], g_wv_lo[L_*D_*D_];
__device__ __nv_bfloat16 g_wg_hi[L_*D_*D_], g_wg_lo[L_*D_*D_];
__device__ __nv_bfloat16 g_wo_hi[L_*D_*D_], g_wo_lo[L_*D_*D_];
__device__ __nv_bfloat16 g_hw_hi[VOCAB_*D_], g_hw_lo[VOCAB_*D_];

// ---------------- PTX helpers (baseline ISA only: sm_80-era) ----------------
__device__ __forceinline__ uint32_t smem_u32(const void* p) {
    uint32_t a;
    asm("{ .reg .u64 t; cvta.to.shared.u64 t, %1; cvt.u32.u64 %0, t; }" : "=r"(a) : "l"(p));
    return a;
}
__device__ __forceinline__ void cp16(uint32_t dst, const void* src) {
    asm volatile("cp.async.cg.shared.global [%0], [%1], 16;" :: "r"(dst), "l"(src));
}
__device__ __forceinline__ void cp_commit() {
    asm volatile("cp.async.commit_group;" ::: "memory");
}
template<int N>
__device__ __forceinline__ void cp_wait() {
    asm volatile("cp.async.wait_group %0;" :: "n"(N) : "memory");
}
__device__ __forceinline__ void ldsm4(uint32_t* r, uint32_t addr) {
    asm volatile("ldmatrix.sync.aligned.m8n8.x4.shared.b16 {%0,%1,%2,%3}, [%4];"
        : "=r"(r[0]), "=r"(r[1]), "=r"(r[2]), "=r"(r[3]) : "r"(addr));
}
__device__ __forceinline__ void mma_bf16(float* c, const uint32_t* a, const uint32_t* b) {
    asm volatile(
        "mma.sync.aligned.m16n8k16.row.col.f32.bf16.bf16.f32 "
        "{%0,%1,%2,%3}, {%4,%5,%6,%7}, {%8,%9}, {%0,%1,%2,%3};"
        : "+f"(c[0]), "+f"(c[1]), "+f"(c[2]), "+f"(c[3])
        : "r"(a[0]), "r"(a[1]), "r"(a[2]), "r"(a[3]), "r"(b[0]), "r"(b[1]));
}
__device__ __forceinline__ void split2(float v, __nv_bfloat16& h, __nv_bfloat16& l) {
    h = __float2bfloat16(v);
    l = __float2bfloat16(v - __bfloat162float(h));
}

// ---------------- fp32 -> bf16 hi/lo conversion ----------------
__global__ void __launch_bounds__(256)
cvt_kernel(const float* __restrict__ src, __nv_bfloat16* __restrict__ hi,
           __nv_bfloat16* __restrict__ lo, int n4)
{
    int i = blockIdx.x * 256 + threadIdx.x;
    if (i >= n4) return;
    float4 v = reinterpret_cast<const float4*>(src)[i];
    __nv_bfloat16 h[4], l[4];
    split2(v.x, h[0], l[0]); split2(v.y, h[1], l[1]);
    split2(v.z, h[2], l[2]); split2(v.w, h[3], l[3]);
    reinterpret_cast<uint2*>(hi)[i] = *reinterpret_cast<uint2*>(h);
    reinterpret_cast<uint2*>(lo)[i] = *reinterpret_cast<uint2*>(l);
}

// ---------------- embed ----------------
__global__ void embed_kernel(const int* __restrict__ tokens,
                             const float* __restrict__ emb,
                             const float* __restrict__ pos,
                             float* __restrict__ x)
{
    int idx = blockIdx.x * blockDim.x + threadIdx.x;
    int row = idx / (D_ / 4);
    int c4  = idx % (D_ / 4);
    int s   = row % S_;
    int tok = tokens[row];
    float4 e = reinterpret_cast<const float4*>(emb + (size_t)tok * D_)[c4];
    float4 p = reinterpret_cast<const float4*>(pos + (size_t)s   * D_)[c4];
    e.x += p.x; e.y += p.y; e.z += p.z; e.w += p.w;
    reinterpret_cast<float4*>(x)[idx] = e;
}

// ---------------- layernorm -> bf16 hi/lo ----------------
__global__ void __launch_bounds__(256)
ln_bf16_kernel(const float* __restrict__ x,
               const float* __restrict__ gw,
               const float* __restrict__ bw,
               __nv_bfloat16* __restrict__ yhi,
               __nv_bfloat16* __restrict__ ylo)
{
    int row = blockIdx.x;
    int t   = threadIdx.x;
    float4 xv = reinterpret_cast<const float4*>(x + (size_t)row * D_)[t];

    float s  = xv.x + xv.y + xv.z + xv.w;
    float ss = xv.x*xv.x + xv.y*xv.y + xv.z*xv.z + xv.w*xv.w;
    #pragma unroll
    for (int o = 16; o; o >>= 1) {
        s  += __shfl_xor_sync(0xffffffffu, s,  o);
        ss += __shfl_xor_sync(0xffffffffu, ss, o);
    }
    __shared__ float sh_s[8], sh_ss[8];
    int w = t >> 5;
    if ((t & 31) == 0) { sh_s[w] = s; sh_ss[w] = ss; }
    __syncthreads();
    __shared__ float s_mean, s_inv;
    if (w == 0) {
        s  = (t < 8) ? sh_s[t]  : 0.f;
        ss = (t < 8) ? sh_ss[t] : 0.f;
        #pragma unroll
        for (int o = 4; o; o >>= 1) {
            s  += __shfl_xor_sync(0xffffffffu, s,  o);
            ss += __shfl_xor_sync(0xffffffffu, ss, o);
        }
        if (t == 0) {
            float mean = s * (1.f / D_);
            float var  = ss * (1.f / D_) - mean * mean;
            s_mean = mean;
            s_inv  = rsqrtf(var + 1e-5f);
        }
    }
    __syncthreads();
    float mean = s_mean, inv = s_inv;

    float4 gv = reinterpret_cast<const float4*>(gw)[t];
    float4 bv = reinterpret_cast<const float4*>(bw)[t];
    float o0 = (xv.x - mean) * inv * gv.x + bv.x;
    float o1 = (xv.y - mean) * inv * gv.y + bv.y;
    float o2 = (xv.z - mean) * inv * gv.z + bv.z;
    float o3 = (xv.w - mean) * inv * gv.w + bv.w;

    __nv_bfloat16 h[4], l[4];
    split2(o0, h[0], l[0]); split2(o1, h[1], l[1]);
    split2(o2, h[2], l[2]); split2(o3, h[3], l[3]);
    reinterpret_cast<uint2*>(yhi + (size_t)row * D_)[t] = *reinterpret_cast<uint2*>(h);
    reinterpret_cast<uint2*>(ylo + (size_t)row * D_)[t] = *reinterpret_cast<uint2*>(l);
}

// ---------------- HMMA GEMM: C[m,n] = sum_k A[m,k]*W[n,k] + bias (+res) ----
// A, W as bf16 hi/lo, K-contiguous. 3-product split into fp32 accumulators.
// BM=BN=128, BK=32, 256 threads (8 warps: 2m x 4n, warp tile 64x32).
// Smem row = 128B: [hi 64B | lo 64B], 16B chunk swizzle c ^= (r&7).
__global__ void __launch_bounds__(256)
gemm_mma(const __nv_bfloat16* __restrict__ Ahi, const __nv_bfloat16* __restrict__ Alo,
         const __nv_bfloat16* __restrict__ Whi, const __nv_bfloat16* __restrict__ Wlo,
         const float* __restrict__ bias, const float* __restrict__ res,
         float* __restrict__ C, int Nn)
{
    constexpr int STAGE = 2 * 128 * 128;   // A tile 16KB + W tile 16KB
    extern __shared__ char smem[];
    const uint32_t sb = smem_u32(smem);

    const int tid  = threadIdx.x;
    const int lane = tid & 31;
    const int wid  = tid >> 5;
    const int wm   = wid & 1;      // 2 m-warps (64 rows each)
    const int wn   = wid >> 1;     // 4 n-warps (32 cols each)
    const int bm   = blockIdx.y * 128;
    const int bn   = blockIdx.x * 128;

    // ---- loader mapping: 2048 16B-chunks/stage, 8 per thread ----
    uint32_t dst_off[8];
    const char* src_p[8];
    #pragma unroll
    for (int i = 0; i < 8; i++) {
        int g     = tid + i * 256;
        int piece = g >> 10;            // 0 = A, 1 = W
        int cid   = g & 1023;
        int r     = cid >> 3;
        int c     = cid & 7;
        dst_off[i] = (uint32_t)(piece * 16384 + r * 128 + ((c ^ (r & 7)) * 16));
        const bool hi = (c < 4);
        const int kof = (c & 3) * 8;
        const __nv_bfloat16* p = (piece == 0)
            ? (hi ? Ahi : Alo) + (size_t)(bm + r) * K_ + kof
            : (hi ? Whi : Wlo) + (size_t)(bn + r) * K_ + kof;
        src_p[i] = reinterpret_cast<const char*>(p);
    }
    auto load_stage = [&](int s, int k0) {
        const uint32_t base = sb + (uint32_t)((s & 1) * STAGE);
        #pragma unroll
        for (int i = 0; i < 8; i++)
            cp16(base + dst_off[i], src_p[i] + (size_t)k0 * 2);
    };

    float acc[4][4][4];
    #pragma unroll
    for (int i = 0; i < 4; i++)
        #pragma unroll
        for (int j = 0; j < 4; j++)
            #pragma unroll
            for (int q = 0; q < 4; q++) acc[i][j][q] = 0.f;

    // ---- ldmatrix address precompute (per-thread invariants) ----
    // A x4: row = r0 + (lane&7) + ((lane>>3)&1)*8 ; chunk = kk*2 + ((lane>>4)&1)
    // B x4: row = n0 + (lane&7) + ((lane>>4)&1)*8 ; chunk = kk*2 + ((lane>>3)&1)
    const int a_row = wm * 64 + (lane & 7) + ((lane >> 3) & 1) * 8;  // + mt*16
    const int a_chk = (lane >> 4) & 1;                               // + kk*2
    const int b_row = wn * 32 + (lane & 7) + ((lane >> 4) & 1) * 8;  // + np*16
    const int b_chk = (lane >> 3) & 1;                               // + kk*2

    load_stage(0, 0);
    cp_commit();

    for (int s = 0; s < NS_; s++) {
        if (s + 1 < NS_) { load_stage(s + 1, (s + 1) * BKc_); cp_commit(); cp_wait<1>(); }
        else             { cp_wait<0>(); }
        __syncthreads();

        const uint32_t ab = sb + (uint32_t)((s & 1) * STAGE);
        const uint32_t wb = ab + 16384;

        #pragma unroll
        for (int kk = 0; kk < 2; kk++) {
            uint32_t ah[4][4], al[4][4], bh[4][2], bl[4][2];
            #pragma unroll
            for (int mt = 0; mt < 4; mt++) {
                const int row = a_row + mt * 16;
                const int ch  = kk * 2 + a_chk;
                ldsm4(ah[mt], ab + row * 128 + (( ch      ^ (row & 7)) * 16));
                ldsm4(al[mt], ab + row * 128 + (((ch + 4) ^ (row & 7)) * 16));
            }
            #pragma unroll
            for (int np = 0; np < 2; np++) {
                const int row = b_row + np * 16;
                const int ch  = kk * 2 + b_chk;
                uint32_t t[4];
                ldsm4(t, wb + row * 128 + ((ch ^ (row & 7)) * 16));
                bh[np*2][0] = t[0]; bh[np*2][1] = t[1];
                bh[np*2+1][0] = t[2]; bh[np*2+1][1] = t[3];
                ldsm4(t, wb + row * 128 + (((ch + 4) ^ (row & 7)) * 16));
                bl[np*2][0] = t[0]; bl[np*2][1] = t[1];
                bl[np*2+1][0] = t[2]; bl[np*2+1][1] = t[3];
            }
            #pragma unroll
            for (int mt = 0; mt < 4; mt++)
                #pragma unroll
                for (int nt = 0; nt < 4; nt++) {
                    mma_bf16(acc[mt][nt], ah[mt], bh[nt]);   // hi*hi
                    mma_bf16(acc[mt][nt], ah[mt], bl[nt]);   // hi*lo
                    mma_bf16(acc[mt][nt], al[mt], bh[nt]);   // lo*hi
                }
        }
        __syncthreads();
    }

    // ---- epilogue: register fragments -> gmem with bias/residual ----
    const int gid = lane >> 2;              // 0..7
    const int tig = lane & 3;               // 0..3
    #pragma unroll
    for (int mt = 0; mt < 4; mt++) {
        const int row0 = bm + wm * 64 + mt * 16 + gid;
        #pragma unroll
        for (int nt = 0; nt < 4; nt++) {
            const int col = bn + wn * 32 + nt * 8 + tig * 2;
            const float bx = bias[col], by = bias[col + 1];
            float c0 = acc[mt][nt][0] + bx, c1 = acc[mt][nt][1] + by;
            float c2 = acc[mt][nt][2] + bx, c3 = acc[mt][nt][3] + by;
            if (res) {
                float2 r0 = *reinterpret_cast<const float2*>(&res[(size_t)row0 * Nn + col]);
                float2 r1 = *reinterpret_cast<const float2*>(&res[(size_t)(row0 + 8) * Nn + col]);
                c0 += r0.x; c1 += r0.y; c2 += r1.x; c3 += r1.y;
            }
            *reinterpret_cast<float2*>(&C[(size_t)row0 * Nn + col])       = make_float2(c0, c1);
            *reinterpret_cast<float2*>(&C[(size_t)(row0 + 8) * Nn + col]) = make_float2(c2, c3);
        }
    }
}

// ---------------- linear-attention scan + SiLU gate -> bf16 hi/lo ----------------
__global__ void __launch_bounds__(64)
scan_kernel(const float* __restrict__ Q, const float* __restrict__ K,
            const float* __restrict__ V, const float* __restrict__ G,
            const float* __restrict__ alog,
            __nv_bfloat16* __restrict__ Ohi, __nv_bfloat16* __restrict__ Olo)
{
    const int bh = blockIdx.x;
    const int b  = bh / H_;
    const int h  = bh % H_;
    const int j  = threadIdx.x;

    __shared__ float sk[NST_], sq[NST_];

    float alpha[NST_];
    #pragma unroll
    for (int i = 0; i < NST_; i++)
        alpha[i] = 1.f / (1.f + expf(-alog[h * NST_ + i]));

    float hst[NST_];
    #pragma unroll
    for (int i = 0; i < NST_; i++) hst[i] = 0.f;

    size_t base = ((size_t)b * S_ * H_ + h) * DH_;
    const size_t strideS = (size_t)H_ * DH_;

    for (int s = 0; s < S_; s++) {
        if (j < NST_) { sk[j] = K[base + j]; sq[j] = Q[base + j]; }
        __syncthreads();
        const float v = V[base + j];
        float o = 0.f;
        #pragma unroll
        for (int i = 0; i < NST_; i++) {
            hst[i] = fmaf(alpha[i], hst[i], sk[i] * v);
            o = fmaf(sq[i], hst[i], o);
        }
        const float gg = G[base + j];
        const float ov = o * gg / (1.f + expf(-gg));
        __nv_bfloat16 hh, ll;
        split2(ov, hh, ll);
        Ohi[base + j] = hh;
        Olo[base + j] = ll;
        __syncthreads();
        base += strideS;
    }
}

// ---------------- launch ----------------
extern "C" void kernel_launch(void* const* d_in, const int* in_sizes, int n_in,
                              void* d_out, int out_size)
{
    const int*   tokens = (const int*)  d_in[0];
    const float* emb    = (const float*)d_in[1];
    const float* pos    = (const float*)d_in[2];
    const float* ln_g   = (const float*)d_in[3];
    const float* ln_b   = (const float*)d_in[4];
    const float* wq     = (const float*)d_in[5];
    const float* bq     = (const float*)d_in[6];
    const float* wk     = (const float*)d_in[7];
    const float* bk     = (const float*)d_in[8];
    const float* wv     = (const float*)d_in[9];
    const float* bv     = (const float*)d_in[10];
    const float* wg     = (const float*)d_in[11];
    const float* bg     = (const float*)d_in[12];
    const float* wo     = (const float*)d_in[13];
    const float* bo     = (const float*)d_in[14];
    const float* alogit = (const float*)d_in[15];
    const float* fn_g   = (const float*)d_in[16];
    const float* fn_b   = (const float*)d_in[17];
    const float* head_w = (const float*)d_in[18];
    const float* head_b = (const float*)d_in[19];
    float*       out    = (float*)d_out;

    float *px, *pq, *pk, *pv, *pg;
    __nv_bfloat16 *pxnh, *pxnl, *poh, *pol;
    __nv_bfloat16 *wqh, *wql, *wkh, *wkl, *wvh, *wvl, *wgh, *wgl, *woh, *wol, *hwh, *hwl;
    cudaGetSymbolAddress((void**)&px,   g_x);
    cudaGetSymbolAddress((void**)&pq,   g_q);
    cudaGetSymbolAddress((void**)&pk,   g_k);
    cudaGetSymbolAddress((void**)&pv,   g_v);
    cudaGetSymbolAddress((void**)&pg,   g_gt);
    cudaGetSymbolAddress((void**)&pxnh, g_xn_hi);
    cudaGetSymbolAddress((void**)&pxnl, g_xn_lo);
    cudaGetSymbolAddress((void**)&poh,  g_o_hi);
    cudaGetSymbolAddress((void**)&pol,  g_o_lo);
    cudaGetSymbolAddress((void**)&wqh,  g_wq_hi); cudaGetSymbolAddress((void**)&wql, g_wq_lo);
    cudaGetSymbolAddress((void**)&wkh,  g_wk_hi); cudaGetSymbolAddress((void**)&wkl, g_wk_lo);
    cudaGetSymbolAddress((void**)&wvh,  g_wv_hi); cudaGetSymbolAddress((void**)&wvl, g_wv_lo);
    cudaGetSymbolAddress((void**)&wgh,  g_wg_hi); cudaGetSymbolAddress((void**)&wgl, g_wg_lo);
    cudaGetSymbolAddress((void**)&woh,  g_wo_hi); cudaGetSymbolAddress((void**)&wol, g_wo_lo);
    cudaGetSymbolAddress((void**)&hwh,  g_hw_hi); cudaGetSymbolAddress((void**)&hwl, g_hw_lo);

    constexpr int SMEM_GEMM = 2 * 2 * 128 * 128;   // 65536
    cudaFuncSetAttribute(gemm_mma, cudaFuncAttributeMaxDynamicSharedMemorySize, SMEM_GEMM);

    // weight conversions (fp32 -> bf16 hi/lo)
    const int nW4 = L_ * D_ * D_ / 4;
    cvt_kernel<<<nW4 / 256, 256>>>(wq, wqh, wql, nW4);
    cvt_kernel<<<nW4 / 256, 256>>>(wk, wkh, wkl, nW4);
    cvt_kernel<<<nW4 / 256, 256>>>(wv, wvh, wvl, nW4);
    cvt_kernel<<<nW4 / 256, 256>>>(wg, wgh, wgl, nW4);
    cvt_kernel<<<nW4 / 256, 256>>>(wo, woh, wol, nW4);
    const int nH4 = VOCAB_ * D_ / 4;
    cvt_kernel<<<nH4 / 256, 256>>>(head_w, hwh, hwl, nH4);

    embed_kernel<<<(M_ * D_ / 4) / 256, 256>>>(tokens, emb, pos, px);

    const dim3 big_grid(D_ / 128, M_ / 128);     // (8, 32)
    const dim3 head_grid(1, M_ / 128);           // (1, 32)

    for (int l = 0; l < L_; l++) {
        const size_t wOff = (size_t)l * D_ * D_;
        ln_bf16_kernel<<<M_, 256>>>(px, ln_g + l * D_, ln_b + l * D_, pxnh, pxnl);

        gemm_mma<<<big_grid, 256, SMEM_GEMM>>>(pxnh, pxnl, wqh + wOff, wql + wOff,
                                               bq + l * D_, nullptr, pq, D_);
        gemm_mma<<<big_grid, 256, SMEM_GEMM>>>(pxnh, pxnl, wkh + wOff, wkl + wOff,
                                               bk + l * D_, nullptr, pk, D_);
        gemm_mma<<<big_grid, 256, SMEM_GEMM>>>(pxnh, pxnl, wvh + wOff, wvl + wOff,
                                               bv + l * D_, nullptr, pv, D_);
        gemm_mma<<<big_grid, 256, SMEM_GEMM>>>(pxnh, pxnl, wgh + wOff, wgl + wOff,
                                               bg + l * D_, nullptr, pg, D_);

        scan_kernel<<<B_ * H_, DH_>>>(pq, pk, pv, pg, alogit + (size_t)l * H_ * NST_, poh, pol);

        gemm_mma<<<big_grid, 256, SMEM_GEMM>>>(poh, pol, woh + wOff, wol + wOff,
                                               bo + l * D_, px, px, D_);
    }

    ln_bf16_kernel<<<M_, 256>>>(px, fn_g, fn_b, pxnh, pxnl);
    gemm_mma<<<head_grid, 256, SMEM_GEMM>>>(pxnh, pxnl, hwh, hwl,
                                            head_b, nullptr, out, VOCAB_);
}

// round 4
// speedup vs baseline: 2.9901x; 1.9950x over previous
#include <cuda_runtime.h>
#include <cuda_bf16.h>
#include <math.h>
#include <stdint.h>

// ---------------- problem constants ----------------
constexpr int B_    = 8;
constexpr int S_    = 512;
constexpr int D_    = 1024;
constexpr int H_    = 16;
constexpr int DH_   = 64;
constexpr int NST_  = 32;
constexpr int L_    = 2;
constexpr int VOCAB_= 128;
constexpr int M_    = B_ * S_;   // 4096
constexpr int K_    = D_;        // 1024
constexpr int BKc_  = 32;        // K per stage
constexpr int NS_   = K_ / BKc_; // 32 stages
constexpr int T_    = 64;        // scan chunk length
constexpr int P_    = S_ / T_;   // 8 chunks

// ---------------- scratch (static device globals) ----------------
__device__ float g_x   [M_ * D_];
__device__ float g_qkvg[M_ * 4 * D_];            // packed Q|K|V|G, row stride 4096
__device__ float g_st  [B_*H_ * P_ * NST_ * DH_];
__device__ float g_hin [B_*H_ * P_ * NST_ * DH_];
__device__ float g_bcat[L_ * 4 * D_];
__device__ __nv_bfloat16 g_xn_hi[M_ * D_], g_xn_lo[M_ * D_];
__device__ __nv_bfloat16 g_o_hi [M_ * D_], g_o_lo [M_ * D_];
__device__ __nv_bfloat16 g_wc_hi[L_*4*D_*D_], g_wc_lo[L_*4*D_*D_];   // packed QKVG weights
__device__ __nv_bfloat16 g_wo_hi[L_*D_*D_],   g_wo_lo[L_*D_*D_];
__device__ __nv_bfloat16 g_hw_hi[VOCAB_*D_],  g_hw_lo[VOCAB_*D_];

// ---------------- PTX helpers (baseline sm_80-era ISA only) ----------------
__device__ __forceinline__ uint32_t smem_u32(const void* p) {
    uint32_t a;
    asm("{ .reg .u64 t; cvta.to.shared.u64 t, %1; cvt.u32.u64 %0, t; }" : "=r"(a) : "l"(p));
    return a;
}
__device__ __forceinline__ void cp16(uint32_t dst, const void* src) {
    asm volatile("cp.async.cg.shared.global [%0], [%1], 16;" :: "r"(dst), "l"(src));
}
__device__ __forceinline__ void cp_commit() {
    asm volatile("cp.async.commit_group;" ::: "memory");
}
template<int N>
__device__ __forceinline__ void cp_wait() {
    asm volatile("cp.async.wait_group %0;" :: "n"(N) : "memory");
}
__device__ __forceinline__ void ldsm4(uint32_t* r, uint32_t addr) {
    asm volatile("ldmatrix.sync.aligned.m8n8.x4.shared.b16 {%0,%1,%2,%3}, [%4];"
        : "=r"(r[0]), "=r"(r[1]), "=r"(r[2]), "=r"(r[3]) : "r"(addr));
}
__device__ __forceinline__ void mma_bf16(float* c, const uint32_t* a, const uint32_t* b) {
    asm volatile(
        "mma.sync.aligned.m16n8k16.row.col.f32.bf16.bf16.f32 "
        "{%0,%1,%2,%3}, {%4,%5,%6,%7}, {%8,%9}, {%0,%1,%2,%3};"
        : "+f"(c[0]), "+f"(c[1]), "+f"(c[2]), "+f"(c[3])
        : "r"(a[0]), "r"(a[1]), "r"(a[2]), "r"(a[3]), "r"(b[0]), "r"(b[1]));
}
__device__ __forceinline__ void split2(float v, __nv_bfloat16& h, __nv_bfloat16& l) {
    h = __float2bfloat16(v);
    l = __float2bfloat16(v - __bfloat162float(h));
}

// ---------------- fp32 -> bf16 hi/lo conversion ----------------
__global__ void __launch_bounds__(256)
cvt_kernel(const float* __restrict__ src, __nv_bfloat16* __restrict__ hi,
           __nv_bfloat16* __restrict__ lo, int n4)
{
    int i = blockIdx.x * 256 + threadIdx.x;
    if (i >= n4) return;
    float4 v = reinterpret_cast<const float4*>(src)[i];
    __nv_bfloat16 h[4], l[4];
    split2(v.x, h[0], l[0]); split2(v.y, h[1], l[1]);
    split2(v.z, h[2], l[2]); split2(v.w, h[3], l[3]);
    reinterpret_cast<uint2*>(hi)[i] = *reinterpret_cast<uint2*>(h);
    reinterpret_cast<uint2*>(lo)[i] = *reinterpret_cast<uint2*>(l);
}

// ---------------- bias pack (4 x 1024 -> 4096) ----------------
__global__ void pack_bias(const float* __restrict__ b0, const float* __restrict__ b1,
                          const float* __restrict__ b2, const float* __restrict__ b3,
                          float* __restrict__ dst)
{
    int i = blockIdx.x * 256 + threadIdx.x;   // 0..4095
    int p = i >> 10, c = i & 1023;
    const float* src = (p == 0) ? b0 : (p == 1) ? b1 : (p == 2) ? b2 : b3;
    dst[i] = src[c];
}

// ---------------- embed ----------------
__global__ void embed_kernel(const int* __restrict__ tokens,
                             const float* __restrict__ emb,
                             const float* __restrict__ pos,
                             float* __restrict__ x)
{
    int idx = blockIdx.x * blockDim.x + threadIdx.x;
    int row = idx / (D_ / 4);
    int c4  = idx % (D_ / 4);
    int s   = row % S_;
    int tok = tokens[row];
    float4 e = reinterpret_cast<const float4*>(emb + (size_t)tok * D_)[c4];
    float4 p = reinterpret_cast<const float4*>(pos + (size_t)s   * D_)[c4];
    e.x += p.x; e.y += p.y; e.z += p.z; e.w += p.w;
    reinterpret_cast<float4*>(x)[idx] = e;
}

// ---------------- layernorm -> bf16 hi/lo ----------------
__global__ void __launch_bounds__(256)
ln_bf16_kernel(const float* __restrict__ x,
               const float* __restrict__ gw,
               const float* __restrict__ bw,
               __nv_bfloat16* __restrict__ yhi,
               __nv_bfloat16* __restrict__ ylo)
{
    int row = blockIdx.x;
    int t   = threadIdx.x;
    float4 xv = reinterpret_cast<const float4*>(x + (size_t)row * D_)[t];

    float s  = xv.x + xv.y + xv.z + xv.w;
    float ss = xv.x*xv.x + xv.y*xv.y + xv.z*xv.z + xv.w*xv.w;
    #pragma unroll
    for (int o = 16; o; o >>= 1) {
        s  += __shfl_xor_sync(0xffffffffu, s,  o);
        ss += __shfl_xor_sync(0xffffffffu, ss, o);
    }
    __shared__ float sh_s[8], sh_ss[8];
    int w = t >> 5;
    if ((t & 31) == 0) { sh_s[w] = s; sh_ss[w] = ss; }
    __syncthreads();
    __shared__ float s_mean, s_inv;
    if (w == 0) {
        s  = (t < 8) ? sh_s[t]  : 0.f;
        ss = (t < 8) ? sh_ss[t] : 0.f;
        #pragma unroll
        for (int o = 4; o; o >>= 1) {
            s  += __shfl_xor_sync(0xffffffffu, s,  o);
            ss += __shfl_xor_sync(0xffffffffu, ss, o);
        }
        if (t == 0) {
            float mean = s * (1.f / D_);
            float var  = ss * (1.f / D_) - mean * mean;
            s_mean = mean;
            s_inv  = rsqrtf(var + 1e-5f);
        }
    }
    __syncthreads();
    float mean = s_mean, inv = s_inv;

    float4 gv = reinterpret_cast<const float4*>(gw)[t];
    float4 bv = reinterpret_cast<const float4*>(bw)[t];
    float o0 = (xv.x - mean) * inv * gv.x + bv.x;
    float o1 = (xv.y - mean) * inv * gv.y + bv.y;
    float o2 = (xv.z - mean) * inv * gv.z + bv.z;
    float o3 = (xv.w - mean) * inv * gv.w + bv.w;

    __nv_bfloat16 h[4], l[4];
    split2(o0, h[0], l[0]); split2(o1, h[1], l[1]);
    split2(o2, h[2], l[2]); split2(o3, h[3], l[3]);
    reinterpret_cast<uint2*>(yhi + (size_t)row * D_)[t] = *reinterpret_cast<uint2*>(h);
    reinterpret_cast<uint2*>(ylo + (size_t)row * D_)[t] = *reinterpret_cast<uint2*>(l);
}

// ---------------- HMMA GEMM: C[m,n] = sum_k A[m,k]*W[n,k] + bias (+res) ----
// BM=128, BN template; 8 warps = 2m x 4n grid of 64x(BN/4) warp tiles.
// 3-stage cp.async pipeline. Split-major MMA ordering (no RAW stalls).
template<int BN>
__global__ void __launch_bounds__(256)
gemm_mma(const __nv_bfloat16* __restrict__ Ahi, const __nv_bfloat16* __restrict__ Alo,
         const __nv_bfloat16* __restrict__ Whi, const __nv_bfloat16* __restrict__ Wlo,
         const float* __restrict__ bias, const float* __restrict__ res,
         float* __restrict__ C, int Nn)
{
    constexpr int WN    = BN / 4;          // cols per n-warp (64 or 32)
    constexpr int NT    = WN / 8;          // n8 tiles per warp (8 or 4)
    constexpr int NP    = WN / 16;         // ldsm n-groups (4 or 2)
    constexpr int STAGE = (128 + BN) * 128;    // bytes per stage
    constexpr int PER   = (128 + BN) * 8 / 256; // 16B chunks per thread

    extern __shared__ char smem[];
    const uint32_t sb = smem_u32(smem);

    const int tid  = threadIdx.x;
    const int lane = tid & 31;
    const int wid  = tid >> 5;
    const int wm   = wid & 1;
    const int wn   = wid >> 1;
    const int bm   = blockIdx.y * 128;
    const int bn   = blockIdx.x * BN;

    // ---- loader mapping ----
    uint32_t dst_off[PER];
    const char* src_p[PER];
    #pragma unroll
    for (int i = 0; i < PER; i++) {
        int g = tid + i * 256;
        const bool isA = (g < 1024);           // A = 128 rows * 8 chunks
        int cid = isA ? g : (g - 1024);
        int r   = cid >> 3;
        int c   = cid & 7;
        dst_off[i] = (uint32_t)((isA ? 0 : 16384) + r * 128 + ((c ^ (r & 7)) * 16));
        const bool hi = (c < 4);
        const int kof = (c & 3) * 8;
        const __nv_bfloat16* p = isA
            ? (hi ? Ahi : Alo) + (size_t)(bm + r) * K_ + kof
            : (hi ? Whi : Wlo) + (size_t)(bn + r) * K_ + kof;
        src_p[i] = reinterpret_cast<const char*>(p);
    }
    auto load_stage = [&](int s) {
        const uint32_t base = sb + (uint32_t)((s % 3) * STAGE);
        const size_t koff = (size_t)(s * BKc_) * 2;
        #pragma unroll
        for (int i = 0; i < PER; i++)
            cp16(base + dst_off[i], src_p[i] + koff);
    };

    float acc[4][NT][4];
    #pragma unroll
    for (int i = 0; i < 4; i++)
        #pragma unroll
        for (int j = 0; j < NT; j++)
            #pragma unroll
            for (int q = 0; q < 4; q++) acc[i][j][q] = 0.f;

    const int a_row = wm * 64 + (lane & 7) + ((lane >> 3) & 1) * 8;
    const int a_chk = (lane >> 4) & 1;
    const int b_row = wn * WN + (lane & 7) + ((lane >> 4) & 1) * 8;
    const int b_chk = (lane >> 3) & 1;

    load_stage(0); cp_commit();
    load_stage(1); cp_commit();

    for (int s = 0; s < NS_; s++) {
        if (s + 2 < NS_) cp_wait<1>(); else cp_wait<0>();
        __syncthreads();
        if (s + 2 < NS_) { load_stage(s + 2); cp_commit(); }

        const uint32_t ab = sb + (uint32_t)((s % 3) * STAGE);
        const uint32_t wb = ab + 16384;

        #pragma unroll
        for (int kk = 0; kk < 2; kk++) {
            uint32_t ah[4][4], al[4][4];
            #pragma unroll
            for (int mt = 0; mt < 4; mt++) {
                const int row = a_row + mt * 16;
                const int ch  = kk * 2 + a_chk;
                ldsm4(ah[mt], ab + row * 128 + (( ch      ^ (row & 7)) * 16));
                ldsm4(al[mt], ab + row * 128 + (((ch + 4) ^ (row & 7)) * 16));
            }
            #pragma unroll
            for (int np = 0; np < NP; np++) {
                const int row = b_row + np * 16;
                const int ch  = kk * 2 + b_chk;
                uint32_t bh[2][2], bl[2][2], t0[4], t1[4];
                ldsm4(t0, wb + row * 128 + (( ch      ^ (row & 7)) * 16));
                ldsm4(t1, wb + row * 128 + (((ch + 4) ^ (row & 7)) * 16));
                bh[0][0]=t0[0]; bh[0][1]=t0[1]; bh[1][0]=t0[2]; bh[1][1]=t0[3];
                bl[0][0]=t1[0]; bl[0][1]=t1[1]; bl[1][0]=t1[2]; bl[1][1]=t1[3];
                // split-major: reuse distance per accumulator = 8 MMAs
                #pragma unroll
                for (int mt = 0; mt < 4; mt++) {
                    mma_bf16(acc[mt][np*2+0], ah[mt], bh[0]);
                    mma_bf16(acc[mt][np*2+1], ah[mt], bh[1]);
                }
                #pragma unroll
                for (int mt = 0; mt < 4; mt++) {
                    mma_bf16(acc[mt][np*2+0], ah[mt], bl[0]);
                    mma_bf16(acc[mt][np*2+1], ah[mt], bl[1]);
                }
                #pragma unroll
                for (int mt = 0; mt < 4; mt++) {
                    mma_bf16(acc[mt][np*2+0], al[mt], bh[0]);
                    mma_bf16(acc[mt][np*2+1], al[mt], bh[1]);
                }
            }
        }
        __syncthreads();
    }

    // ---- epilogue ----
    const int gid = lane >> 2;
    const int tig = lane & 3;
    #pragma unroll
    for (int mt = 0; mt < 4; mt++) {
        const int row0 = bm + wm * 64 + mt * 16 + gid;
        #pragma unroll
        for (int nt = 0; nt < NT; nt++) {
            const int col = bn + wn * WN + nt * 8 + tig * 2;
            const float bx = bias[col], by = bias[col + 1];
            float c0 = acc[mt][nt][0] + bx, c1 = acc[mt][nt][1] + by;
            float c2 = acc[mt][nt][2] + bx, c3 = acc[mt][nt][3] + by;
            if (res) {
                float2 r0 = *reinterpret_cast<const float2*>(&res[(size_t)row0 * Nn + col]);
                float2 r1 = *reinterpret_cast<const float2*>(&res[(size_t)(row0 + 8) * Nn + col]);
                c0 += r0.x; c1 += r0.y; c2 += r1.x; c3 += r1.y;
            }
            *reinterpret_cast<float2*>(&C[(size_t)row0 * Nn + col])       = make_float2(c0, c1);
            *reinterpret_cast<float2*>(&C[(size_t)(row0 + 8) * Nn + col]) = make_float2(c2, c3);
        }
    }
}

// ---------------- chunked linear-attention scan ----------------
// packed qkvg row layout: [Q | K | V | G], each D_ wide; head h occupies cols h*64..
// phase A: per-chunk local end state from zero init
__global__ void __launch_bounds__(64)
scan_phaseA(const float* __restrict__ qkvg, const float* __restrict__ alog,
            float* __restrict__ st)
{
    const int bh = blockIdx.x, c = blockIdx.y;
    const int b = bh >> 4, h = bh & 15;
    const int j = threadIdx.x;
    __shared__ float sk[NST_];

    float alpha[NST_];
    #pragma unroll
    for (int i = 0; i < NST_; i++)
        alpha[i] = 1.f / (1.f + expf(-alog[h * NST_ + i]));
    float hst[NST_];
    #pragma unroll
    for (int i = 0; i < NST_; i++) hst[i] = 0.f;

    const float* base = qkvg + (size_t)(b * S_ + c * T_) * 4096;
    const int kcol = D_ + h * DH_;
    const int vcol = 2 * D_ + h * DH_;

    for (int t = 0; t < T_; t++) {
        if (j < NST_) sk[j] = base[kcol + j];
        __syncthreads();
        const float v = base[vcol + j];
        #pragma unroll
        for (int i = 0; i < NST_; i++)
            hst[i] = fmaf(alpha[i], hst[i], sk[i] * v);
        __syncthreads();
        base += 4096;
    }
    float* dst = st + (((size_t)bh * P_ + c) * NST_) * DH_ + j;
    #pragma unroll
    for (int i = 0; i < NST_; i++) dst[i * DH_] = hst[i];
}

// phase B: sequential prefix over P chunks (tiny)
__global__ void __launch_bounds__(64)
scan_phaseB(const float* __restrict__ alog, const float* __restrict__ st,
            float* __restrict__ hin)
{
    const int bh = blockIdx.x;
    const int h = bh & 15;
    const int j = threadIdx.x;

    float aT[NST_];
    #pragma unroll
    for (int i = 0; i < NST_; i++) {
        float a = 1.f / (1.f + expf(-alog[h * NST_ + i]));
        aT[i] = powf(a, (float)T_);
    }
    float Hin[NST_];
    #pragma unroll
    for (int i = 0; i < NST_; i++) Hin[i] = 0.f;

    for (int c = 0; c < P_; c++) {
        float* dst = hin + (((size_t)bh * P_ + c) * NST_) * DH_ + j;
        #pragma unroll
        for (int i = 0; i < NST_; i++) dst[i * DH_] = Hin[i];
        if (c < P_ - 1) {
            const float* src = st + (((size_t)bh * P_ + c) * NST_) * DH_ + j;
            #pragma unroll
            for (int i = 0; i < NST_; i++)
                Hin[i] = fmaf(aT[i], Hin[i], src[i * DH_]);
        }
    }
}

// phase C: rerun chunk with corrected init, produce gated output (bf16 hi/lo)
__global__ void __launch_bounds__(64)
scan_phaseC(const float* __restrict__ qkvg, const float* __restrict__ alog,
            const float* __restrict__ hin,
            __nv_bfloat16* __restrict__ Ohi, __nv_bfloat16* __restrict__ Olo)
{
    const int bh = blockIdx.x, c = blockIdx.y;
    const int b = bh >> 4, h = bh & 15;
    const int j = threadIdx.x;
    __shared__ float sk[NST_], sq[NST_];

    float alpha[NST_];
    #pragma unroll
    for (int i = 0; i < NST_; i++)
        alpha[i] = 1.f / (1.f + expf(-alog[h * NST_ + i]));
    float hst[NST_];
    {
        const float* src = hin + (((size_t)bh * P_ + c) * NST_) * DH_ + j;
        #pragma unroll
        for (int i = 0; i < NST_; i++) hst[i] = src[i * DH_];
    }

    const int m0 = b * S_ + c * T_;
    const float* base = qkvg + (size_t)m0 * 4096;
    const int qcol = h * DH_;
    const int kcol = D_ + h * DH_;
    const int vcol = 2 * D_ + h * DH_;
    const int gcol = 3 * D_ + h * DH_;
    __nv_bfloat16* oh = Ohi + (size_t)m0 * D_ + h * DH_ + j;
    __nv_bfloat16* ol = Olo + (size_t)m0 * D_ + h * DH_ + j;

    for (int t = 0; t < T_; t++) {
        if (j < NST_) { sk[j] = base[kcol + j]; sq[j] = base[qcol + j]; }
        __syncthreads();
        const float v = base[vcol + j];
        float o = 0.f;
        #pragma unroll
        for (int i = 0; i < NST_; i++) {
            hst[i] = fmaf(alpha[i], hst[i], sk[i] * v);
            o = fmaf(sq[i], hst[i], o);
        }
        const float gg = base[gcol + j];
        const float ov = o * gg / (1.f + expf(-gg));
        __nv_bfloat16 hh, ll;
        split2(ov, hh, ll);
        *oh = hh; *ol = ll;
        __syncthreads();
        base += 4096; oh += D_; ol += D_;
    }
}

// ---------------- launch ----------------
extern "C" void kernel_launch(void* const* d_in, const int* in_sizes, int n_in,
                              void* d_out, int out_size)
{
    const int*   tokens = (const int*)  d_in[0];
    const float* emb    = (const float*)d_in[1];
    const float* pos    = (const float*)d_in[2];
    const float* ln_g   = (const float*)d_in[3];
    const float* ln_b   = (const float*)d_in[4];
    const float* wq     = (const float*)d_in[5];
    const float* bq     = (const float*)d_in[6];
    const float* wk     = (const float*)d_in[7];
    const float* bk     = (const float*)d_in[8];
    const float* wv     = (const float*)d_in[9];
    const float* bv     = (const float*)d_in[10];
    const float* wg     = (const float*)d_in[11];
    const float* bg     = (const float*)d_in[12];
    const float* wo     = (const float*)d_in[13];
    const float* bo     = (const float*)d_in[14];
    const float* alogit = (const float*)d_in[15];
    const float* fn_g   = (const float*)d_in[16];
    const float* fn_b   = (const float*)d_in[17];
    const float* head_w = (const float*)d_in[18];
    const float* head_b = (const float*)d_in[19];
    float*       out    = (float*)d_out;

    float *px, *pqkvg, *pst, *phin, *pbcat;
    __nv_bfloat16 *pxnh, *pxnl, *poh, *pol;
    __nv_bfloat16 *wch, *wcl, *woh, *wol, *hwh, *hwl;
    cudaGetSymbolAddress((void**)&px,    g_x);
    cudaGetSymbolAddress((void**)&pqkvg, g_qkvg);
    cudaGetSymbolAddress((void**)&pst,   g_st);
    cudaGetSymbolAddress((void**)&phin,  g_hin);
    cudaGetSymbolAddress((void**)&pbcat, g_bcat);
    cudaGetSymbolAddress((void**)&pxnh,  g_xn_hi);
    cudaGetSymbolAddress((void**)&pxnl,  g_xn_lo);
    cudaGetSymbolAddress((void**)&poh,   g_o_hi);
    cudaGetSymbolAddress((void**)&pol,   g_o_lo);
    cudaGetSymbolAddress((void**)&wch,   g_wc_hi); cudaGetSymbolAddress((void**)&wcl, g_wc_lo);
    cudaGetSymbolAddress((void**)&woh,   g_wo_hi); cudaGetSymbolAddress((void**)&wol, g_wo_lo);
    cudaGetSymbolAddress((void**)&hwh,   g_hw_hi); cudaGetSymbolAddress((void**)&hwl, g_hw_lo);

    constexpr int SMEM_256 = 3 * (128 + 256) * 128;   // 147456
    constexpr int SMEM_128 = 3 * (128 + 128) * 128;   // 98304
    cudaFuncSetAttribute(gemm_mma<256>, cudaFuncAttributeMaxDynamicSharedMemorySize, SMEM_256);
    cudaFuncSetAttribute(gemm_mma<128>, cudaFuncAttributeMaxDynamicSharedMemorySize, SMEM_128);

    // pack weights: [L][4D][K] = Q,K,V,G rows
    const int nW4 = D_ * D_ / 4;   // per piece
    const size_t PIECE = (size_t)D_ * D_;
    for (int l = 0; l < L_; l++) {
        cvt_kernel<<<nW4 / 256, 256>>>(wq + l * PIECE, wch + (l*4+0)*PIECE, wcl + (l*4+0)*PIECE, nW4);
        cvt_kernel<<<nW4 / 256, 256>>>(wk + l * PIECE, wch + (l*4+1)*PIECE, wcl + (l*4+1)*PIECE, nW4);
        cvt_kernel<<<nW4 / 256, 256>>>(wv + l * PIECE, wch + (l*4+2)*PIECE, wcl + (l*4+2)*PIECE, nW4);
        cvt_kernel<<<nW4 / 256, 256>>>(wg + l * PIECE, wch + (l*4+3)*PIECE, wcl + (l*4+3)*PIECE, nW4);
        cvt_kernel<<<nW4 / 256, 256>>>(wo + l * PIECE, woh + l * PIECE, wol + l * PIECE, nW4);
        pack_bias<<<16, 256>>>(bq + l * D_, bk + l * D_, bv + l * D_, bg + l * D_, pbcat + l * 4 * D_);
    }
    cvt_kernel<<<VOCAB_ * D_ / 1024, 256>>>(head_w, hwh, hwl, VOCAB_ * D_ / 4);

    embed_kernel<<<(M_ * D_ / 4) / 256, 256>>>(tokens, emb, pos, px);

    const dim3 qkvg_grid(4 * D_ / 256, M_ / 128);   // (16, 32)
    const dim3 wo_grid(D_ / 256, M_ / 128);         // (4, 32)
    const dim3 head_grid(1, M_ / 128);              // (1, 32)

    for (int l = 0; l < L_; l++) {
        const size_t wOff = (size_t)l * PIECE;
        const float* alog = alogit + (size_t)l * H_ * NST_;

        ln_bf16_kernel<<<M_, 256>>>(px, ln_g + l * D_, ln_b + l * D_, pxnh, pxnl);

        // fused QKVG projection: [4096 x 4096] = xn @ Wcat^T + bcat
        gemm_mma<256><<<qkvg_grid, 256, SMEM_256>>>(pxnh, pxnl,
            wch + (size_t)l * 4 * PIECE, wcl + (size_t)l * 4 * PIECE,
            pbcat + l * 4 * D_, nullptr, pqkvg, 4 * D_);

        // chunked scan
        scan_phaseA<<<dim3(B_ * H_, P_ - 1), 64>>>(pqkvg, alog, pst);
        scan_phaseB<<<B_ * H_, 64>>>(alog, pst, phin);
        scan_phaseC<<<dim3(B_ * H_, P_), 64>>>(pqkvg, alog, phin, poh, pol);

        // x = x + o @ Wo^T + bo
        gemm_mma<256><<<wo_grid, 256, SMEM_256>>>(poh, pol, woh + wOff, wol + wOff,
                                                  bo + l * D_, px, px, D_);
    }

    ln_bf16_kernel<<<M_, 256>>>(px, fn_g, fn_b, pxnh, pxnl);
    gemm_mma<128><<<head_grid, 256, SMEM_128>>>(pxnh, pxnl, hwh, hwl,
                                                head_b, nullptr, out, VOCAB_);
}

// round 5
// speedup vs baseline: 3.1255x; 1.0453x over previous
#include <cuda_runtime.h>
#include <cuda_bf16.h>
#include <math.h>
#include <stdint.h>

// ---------------- problem constants ----------------
constexpr int B_    = 8;
constexpr int S_    = 512;
constexpr int D_    = 1024;
constexpr int H_    = 16;
constexpr int DH_   = 64;
constexpr int NST_  = 32;
constexpr int L_    = 2;
constexpr int VOCAB_= 128;
constexpr int M_    = B_ * S_;   // 4096
constexpr int K_    = D_;        // 1024
constexpr int BKc_  = 32;        // K per stage
constexpr int NS_   = K_ / BKc_; // 32 stages
constexpr int T_    = 64;        // scan chunk length
constexpr int P_    = S_ / T_;   // 8 chunks

// ---------------- scratch (static device globals) ----------------
__device__ float g_x   [M_ * D_];
__device__ float g_qkvg[M_ * 4 * D_];            // packed Q|K|V|G, row stride 4096
__device__ float g_st  [B_*H_ * P_ * NST_ * DH_];
__device__ float g_hin [B_*H_ * P_ * NST_ * DH_];
__device__ float g_bcat[L_ * 4 * D_];
__device__ __nv_bfloat16 g_xn_hi[M_ * D_], g_xn_lo[M_ * D_];
__device__ __nv_bfloat16 g_o_hi [M_ * D_], g_o_lo [M_ * D_];
__device__ __nv_bfloat16 g_wc_hi[L_*4*D_*D_], g_wc_lo[L_*4*D_*D_];   // packed QKVG weights
__device__ __nv_bfloat16 g_wo_hi[L_*D_*D_],   g_wo_lo[L_*D_*D_];
__device__ __nv_bfloat16 g_hw_hi[VOCAB_*D_],  g_hw_lo[VOCAB_*D_];

// ---------------- PTX helpers (baseline sm_80-era ISA only) ----------------
__device__ __forceinline__ uint32_t smem_u32(const void* p) {
    uint32_t a;
    asm("{ .reg .u64 t; cvta.to.shared.u64 t, %1; cvt.u32.u64 %0, t; }" : "=r"(a) : "l"(p));
    return a;
}
__device__ __forceinline__ void cp16(uint32_t dst, const void* src) {
    asm volatile("cp.async.cg.shared.global [%0], [%1], 16;" :: "r"(dst), "l"(src));
}
__device__ __forceinline__ void cp_commit() {
    asm volatile("cp.async.commit_group;" ::: "memory");
}
template<int N>
__device__ __forceinline__ void cp_wait() {
    asm volatile("cp.async.wait_group %0;" :: "n"(N) : "memory");
}
__device__ __forceinline__ void ldsm4(uint32_t* r, uint32_t addr) {
    asm volatile("ldmatrix.sync.aligned.m8n8.x4.shared.b16 {%0,%1,%2,%3}, [%4];"
        : "=r"(r[0]), "=r"(r[1]), "=r"(r[2]), "=r"(r[3]) : "r"(addr));
}
__device__ __forceinline__ void mma_bf16(float* c, const uint32_t* a, const uint32_t* b) {
    asm volatile(
        "mma.sync.aligned.m16n8k16.row.col.f32.bf16.bf16.f32 "
        "{%0,%1,%2,%3}, {%4,%5,%6,%7}, {%8,%9}, {%0,%1,%2,%3};"
        : "+f"(c[0]), "+f"(c[1]), "+f"(c[2]), "+f"(c[3])
        : "r"(a[0]), "r"(a[1]), "r"(a[2]), "r"(a[3]), "r"(b[0]), "r"(b[1]));
}
__device__ __forceinline__ void split2(float v, __nv_bfloat16& h, __nv_bfloat16& l) {
    h = __float2bfloat16(v);
    l = __float2bfloat16(v - __bfloat162float(h));
}

// ---------------- fused fp32 -> bf16 hi/lo conversion for ALL weights ----------------
// ranges (in float4 units): [0, WC4) packed QKVG, [WC4, WC4+WO4) Wo, then head.
__global__ void __launch_bounds__(256)
cvt_all(const float* __restrict__ wq, const float* __restrict__ wk,
        const float* __restrict__ wv, const float* __restrict__ wg,
        const float* __restrict__ wo, const float* __restrict__ hw,
        __nv_bfloat16* __restrict__ wch, __nv_bfloat16* __restrict__ wcl,
        __nv_bfloat16* __restrict__ woh, __nv_bfloat16* __restrict__ wol,
        __nv_bfloat16* __restrict__ hwh, __nv_bfloat16* __restrict__ hwl)
{
    constexpr int PC4 = D_ * D_ / 4;          // 262144 float4 per piece
    constexpr int WC4 = L_ * 4 * PC4;         // 2097152
    constexpr int WO4 = L_ * PC4;             // 524288
    constexpr int HW4 = VOCAB_ * D_ / 4;      // 32768
    int idx = blockIdx.x * 256 + threadIdx.x;
    const float4* src;
    __nv_bfloat16 *dh, *dl;
    int d4;
    if (idx < WC4) {
        int q   = idx >> 18;        // l*4+p
        int p   = q & 3;
        int off = idx & (PC4 - 1);
        int l   = q >> 2;
        const float* s = (p == 0) ? wq : (p == 1) ? wk : (p == 2) ? wv : wg;
        src = reinterpret_cast<const float4*>(s) + (size_t)l * PC4 + off;
        dh = wch; dl = wcl; d4 = idx;
    } else if (idx < WC4 + WO4) {
        int j = idx - WC4;
        src = reinterpret_cast<const float4*>(wo) + j;
        dh = woh; dl = wol; d4 = j;
    } else if (idx < WC4 + WO4 + HW4) {
        int j = idx - WC4 - WO4;
        src = reinterpret_cast<const float4*>(hw) + j;
        dh = hwh; dl = hwl; d4 = j;
    } else return;

    float4 v = *src;
    __nv_bfloat16 h[4], l[4];
    split2(v.x, h[0], l[0]); split2(v.y, h[1], l[1]);
    split2(v.z, h[2], l[2]); split2(v.w, h[3], l[3]);
    reinterpret_cast<uint2*>(dh)[d4] = *reinterpret_cast<uint2*>(h);
    reinterpret_cast<uint2*>(dl)[d4] = *reinterpret_cast<uint2*>(l);
}

// ---------------- bias pack (4 x 1024 -> 4096) ----------------
__global__ void pack_bias(const float* __restrict__ b0, const float* __restrict__ b1,
                          const float* __restrict__ b2, const float* __restrict__ b3,
                          float* __restrict__ dst)
{
    int i = blockIdx.x * 256 + threadIdx.x;   // 0..4095
    int p = i >> 10, c = i & 1023;
    const float* src = (p == 0) ? b0 : (p == 1) ? b1 : (p == 2) ? b2 : b3;
    dst[i] = src[c];
}

// ---------------- embed ----------------
__global__ void embed_kernel(const int* __restrict__ tokens,
                             const float* __restrict__ emb,
                             const float* __restrict__ pos,
                             float* __restrict__ x)
{
    int idx = blockIdx.x * blockDim.x + threadIdx.x;
    int row = idx / (D_ / 4);
    int c4  = idx % (D_ / 4);
    int s   = row % S_;
    int tok = tokens[row];
    float4 e = reinterpret_cast<const float4*>(emb + (size_t)tok * D_)[c4];
    float4 p = reinterpret_cast<const float4*>(pos + (size_t)s   * D_)[c4];
    e.x += p.x; e.y += p.y; e.z += p.z; e.w += p.w;
    reinterpret_cast<float4*>(x)[idx] = e;
}

// ---------------- layernorm -> bf16 hi/lo ----------------
__global__ void __launch_bounds__(256)
ln_bf16_kernel(const float* __restrict__ x,
               const float* __restrict__ gw,
               const float* __restrict__ bw,
               __nv_bfloat16* __restrict__ yhi,
               __nv_bfloat16* __restrict__ ylo)
{
    int row = blockIdx.x;
    int t   = threadIdx.x;
    float4 xv = reinterpret_cast<const float4*>(x + (size_t)row * D_)[t];

    float s  = xv.x + xv.y + xv.z + xv.w;
    float ss = xv.x*xv.x + xv.y*xv.y + xv.z*xv.z + xv.w*xv.w;
    #pragma unroll
    for (int o = 16; o; o >>= 1) {
        s  += __shfl_xor_sync(0xffffffffu, s,  o);
        ss += __shfl_xor_sync(0xffffffffu, ss, o);
    }
    __shared__ float sh_s[8], sh_ss[8];
    int w = t >> 5;
    if ((t & 31) == 0) { sh_s[w] = s; sh_ss[w] = ss; }
    __syncthreads();
    __shared__ float s_mean, s_inv;
    if (w == 0) {
        s  = (t < 8) ? sh_s[t]  : 0.f;
        ss = (t < 8) ? sh_ss[t] : 0.f;
        #pragma unroll
        for (int o = 4; o; o >>= 1) {
            s  += __shfl_xor_sync(0xffffffffu, s,  o);
            ss += __shfl_xor_sync(0xffffffffu, ss, o);
        }
        if (t == 0) {
            float mean = s * (1.f / D_);
            float var  = ss * (1.f / D_) - mean * mean;
            s_mean = mean;
            s_inv  = rsqrtf(var + 1e-5f);
        }
    }
    __syncthreads();
    float mean = s_mean, inv = s_inv;

    float4 gv = reinterpret_cast<const float4*>(gw)[t];
    float4 bv = reinterpret_cast<const float4*>(bw)[t];
    float o0 = (xv.x - mean) * inv * gv.x + bv.x;
    float o1 = (xv.y - mean) * inv * gv.y + bv.y;
    float o2 = (xv.z - mean) * inv * gv.z + bv.z;
    float o3 = (xv.w - mean) * inv * gv.w + bv.w;

    __nv_bfloat16 h[4], l[4];
    split2(o0, h[0], l[0]); split2(o1, h[1], l[1]);
    split2(o2, h[2], l[2]); split2(o3, h[3], l[3]);
    reinterpret_cast<uint2*>(yhi + (size_t)row * D_)[t] = *reinterpret_cast<uint2*>(h);
    reinterpret_cast<uint2*>(ylo + (size_t)row * D_)[t] = *reinterpret_cast<uint2*>(l);
}

// ---------------- HMMA GEMM: C[m,n] = sum_k A[m,k]*W[n,k] + bias (+res) ----
// BM=128, BN template; 8 warps = 2m x 4n, warp tile 64 x (BN/4).
// 4-stage cp.async pipeline, ONE sync per stage, sweep-ordered MMAs
// (each accumulator touched once per 32-MMA sweep -> no RAW stalls).
template<int BN>
__global__ void __launch_bounds__(256)
gemm_mma(const __nv_bfloat16* __restrict__ Ahi, const __nv_bfloat16* __restrict__ Alo,
         const __nv_bfloat16* __restrict__ Whi, const __nv_bfloat16* __restrict__ Wlo,
         const float* __restrict__ bias, const float* __restrict__ res,
         float* __restrict__ C, int Nn)
{
    constexpr int WN    = BN / 4;               // cols per n-warp
    constexpr int NT    = WN / 8;               // n8 tiles per warp
    constexpr int NP    = WN / 16;              // ldsm n-groups
    constexpr int STAGE = (128 + BN) * 128;     // bytes per stage
    constexpr int PER   = (128 + BN) * 8 / 256; // 16B chunks per thread

    extern __shared__ char smem[];
    const uint32_t sb = smem_u32(smem);

    const int tid  = threadIdx.x;
    const int lane = tid & 31;
    const int wid  = tid >> 5;
    const int wm   = wid & 1;
    const int wn   = wid >> 1;
    const int bm   = blockIdx.y * 128;
    const int bn   = blockIdx.x * BN;

    // loader: recompute addresses each call (keeps register pressure low)
    auto load_stage = [&](int s, int k0) {
        const uint32_t base = sb + (uint32_t)((s & 3) * STAGE);
        #pragma unroll
        for (int i = 0; i < PER; i++) {
            const int g   = tid + i * 256;
            const bool isA = (g < 1024);
            const int cid = isA ? g : g - 1024;
            const int r   = cid >> 3;
            const int c   = cid & 7;
            const uint32_t dst = base +
                (uint32_t)((isA ? 0 : 16384) + r * 128 + ((c ^ (r & 7)) * 16));
            const bool hi = (c < 4);
            const int kof = (c & 3) * 8 + k0;
            const __nv_bfloat16* p = isA
                ? (hi ? Ahi : Alo) + (size_t)(bm + r) * K_ + kof
                : (hi ? Whi : Wlo) + (size_t)(bn + r) * K_ + kof;
            cp16(dst, p);
        }
    };

    float acc[4][NT][4];
    #pragma unroll
    for (int i = 0; i < 4; i++)
        #pragma unroll
        for (int j = 0; j < NT; j++)
            #pragma unroll
            for (int q = 0; q < 4; q++) acc[i][j][q] = 0.f;

    const int a_row = wm * 64 + (lane & 7) + ((lane >> 3) & 1) * 8;
    const int a_chk = (lane >> 4) & 1;
    const int b_row = wn * WN + (lane & 7) + ((lane >> 4) & 1) * 8;
    const int b_chk = (lane >> 3) & 1;

    load_stage(0, 0);        cp_commit();
    load_stage(1, BKc_);     cp_commit();
    load_stage(2, 2 * BKc_); cp_commit();

    for (int s = 0; s < NS_; s++) {
        if      (s + 2 < NS_) cp_wait<2>();
        else if (s + 1 < NS_) cp_wait<1>();
        else                  cp_wait<0>();
        __syncthreads();
        if (s + 3 < NS_) { load_stage(s + 3, (s + 3) * BKc_); cp_commit(); }

        const uint32_t ab = sb + (uint32_t)((s & 3) * STAGE);
        const uint32_t wb = ab + 16384;

        #pragma unroll
        for (int kk = 0; kk < 2; kk++) {
            uint32_t ah[4][4], al[4][4], bh[NT][2], bl[NT][2];
            #pragma unroll
            for (int mt = 0; mt < 4; mt++) {
                const int row = a_row + mt * 16;
                const int ch  = kk * 2 + a_chk;
                ldsm4(ah[mt], ab + row * 128 + (( ch      ^ (row & 7)) * 16));
                ldsm4(al[mt], ab + row * 128 + (((ch + 4) ^ (row & 7)) * 16));
            }
            #pragma unroll
            for (int np = 0; np < NP; np++) {
                const int row = b_row + np * 16;
                const int ch  = kk * 2 + b_chk;
                uint32_t t0[4], t1[4];
                ldsm4(t0, wb + row * 128 + (( ch      ^ (row & 7)) * 16));
                ldsm4(t1, wb + row * 128 + (((ch + 4) ^ (row & 7)) * 16));
                bh[np*2][0]=t0[0]; bh[np*2][1]=t0[1]; bh[np*2+1][0]=t0[2]; bh[np*2+1][1]=t0[3];
                bl[np*2][0]=t1[0]; bl[np*2][1]=t1[1]; bl[np*2+1][0]=t1[2]; bl[np*2+1][1]=t1[3];
            }
            // three sweeps; each acc touched once per 32-MMA sweep
            #pragma unroll
            for (int nt = 0; nt < NT; nt++)
                #pragma unroll
                for (int mt = 0; mt < 4; mt++)
                    mma_bf16(acc[mt][nt], ah[mt], bh[nt]);
            #pragma unroll
            for (int nt = 0; nt < NT; nt++)
                #pragma unroll
                for (int mt = 0; mt < 4; mt++)
                    mma_bf16(acc[mt][nt], ah[mt], bl[nt]);
            #pragma unroll
            for (int nt = 0; nt < NT; nt++)
                #pragma unroll
                for (int mt = 0; mt < 4; mt++)
                    mma_bf16(acc[mt][nt], al[mt], bh[nt]);
        }
    }

    // ---- epilogue: direct register -> gmem, fused bias/residual ----
    const int gid = lane >> 2;
    const int tig = lane & 3;
    #pragma unroll
    for (int mt = 0; mt < 4; mt++) {
        const int row0 = bm + wm * 64 + mt * 16 + gid;
        #pragma unroll
        for (int nt = 0; nt < NT; nt++) {
            const int col = bn + wn * WN + nt * 8 + tig * 2;
            const float bx = bias[col], by = bias[col + 1];
            float c0 = acc[mt][nt][0] + bx, c1 = acc[mt][nt][1] + by;
            float c2 = acc[mt][nt][2] + bx, c3 = acc[mt][nt][3] + by;
            if (res) {
                float2 r0 = *reinterpret_cast<const float2*>(&res[(size_t)row0 * Nn + col]);
                float2 r1 = *reinterpret_cast<const float2*>(&res[(size_t)(row0 + 8) * Nn + col]);
                c0 += r0.x; c1 += r0.y; c2 += r1.x; c3 += r1.y;
            }
            *reinterpret_cast<float2*>(&C[(size_t)row0 * Nn + col])       = make_float2(c0, c1);
            *reinterpret_cast<float2*>(&C[(size_t)(row0 + 8) * Nn + col]) = make_float2(c2, c3);
        }
    }
}

// ---------------- chunked linear-attention scan ----------------
// phase A: per-chunk local end state from zero init
__global__ void __launch_bounds__(64)
scan_phaseA(const float* __restrict__ qkvg, const float* __restrict__ alog,
            float* __restrict__ st)
{
    const int bh = blockIdx.x, c = blockIdx.y;
    const int b = bh >> 4, h = bh & 15;
    const int j = threadIdx.x;
    __shared__ float sk[NST_];

    float alpha[NST_];
    #pragma unroll
    for (int i = 0; i < NST_; i++)
        alpha[i] = 1.f / (1.f + expf(-alog[h * NST_ + i]));
    float hst[NST_];
    #pragma unroll
    for (int i = 0; i < NST_; i++) hst[i] = 0.f;

    const float* base = qkvg + (size_t)(b * S_ + c * T_) * 4096;
    const int kcol = D_ + h * DH_;
    const int vcol = 2 * D_ + h * DH_;

    for (int t = 0; t < T_; t++) {
        if (j < NST_) sk[j] = base[kcol + j];
        __syncthreads();
        const float v = base[vcol + j];
        #pragma unroll
        for (int i = 0; i < NST_; i++)
            hst[i] = fmaf(alpha[i], hst[i], sk[i] * v);
        __syncthreads();
        base += 4096;
    }
    float* dst = st + (((size_t)bh * P_ + c) * NST_) * DH_ + j;
    #pragma unroll
    for (int i = 0; i < NST_; i++) dst[i * DH_] = hst[i];
}

// phase B: sequential prefix over P chunks (tiny)
__global__ void __launch_bounds__(64)
scan_phaseB(const float* __restrict__ alog, const float* __restrict__ st,
            float* __restrict__ hin)
{
    const int bh = blockIdx.x;
    const int h = bh & 15;
    const int j = threadIdx.x;

    float aT[NST_];
    #pragma unroll
    for (int i = 0; i < NST_; i++) {
        float a = 1.f / (1.f + expf(-alog[h * NST_ + i]));
        aT[i] = powf(a, (float)T_);
    }
    float Hin[NST_];
    #pragma unroll
    for (int i = 0; i < NST_; i++) Hin[i] = 0.f;

    for (int c = 0; c < P_; c++) {
        float* dst = hin + (((size_t)bh * P_ + c) * NST_) * DH_ + j;
        #pragma unroll
        for (int i = 0; i < NST_; i++) dst[i * DH_] = Hin[i];
        if (c < P_ - 1) {
            const float* src = st + (((size_t)bh * P_ + c) * NST_) * DH_ + j;
            #pragma unroll
            for (int i = 0; i < NST_; i++)
                Hin[i] = fmaf(aT[i], Hin[i], src[i * DH_]);
        }
    }
}

// phase C: rerun chunk with corrected init, gated output (bf16 hi/lo).
// 4 independent o-chains (was a 32-deep serial FMA chain).
__global__ void __launch_bounds__(64)
scan_phaseC(const float* __restrict__ qkvg, const float* __restrict__ alog,
            const float* __restrict__ hin,
            __nv_bfloat16* __restrict__ Ohi, __nv_bfloat16* __restrict__ Olo)
{
    const int bh = blockIdx.x, c = blockIdx.y;
    const int b = bh >> 4, h = bh & 15;
    const int j = threadIdx.x;
    __shared__ float sk[NST_], sq[NST_];

    float alpha[NST_];
    #pragma unroll
    for (int i = 0; i < NST_; i++)
        alpha[i] = 1.f / (1.f + expf(-alog[h * NST_ + i]));
    float hst[NST_];
    {
        const float* src = hin + (((size_t)bh * P_ + c) * NST_) * DH_ + j;
        #pragma unroll
        for (int i = 0; i < NST_; i++) hst[i] = src[i * DH_];
    }

    const int m0 = b * S_ + c * T_;
    const float* base = qkvg + (size_t)m0 * 4096;
    const int qcol = h * DH_;
    const int kcol = D_ + h * DH_;
    const int vcol = 2 * D_ + h * DH_;
    const int gcol = 3 * D_ + h * DH_;
    __nv_bfloat16* oh = Ohi + (size_t)m0 * D_ + h * DH_ + j;
    __nv_bfloat16* ol = Olo + (size_t)m0 * D_ + h * DH_ + j;

    for (int t = 0; t < T_; t++) {
        if (j < NST_) { sk[j] = base[kcol + j]; sq[j] = base[qcol + j]; }
        __syncthreads();
        const float v = base[vcol + j];
        float o0 = 0.f, o1 = 0.f, o2 = 0.f, o3 = 0.f;
        #pragma unroll
        for (int i = 0; i < NST_; i += 4) {
            hst[i]   = fmaf(alpha[i],   hst[i],   sk[i]   * v); o0 = fmaf(sq[i],   hst[i],   o0);
            hst[i+1] = fmaf(alpha[i+1], hst[i+1], sk[i+1] * v); o1 = fmaf(sq[i+1], hst[i+1], o1);
            hst[i+2] = fmaf(alpha[i+2], hst[i+2], sk[i+2] * v); o2 = fmaf(sq[i+2], hst[i+2], o2);
            hst[i+3] = fmaf(alpha[i+3], hst[i+3], sk[i+3] * v); o3 = fmaf(sq[i+3], hst[i+3], o3);
        }
        const float o = (o0 + o1) + (o2 + o3);
        const float gg = base[gcol + j];
        const float ov = o * gg / (1.f + expf(-gg));
        __nv_bfloat16 hh, ll;
        split2(ov, hh, ll);
        *oh = hh; *ol = ll;
        __syncthreads();
        base += 4096; oh += D_; ol += D_;
    }
}

// ---------------- launch ----------------
extern "C" void kernel_launch(void* const* d_in, const int* in_sizes, int n_in,
                              void* d_out, int out_size)
{
    const int*   tokens = (const int*)  d_in[0];
    const float* emb    = (const float*)d_in[1];
    const float* pos    = (const float*)d_in[2];
    const float* ln_g   = (const float*)d_in[3];
    const float* ln_b   = (const float*)d_in[4];
    const float* wq     = (const float*)d_in[5];
    const float* bq     = (const float*)d_in[6];
    const float* wk     = (const float*)d_in[7];
    const float* bk     = (const float*)d_in[8];
    const float* wv     = (const float*)d_in[9];
    const float* bv     = (const float*)d_in[10];
    const float* wg     = (const float*)d_in[11];
    const float* bg     = (const float*)d_in[12];
    const float* wo     = (const float*)d_in[13];
    const float* bo     = (const float*)d_in[14];
    const float* alogit = (const float*)d_in[15];
    const float* fn_g   = (const float*)d_in[16];
    const float* fn_b   = (const float*)d_in[17];
    const float* head_w = (const float*)d_in[18];
    const float* head_b = (const float*)d_in[19];
    float*       out    = (float*)d_out;

    float *px, *pqkvg, *pst, *phin, *pbcat;
    __nv_bfloat16 *pxnh, *pxnl, *poh, *pol;
    __nv_bfloat16 *wch, *wcl, *woh, *wol, *hwh, *hwl;
    cudaGetSymbolAddress((void**)&px,    g_x);
    cudaGetSymbolAddress((void**)&pqkvg, g_qkvg);
    cudaGetSymbolAddress((void**)&pst,   g_st);
    cudaGetSymbolAddress((void**)&phin,  g_hin);
    cudaGetSymbolAddress((void**)&pbcat, g_bcat);
    cudaGetSymbolAddress((void**)&pxnh,  g_xn_hi);
    cudaGetSymbolAddress((void**)&pxnl,  g_xn_lo);
    cudaGetSymbolAddress((void**)&poh,   g_o_hi);
    cudaGetSymbolAddress((void**)&pol,   g_o_lo);
    cudaGetSymbolAddress((void**)&wch,   g_wc_hi); cudaGetSymbolAddress((void**)&wcl, g_wc_lo);
    cudaGetSymbolAddress((void**)&woh,   g_wo_hi); cudaGetSymbolAddress((void**)&wol, g_wo_lo);
    cudaGetSymbolAddress((void**)&hwh,   g_hw_hi); cudaGetSymbolAddress((void**)&hwl, g_hw_lo);

    constexpr int SMEM_256 = 4 * (128 + 256) * 128;   // 196608
    constexpr int SMEM_128 = 4 * (128 + 128) * 128;   // 131072
    cudaFuncSetAttribute(gemm_mma<256>, cudaFuncAttributeMaxDynamicSharedMemorySize, SMEM_256);
    cudaFuncSetAttribute(gemm_mma<128>, cudaFuncAttributeMaxDynamicSharedMemorySize, SMEM_128);

    // launch order puts the big QKVG GEMM at launch index 5 (ncu -s 5 -c 1 target)
    constexpr int CVT_TOT = (L_*4*D_*D_ + L_*D_*D_ + VOCAB_*D_) / 4;   // float4 units
    cvt_all<<<(CVT_TOT + 255) / 256, 256>>>(wq, wk, wv, wg, wo, head_w,
                                            wch, wcl, woh, wol, hwh, hwl);    // 0
    pack_bias<<<16, 256>>>(bq, bk, bv, bg, pbcat);                            // 1
    pack_bias<<<16, 256>>>(bq + D_, bk + D_, bv + D_, bg + D_, pbcat + 4*D_); // 2
    embed_kernel<<<(M_ * D_ / 4) / 256, 256>>>(tokens, emb, pos, px);         // 3

    const dim3 qkvg_grid(4 * D_ / 256, M_ / 128);   // (16, 32)
    const dim3 wo_grid(D_ / 256, M_ / 128);         // (4, 32)
    const dim3 head_grid(1, M_ / 128);              // (1, 32)
    const size_t PIECE = (size_t)D_ * D_;

    for (int l = 0; l < L_; l++) {
        const size_t wOff = (size_t)l * PIECE;
        const float* alog = alogit + (size_t)l * H_ * NST_;

        ln_bf16_kernel<<<M_, 256>>>(px, ln_g + l * D_, ln_b + l * D_, pxnh, pxnl);  // 4

        gemm_mma<256><<<qkvg_grid, 256, SMEM_256>>>(pxnh, pxnl,                     // 5 <- profiled
            wch + (size_t)l * 4 * PIECE, wcl + (size_t)l * 4 * PIECE,
            pbcat + l * 4 * D_, nullptr, pqkvg, 4 * D_);

        scan_phaseA<<<dim3(B_ * H_, P_ - 1), 64>>>(pqkvg, alog, pst);
        scan_phaseB<<<B_ * H_, 64>>>(alog, pst, phin);
        scan_phaseC<<<dim3(B_ * H_, P_), 64>>>(pqkvg, alog, phin, poh, pol);

        gemm_mma<256><<<wo_grid, 256, SMEM_256>>>(poh, pol, woh + wOff, wol + wOff,
                                                  bo + l * D_, px, px, D_);
    }

    ln_bf16_kernel<<<M_, 256>>>(px, fn_g, fn_b, pxnh, pxnl);
    gemm_mma<128><<<head_grid, 256, SMEM_128>>>(pxnh, pxnl, hwh, hwl,
                                                head_b, nullptr, out, VOCAB_);
}

// round 6
// speedup vs baseline: 3.3066x; 1.0579x over previous
#include <cuda_runtime.h>
#include <cuda_bf16.h>
#include <math.h>
#include <stdint.h>

// ---------------- problem constants ----------------
constexpr int B_    = 8;
constexpr int S_    = 512;
constexpr int D_    = 1024;
constexpr int H_    = 16;
constexpr int DH_   = 64;
constexpr int NST_  = 32;
constexpr int L_    = 2;
constexpr int VOCAB_= 128;
constexpr int M_    = B_ * S_;   // 4096
constexpr int K_    = D_;        // 1024
constexpr int BKc_  = 32;        // K per stage
constexpr int NS_   = K_ / BKc_; // 32 stages
constexpr int T_    = 64;        // scan chunk length
constexpr int P_    = S_ / T_;   // 8 chunks

// ---------------- scratch (static device globals) ----------------
__device__ float g_x   [M_ * D_];
__device__ float g_qkvg[M_ * 4 * D_];
__device__ float g_st  [B_*H_ * P_ * NST_ * DH_];
__device__ float g_hin [B_*H_ * P_ * NST_ * DH_];
__device__ float g_bcat[L_ * 4 * D_];
__device__ __nv_bfloat16 g_xn_hi[M_ * D_], g_xn_lo[M_ * D_];
__device__ __nv_bfloat16 g_o_hi [M_ * D_], g_o_lo [M_ * D_];
__device__ __nv_bfloat16 g_wc_hi[L_*4*D_*D_], g_wc_lo[L_*4*D_*D_];
__device__ __nv_bfloat16 g_wo_hi[L_*D_*D_],   g_wo_lo[L_*D_*D_];
__device__ __nv_bfloat16 g_hw_hi[VOCAB_*D_],  g_hw_lo[VOCAB_*D_];

// ---------------- PTX helpers (baseline sm_80-era ISA only) ----------------
__device__ __forceinline__ uint32_t smem_u32(const void* p) {
    uint32_t a;
    asm("{ .reg .u64 t; cvta.to.shared.u64 t, %1; cvt.u32.u64 %0, t; }" : "=r"(a) : "l"(p));
    return a;
}
__device__ __forceinline__ void cp16(uint32_t dst, const void* src) {
    asm volatile("cp.async.cg.shared.global [%0], [%1], 16;" :: "r"(dst), "l"(src));
}
__device__ __forceinline__ void cp_commit() {
    asm volatile("cp.async.commit_group;" ::: "memory");
}
template<int N>
__device__ __forceinline__ void cp_wait() {
    asm volatile("cp.async.wait_group %0;" :: "n"(N) : "memory");
}
__device__ __forceinline__ void ldsm4(uint32_t* r, uint32_t addr) {
    asm volatile("ldmatrix.sync.aligned.m8n8.x4.shared.b16 {%0,%1,%2,%3}, [%4];"
        : "=r"(r[0]), "=r"(r[1]), "=r"(r[2]), "=r"(r[3]) : "r"(addr));
}
__device__ __forceinline__ void mma_bf16(float* c, const uint32_t* a, const uint32_t* b) {
    asm volatile(
        "mma.sync.aligned.m16n8k16.row.col.f32.bf16.bf16.f32 "
        "{%0,%1,%2,%3}, {%4,%5,%6,%7}, {%8,%9}, {%0,%1,%2,%3};"
        : "+f"(c[0]), "+f"(c[1]), "+f"(c[2]), "+f"(c[3])
        : "r"(a[0]), "r"(a[1]), "r"(a[2]), "r"(a[3]), "r"(b[0]), "r"(b[1]));
}
__device__ __forceinline__ void split2(float v, __nv_bfloat16& h, __nv_bfloat16& l) {
    h = __float2bfloat16(v);
    l = __float2bfloat16(v - __bfloat162float(h));
}

// ---------------- fused fp32 -> bf16 hi/lo for ALL weights + bias pack ----------------
__global__ void __launch_bounds__(256)
cvt_all(const float* __restrict__ wq, const float* __restrict__ wk,
        const float* __restrict__ wv, const float* __restrict__ wg,
        const float* __restrict__ wo, const float* __restrict__ hw,
        const float* __restrict__ bq, const float* __restrict__ bk,
        const float* __restrict__ bv, const float* __restrict__ bg,
        __nv_bfloat16* __restrict__ wch, __nv_bfloat16* __restrict__ wcl,
        __nv_bfloat16* __restrict__ woh, __nv_bfloat16* __restrict__ wol,
        __nv_bfloat16* __restrict__ hwh, __nv_bfloat16* __restrict__ hwl,
        float* __restrict__ bcat)
{
    constexpr int PC4 = D_ * D_ / 4;
    constexpr int WC4 = L_ * 4 * PC4;
    constexpr int WO4 = L_ * PC4;
    constexpr int HW4 = VOCAB_ * D_ / 4;
    constexpr int BC4 = L_ * 4 * D_ / 4;        // 2048
    int idx = blockIdx.x * 256 + threadIdx.x;
    const float4* src;
    __nv_bfloat16 *dh, *dl;
    int d4;
    if (idx < WC4) {
        int q   = idx >> 18;
        int p   = q & 3;
        int off = idx & (PC4 - 1);
        int l   = q >> 2;
        const float* s = (p == 0) ? wq : (p == 1) ? wk : (p == 2) ? wv : wg;
        src = reinterpret_cast<const float4*>(s) + (size_t)l * PC4 + off;
        dh = wch; dl = wcl; d4 = idx;
    } else if (idx < WC4 + WO4) {
        int j = idx - WC4;
        src = reinterpret_cast<const float4*>(wo) + j;
        dh = woh; dl = wol; d4 = j;
    } else if (idx < WC4 + WO4 + HW4) {
        int j = idx - WC4 - WO4;
        src = reinterpret_cast<const float4*>(hw) + j;
        dh = hwh; dl = hwl; d4 = j;
    } else if (idx < WC4 + WO4 + HW4 + BC4) {
        int j  = idx - WC4 - WO4 - HW4;        // float4 idx into bcat
        int p4 = j & 255;                       // 256 float4 per 1024-piece
        int p  = (j >> 8) & 3;
        int l  = j >> 10;
        const float* s = (p == 0) ? bq : (p == 1) ? bk : (p == 2) ? bv : bg;
        float4 v = reinterpret_cast<const float4*>(s + (size_t)l * D_)[p4];
        reinterpret_cast<float4*>(bcat)[j] = v;
        return;
    } else return;

    float4 v = *src;
    __nv_bfloat16 h[4], l[4];
    split2(v.x, h[0], l[0]); split2(v.y, h[1], l[1]);
    split2(v.z, h[2], l[2]); split2(v.w, h[3], l[3]);
    reinterpret_cast<uint2*>(dh)[d4] = *reinterpret_cast<uint2*>(h);
    reinterpret_cast<uint2*>(dl)[d4] = *reinterpret_cast<uint2*>(l);
}

// ---------------- embed ----------------
__global__ void embed_kernel(const int* __restrict__ tokens,
                             const float* __restrict__ emb,
                             const float* __restrict__ pos,
                             float* __restrict__ x)
{
    int idx = blockIdx.x * blockDim.x + threadIdx.x;
    int row = idx / (D_ / 4);
    int c4  = idx % (D_ / 4);
    int s   = row % S_;
    int tok = tokens[row];
    float4 e = reinterpret_cast<const float4*>(emb + (size_t)tok * D_)[c4];
    float4 p = reinterpret_cast<const float4*>(pos + (size_t)s   * D_)[c4];
    e.x += p.x; e.y += p.y; e.z += p.z; e.w += p.w;
    reinterpret_cast<float4*>(x)[idx] = e;
}

// ---------------- layernorm -> bf16 hi/lo ----------------
__global__ void __launch_bounds__(256)
ln_bf16_kernel(const float* __restrict__ x,
               const float* __restrict__ gw,
               const float* __restrict__ bw,
               __nv_bfloat16* __restrict__ yhi,
               __nv_bfloat16* __restrict__ ylo)
{
    int row = blockIdx.x;
    int t   = threadIdx.x;
    float4 xv = reinterpret_cast<const float4*>(x + (size_t)row * D_)[t];

    float s  = xv.x + xv.y + xv.z + xv.w;
    float ss = xv.x*xv.x + xv.y*xv.y + xv.z*xv.z + xv.w*xv.w;
    #pragma unroll
    for (int o = 16; o; o >>= 1) {
        s  += __shfl_xor_sync(0xffffffffu, s,  o);
        ss += __shfl_xor_sync(0xffffffffu, ss, o);
    }
    __shared__ float sh_s[8], sh_ss[8];
    int w = t >> 5;
    if ((t & 31) == 0) { sh_s[w] = s; sh_ss[w] = ss; }
    __syncthreads();
    __shared__ float s_mean, s_inv;
    if (w == 0) {
        s  = (t < 8) ? sh_s[t]  : 0.f;
        ss = (t < 8) ? sh_ss[t] : 0.f;
        #pragma unroll
        for (int o = 4; o; o >>= 1) {
            s  += __shfl_xor_sync(0xffffffffu, s,  o);
            ss += __shfl_xor_sync(0xffffffffu, ss, o);
        }
        if (t == 0) {
            float mean = s * (1.f / D_);
            float var  = ss * (1.f / D_) - mean * mean;
            s_mean = mean;
            s_inv  = rsqrtf(var + 1e-5f);
        }
    }
    __syncthreads();
    float mean = s_mean, inv = s_inv;

    float4 gv = reinterpret_cast<const float4*>(gw)[t];
    float4 bv = reinterpret_cast<const float4*>(bw)[t];
    float o0 = (xv.x - mean) * inv * gv.x + bv.x;
    float o1 = (xv.y - mean) * inv * gv.y + bv.y;
    float o2 = (xv.z - mean) * inv * gv.z + bv.z;
    float o3 = (xv.w - mean) * inv * gv.w + bv.w;

    __nv_bfloat16 h[4], l[4];
    split2(o0, h[0], l[0]); split2(o1, h[1], l[1]);
    split2(o2, h[2], l[2]); split2(o3, h[3], l[3]);
    reinterpret_cast<uint2*>(yhi + (size_t)row * D_)[t] = *reinterpret_cast<uint2*>(h);
    reinterpret_cast<uint2*>(ylo + (size_t)row * D_)[t] = *reinterpret_cast<uint2*>(l);
}

// ---------------- HMMA GEMM: C[m,n] = sum_k A[m,k]*W[n,k] + bias (+res) ----
// 512 threads (16 warps = 4m x 4n), BM=128, BN template, warp tile 32 x (BN/4).
// 4-stage cp.async pipeline, one sync per stage, np-paired B fragments,
// 3-product sweeps (hi*hi, hi*lo, lo*hi).
template<int BN>
__global__ void __launch_bounds__(512, 1)
gemm_mma(const __nv_bfloat16* __restrict__ Ahi, const __nv_bfloat16* __restrict__ Alo,
         const __nv_bfloat16* __restrict__ Whi, const __nv_bfloat16* __restrict__ Wlo,
         const float* __restrict__ bias, const float* __restrict__ res,
         float* __restrict__ C, int Nn)
{
    constexpr int WN    = BN / 4;               // cols per n-warp (64 or 32)
    constexpr int NT    = WN / 8;               // n8 tiles per warp (8 or 4)
    constexpr int NP    = WN / 16;              // ldsm n-groups (4 or 2)
    constexpr int STAGE = (128 + BN) * 128;
    constexpr int PER   = (128 + BN) * 8 / 512; // 16B chunks per thread (6 or 4)

    extern __shared__ char smem[];
    const uint32_t sb = smem_u32(smem);

    const int tid  = threadIdx.x;
    const int lane = tid & 31;
    const int wid  = tid >> 5;
    const int wm   = wid & 3;                   // 4 m-warps (32 rows each)
    const int wn   = wid >> 2;                  // 4 n-warps (WN cols each)
    const int bm   = blockIdx.y * 128;
    const int bn   = blockIdx.x * BN;

    auto load_stage = [&](int s, int k0) {
        const uint32_t base = sb + (uint32_t)((s & 3) * STAGE);
        #pragma unroll
        for (int i = 0; i < PER; i++) {
            const int g   = tid + i * 512;
            const bool isA = (g < 1024);
            const int cid = isA ? g : g - 1024;
            const int r   = cid >> 3;
            const int c   = cid & 7;
            const uint32_t dst = base +
                (uint32_t)((isA ? 0 : 16384) + r * 128 + ((c ^ (r & 7)) * 16));
            const bool hi = (c < 4);
            const int kof = (c & 3) * 8 + k0;
            const __nv_bfloat16* p = isA
                ? (hi ? Ahi : Alo) + (size_t)(bm + r) * K_ + kof
                : (hi ? Whi : Wlo) + (size_t)(bn + r) * K_ + kof;
            cp16(dst, p);
        }
    };

    float acc[2][NT][4];
    #pragma unroll
    for (int i = 0; i < 2; i++)
        #pragma unroll
        for (int j = 0; j < NT; j++)
            #pragma unroll
            for (int q = 0; q < 4; q++) acc[i][j][q] = 0.f;

    const int a_row = wm * 32 + (lane & 7) + ((lane >> 3) & 1) * 8;
    const int a_chk = (lane >> 4) & 1;
    const int b_row = wn * WN + (lane & 7) + ((lane >> 4) & 1) * 8;
    const int b_chk = (lane >> 3) & 1;

    load_stage(0, 0);        cp_commit();
    load_stage(1, BKc_);     cp_commit();
    load_stage(2, 2 * BKc_); cp_commit();

    for (int s = 0; s < NS_; s++) {
        if      (s + 2 < NS_) cp_wait<2>();
        else if (s + 1 < NS_) cp_wait<1>();
        else                  cp_wait<0>();
        __syncthreads();
        if (s + 3 < NS_) { load_stage(s + 3, (s + 3) * BKc_); cp_commit(); }

        const uint32_t ab = sb + (uint32_t)((s & 3) * STAGE);
        const uint32_t wb = ab + 16384;

        #pragma unroll
        for (int kk = 0; kk < 2; kk++) {
            uint32_t ah[2][4], al[2][4];
            #pragma unroll
            for (int mt = 0; mt < 2; mt++) {
                const int row = a_row + mt * 16;
                const int ch  = kk * 2 + a_chk;
                ldsm4(ah[mt], ab + row * 128 + (( ch      ^ (row & 7)) * 16));
                ldsm4(al[mt], ab + row * 128 + (((ch + 4) ^ (row & 7)) * 16));
            }
            // process np groups in pairs -> 4 n8-tiles live at a time
            #pragma unroll
            for (int pp = 0; pp < NP / 2; pp++) {
                uint32_t bh[4][2], bl[4][2];
                #pragma unroll
                for (int q = 0; q < 2; q++) {
                    const int np  = pp * 2 + q;
                    const int row = b_row + np * 16;
                    const int ch  = kk * 2 + b_chk;
                    uint32_t t0[4], t1[4];
                    ldsm4(t0, wb + row * 128 + (( ch      ^ (row & 7)) * 16));
                    ldsm4(t1, wb + row * 128 + (((ch + 4) ^ (row & 7)) * 16));
                    bh[q*2][0]=t0[0]; bh[q*2][1]=t0[1]; bh[q*2+1][0]=t0[2]; bh[q*2+1][1]=t0[3];
                    bl[q*2][0]=t1[0]; bl[q*2][1]=t1[1]; bl[q*2+1][0]=t1[2]; bl[q*2+1][1]=t1[3];
                }
                const int nb = pp * 4;
                #pragma unroll
                for (int nt = 0; nt < 4; nt++)
                    #pragma unroll
                    for (int mt = 0; mt < 2; mt++)
                        mma_bf16(acc[mt][nb + nt], ah[mt], bh[nt]);
                #pragma unroll
                for (int nt = 0; nt < 4; nt++)
                    #pragma unroll
                    for (int mt = 0; mt < 2; mt++)
                        mma_bf16(acc[mt][nb + nt], ah[mt], bl[nt]);
                #pragma unroll
                for (int nt = 0; nt < 4; nt++)
                    #pragma unroll
                    for (int mt = 0; mt < 2; mt++)
                        mma_bf16(acc[mt][nb + nt], al[mt], bh[nt]);
            }
        }
    }

    // ---- epilogue ----
    const int gid = lane >> 2;
    const int tig = lane & 3;
    #pragma unroll
    for (int mt = 0; mt < 2; mt++) {
        const int row0 = bm + wm * 32 + mt * 16 + gid;
        #pragma unroll
        for (int nt = 0; nt < NT; nt++) {
            const int col = bn + wn * WN + nt * 8 + tig * 2;
            const float bx = bias[col], by = bias[col + 1];
            float c0 = acc[mt][nt][0] + bx, c1 = acc[mt][nt][1] + by;
            float c2 = acc[mt][nt][2] + bx, c3 = acc[mt][nt][3] + by;
            if (res) {
                float2 r0 = *reinterpret_cast<const float2*>(&res[(size_t)row0 * Nn + col]);
                float2 r1 = *reinterpret_cast<const float2*>(&res[(size_t)(row0 + 8) * Nn + col]);
                c0 += r0.x; c1 += r0.y; c2 += r1.x; c3 += r1.y;
            }
            *reinterpret_cast<float2*>(&C[(size_t)row0 * Nn + col])       = make_float2(c0, c1);
            *reinterpret_cast<float2*>(&C[(size_t)(row0 + 8) * Nn + col]) = make_float2(c2, c3);
        }
    }
}

// ---------------- chunked linear-attention scan (cp.async prefetched) ----------------
// phase A: per-chunk local end state from zero init (needs K, V)
__global__ void __launch_bounds__(64)
scan_phaseA(const float* __restrict__ qkvg, const float* __restrict__ alog,
            float* __restrict__ st)
{
    const int bh = blockIdx.x, c = blockIdx.y;
    const int b = bh >> 4, h = bh & 15;
    const int j = threadIdx.x;

    __shared__ float sK[4][NST_], sV[4][DH_];

    float alpha[NST_];
    #pragma unroll
    for (int i = 0; i < NST_; i++)
        alpha[i] = 1.f / (1.f + expf(-alog[h * NST_ + i]));
    float hst[NST_];
    #pragma unroll
    for (int i = 0; i < NST_; i++) hst[i] = 0.f;

    const float* rows = qkvg + (size_t)(b * S_ + c * T_) * 4096;
    const int kcol = D_ + h * DH_;
    const int vcol = 2 * D_ + h * DH_;

    auto prefetch = [&](int t) {
        const float* row = rows + (size_t)t * 4096;
        const int slot = t & 3;
        if (j < 8)       cp16(smem_u32(&sK[slot][j * 4]),        row + kcol + j * 4);
        else if (j < 24) cp16(smem_u32(&sV[slot][(j - 8) * 4]),  row + vcol + (j - 8) * 4);
    };
    prefetch(0); cp_commit();
    prefetch(1); cp_commit();
    prefetch(2); cp_commit();

    for (int t = 0; t < T_; t++) {
        if (t + 3 < T_) { prefetch(t + 3); cp_commit(); }
        if      (t + 3 < T_) cp_wait<3>();
        else if (t + 2 < T_) cp_wait<2>();
        else if (t + 1 < T_) cp_wait<1>();
        else                 cp_wait<0>();
        __syncthreads();
        const int slot = t & 3;
        const float v = sV[slot][j];
        #pragma unroll
        for (int i = 0; i < NST_; i++)
            hst[i] = fmaf(alpha[i], hst[i], sK[slot][i] * v);
        __syncthreads();
    }
    float* dst = st + (((size_t)bh * P_ + c) * NST_) * DH_ + j;
    #pragma unroll
    for (int i = 0; i < NST_; i++) dst[i * DH_] = hst[i];
}

// phase B: sequential prefix over P chunks (tiny)
__global__ void __launch_bounds__(64)
scan_phaseB(const float* __restrict__ alog, const float* __restrict__ st,
            float* __restrict__ hin)
{
    const int bh = blockIdx.x;
    const int h = bh & 15;
    const int j = threadIdx.x;

    float aT[NST_];
    #pragma unroll
    for (int i = 0; i < NST_; i++) {
        float a = 1.f / (1.f + expf(-alog[h * NST_ + i]));
        aT[i] = powf(a, (float)T_);
    }
    float Hin[NST_];
    #pragma unroll
    for (int i = 0; i < NST_; i++) Hin[i] = 0.f;

    for (int c = 0; c < P_; c++) {
        float* dst = hin + (((size_t)bh * P_ + c) * NST_) * DH_ + j;
        #pragma unroll
        for (int i = 0; i < NST_; i++) dst[i * DH_] = Hin[i];
        if (c < P_ - 1) {
            const float* src = st + (((size_t)bh * P_ + c) * NST_) * DH_ + j;
            #pragma unroll
            for (int i = 0; i < NST_; i++)
                Hin[i] = fmaf(aT[i], Hin[i], src[i * DH_]);
        }
    }
}

// phase C: rerun chunk with corrected init, gated output (bf16 hi/lo)
__global__ void __launch_bounds__(64)
scan_phaseC(const float* __restrict__ qkvg, const float* __restrict__ alog,
            const float* __restrict__ hin,
            __nv_bfloat16* __restrict__ Ohi, __nv_bfloat16* __restrict__ Olo)
{
    const int bh = blockIdx.x, c = blockIdx.y;
    const int b = bh >> 4, h = bh & 15;
    const int j = threadIdx.x;

    __shared__ float sQ[4][NST_], sK[4][NST_], sV[4][DH_], sG[4][DH_];

    float alpha[NST_];
    #pragma unroll
    for (int i = 0; i < NST_; i++)
        alpha[i] = 1.f / (1.f + expf(-alog[h * NST_ + i]));
    float hst[NST_];
    {
        const float* src = hin + (((size_t)bh * P_ + c) * NST_) * DH_ + j;
        #pragma unroll
        for (int i = 0; i < NST_; i++) hst[i] = src[i * DH_];
    }

    const int m0 = b * S_ + c * T_;
    const float* rows = qkvg + (size_t)m0 * 4096;
    const int qcol = h * DH_;
    const int kcol = D_ + h * DH_;
    const int vcol = 2 * D_ + h * DH_;
    const int gcol = 3 * D_ + h * DH_;
    __nv_bfloat16* oh = Ohi + (size_t)m0 * D_ + h * DH_ + j;
    __nv_bfloat16* ol = Olo + (size_t)m0 * D_ + h * DH_ + j;

    auto prefetch = [&](int t) {
        const float* row = rows + (size_t)t * 4096;
        const int slot = t & 3;
        if (j < 8)       cp16(smem_u32(&sQ[slot][j * 4]),         row + qcol + j * 4);
        else if (j < 16) cp16(smem_u32(&sK[slot][(j - 8)  * 4]),  row + kcol + (j - 8)  * 4);
        else if (j < 32) cp16(smem_u32(&sV[slot][(j - 16) * 4]),  row + vcol + (j - 16) * 4);
        else if (j < 48) cp16(smem_u32(&sG[slot][(j - 32) * 4]),  row + gcol + (j - 32) * 4);
    };
    prefetch(0); cp_commit();
    prefetch(1); cp_commit();
    prefetch(2); cp_commit();

    for (int t = 0; t < T_; t++) {
        if (t + 3 < T_) { prefetch(t + 3); cp_commit(); }
        if      (t + 3 < T_) cp_wait<3>();
        else if (t + 2 < T_) cp_wait<2>();
        else if (t + 1 < T_) cp_wait<1>();
        else                 cp_wait<0>();
        __syncthreads();
        const int slot = t & 3;
        const float v = sV[slot][j];
        float o0 = 0.f, o1 = 0.f, o2 = 0.f, o3 = 0.f;
        #pragma unroll
        for (int i = 0; i < NST_; i += 4) {
            hst[i]   = fmaf(alpha[i],   hst[i],   sK[slot][i]   * v); o0 = fmaf(sQ[slot][i],   hst[i],   o0);
            hst[i+1] = fmaf(alpha[i+1], hst[i+1], sK[slot][i+1] * v); o1 = fmaf(sQ[slot][i+1], hst[i+1], o1);
            hst[i+2] = fmaf(alpha[i+2], hst[i+2], sK[slot][i+2] * v); o2 = fmaf(sQ[slot][i+2], hst[i+2], o2);
            hst[i+3] = fmaf(alpha[i+3], hst[i+3], sK[slot][i+3] * v); o3 = fmaf(sQ[slot][i+3], hst[i+3], o3);
        }
        const float o = (o0 + o1) + (o2 + o3);
        const float gg = sG[slot][j];
        const float ov = o * gg / (1.f + expf(-gg));
        __nv_bfloat16 hh, ll;
        split2(ov, hh, ll);
        *oh = hh; *ol = ll;
        __syncthreads();
        oh += D_; ol += D_;
    }
}

// ---------------- launch ----------------
extern "C" void kernel_launch(void* const* d_in, const int* in_sizes, int n_in,
                              void* d_out, int out_size)
{
    const int*   tokens = (const int*)  d_in[0];
    const float* emb    = (const float*)d_in[1];
    const float* pos    = (const float*)d_in[2];
    const float* ln_g   = (const float*)d_in[3];
    const float* ln_b   = (const float*)d_in[4];
    const float* wq     = (const float*)d_in[5];
    const float* bq     = (const float*)d_in[6];
    const float* wk     = (const float*)d_in[7];
    const float* bk     = (const float*)d_in[8];
    const float* wv     = (const float*)d_in[9];
    const float* bv     = (const float*)d_in[10];
    const float* wg     = (const float*)d_in[11];
    const float* bg     = (const float*)d_in[12];
    const float* wo     = (const float*)d_in[13];
    const float* bo     = (const float*)d_in[14];
    const float* alogit = (const float*)d_in[15];
    const float* fn_g   = (const float*)d_in[16];
    const float* fn_b   = (const float*)d_in[17];
    const float* head_w = (const float*)d_in[18];
    const float* head_b = (const float*)d_in[19];
    float*       out    = (float*)d_out;

    float *px, *pqkvg, *pst, *phin, *pbcat;
    __nv_bfloat16 *pxnh, *pxnl, *poh, *pol;
    __nv_bfloat16 *wch, *wcl, *woh, *wol, *hwh, *hwl;
    cudaGetSymbolAddress((void**)&px,    g_x);
    cudaGetSymbolAddress((void**)&pqkvg, g_qkvg);
    cudaGetSymbolAddress((void**)&pst,   g_st);
    cudaGetSymbolAddress((void**)&phin,  g_hin);
    cudaGetSymbolAddress((void**)&pbcat, g_bcat);
    cudaGetSymbolAddress((void**)&pxnh,  g_xn_hi);
    cudaGetSymbolAddress((void**)&pxnl,  g_xn_lo);
    cudaGetSymbolAddress((void**)&poh,   g_o_hi);
    cudaGetSymbolAddress((void**)&pol,   g_o_lo);
    cudaGetSymbolAddress((void**)&wch,   g_wc_hi); cudaGetSymbolAddress((void**)&wcl, g_wc_lo);
    cudaGetSymbolAddress((void**)&woh,   g_wo_hi); cudaGetSymbolAddress((void**)&wol, g_wo_lo);
    cudaGetSymbolAddress((void**)&hwh,   g_hw_hi); cudaGetSymbolAddress((void**)&hwl, g_hw_lo);

    constexpr int SMEM_256 = 4 * (128 + 256) * 128;   // 196608
    constexpr int SMEM_128 = 4 * (128 + 128) * 128;   // 131072
    cudaFuncSetAttribute(gemm_mma<256>, cudaFuncAttributeMaxDynamicSharedMemorySize, SMEM_256);
    cudaFuncSetAttribute(gemm_mma<128>, cudaFuncAttributeMaxDynamicSharedMemorySize, SMEM_128);

    // launch order: harness prepends 2 launches; ncu -s 5 profiles overall #5
    // = our #3 = the first QKVG GEMM.
    embed_kernel<<<(M_ * D_ / 4) / 256, 256>>>(tokens, emb, pos, px);            // 0
    constexpr int CVT_TOT = (L_*4*D_*D_ + L_*D_*D_ + VOCAB_*D_ + L_*4*D_) / 4;
    cvt_all<<<(CVT_TOT + 255) / 256, 256>>>(wq, wk, wv, wg, wo, head_w,
                                            bq, bk, bv, bg,
                                            wch, wcl, woh, wol, hwh, hwl, pbcat); // 1

    const dim3 qkvg_grid(4 * D_ / 256, M_ / 128);   // (16, 32)
    const dim3 wo_grid(D_ / 256, M_ / 128);         // (4, 32)
    const dim3 head_grid(1, M_ / 128);              // (1, 32)
    const size_t PIECE = (size_t)D_ * D_;

    for (int l = 0; l < L_; l++) {
        const size_t wOff = (size_t)l * PIECE;
        const float* alog = alogit + (size_t)l * H_ * NST_;

        ln_bf16_kernel<<<M_, 256>>>(px, ln_g + l * D_, ln_b + l * D_, pxnh, pxnl); // 2

        gemm_mma<256><<<qkvg_grid, 512, SMEM_256>>>(pxnh, pxnl,                    // 3 <- profiled
            wch + (size_t)l * 4 * PIECE, wcl + (size_t)l * 4 * PIECE,
            pbcat + l * 4 * D_, nullptr, pqkvg, 4 * D_);

        scan_phaseA<<<dim3(B_ * H_, P_ - 1), 64>>>(pqkvg, alog, pst);
        scan_phaseB<<<B_ * H_, 64>>>(alog, pst, phin);
        scan_phaseC<<<dim3(B_ * H_, P_), 64>>>(pqkvg, alog, phin, poh, pol);

        gemm_mma<256><<<wo_grid, 512, SMEM_256>>>(poh, pol, woh + wOff, wol + wOff,
                                                  bo + l * D_, px, px, D_);
    }

    ln_bf16_kernel<<<M_, 256>>>(px, fn_g, fn_b, pxnh, pxnl);
    gemm_mma<128><<<head_grid, 512, SMEM_128>>>(pxnh, pxnl, hwh, hwl,
                                                head_b, nullptr, out, VOCAB_);
}

// round 7
// speedup vs baseline: 3.5968x; 1.0878x over previous
#include <cuda_runtime.h>
#include <cuda_bf16.h>
#include <math.h>
#include <stdint.h>

// ---------------- problem constants ----------------
constexpr int B_    = 8;
constexpr int S_    = 512;
constexpr int D_    = 1024;
constexpr int H_    = 16;
constexpr int DH_   = 64;
constexpr int NST_  = 32;
constexpr int L_    = 2;
constexpr int VOCAB_= 128;
constexpr int M_    = B_ * S_;   // 4096
constexpr int K_    = D_;        // 1024
constexpr int BKc_  = 32;        // K per stage
constexpr int NS_   = K_ / BKc_; // 32 stages
constexpr int T_    = 64;        // scan chunk length
constexpr int P_    = S_ / T_;   // 8 chunks

// ---------------- scratch (static device globals) ----------------
__device__ float g_x   [M_ * D_];
__device__ float g_qkvg[M_ * 4 * D_];
__device__ float g_st  [B_*H_ * P_ * NST_ * DH_];
__device__ float g_hin [B_*H_ * P_ * NST_ * DH_];
__device__ float g_bcat[L_ * 4 * D_];
__device__ __nv_bfloat16 g_xn_hi[M_ * D_], g_xn_lo[M_ * D_];
__device__ __nv_bfloat16 g_o_hi [M_ * D_], g_o_lo [M_ * D_];
__device__ __nv_bfloat16 g_wc_hi[L_*4*D_*D_], g_wc_lo[L_*4*D_*D_];
__device__ __nv_bfloat16 g_wo_hi[L_*D_*D_],   g_wo_lo[L_*D_*D_];
__device__ __nv_bfloat16 g_hw_hi[VOCAB_*D_],  g_hw_lo[VOCAB_*D_];

// ---------------- PTX helpers (baseline sm_80-era ISA only) ----------------
__device__ __forceinline__ uint32_t smem_u32(const void* p) {
    uint32_t a;
    asm("{ .reg .u64 t; cvta.to.shared.u64 t, %1; cvt.u32.u64 %0, t; }" : "=r"(a) : "l"(p));
    return a;
}
__device__ __forceinline__ void cp16(uint32_t dst, const void* src) {
    asm volatile("cp.async.cg.shared.global [%0], [%1], 16;" :: "r"(dst), "l"(src));
}
__device__ __forceinline__ void cp_commit() {
    asm volatile("cp.async.commit_group;" ::: "memory");
}
template<int N>
__device__ __forceinline__ void cp_wait() {
    asm volatile("cp.async.wait_group %0;" :: "n"(N) : "memory");
}
__device__ __forceinline__ void ldsm4(uint32_t* r, uint32_t addr) {
    asm volatile("ldmatrix.sync.aligned.m8n8.x4.shared.b16 {%0,%1,%2,%3}, [%4];"
        : "=r"(r[0]), "=r"(r[1]), "=r"(r[2]), "=r"(r[3]) : "r"(addr));
}
__device__ __forceinline__ void mma_bf16(float* c, const uint32_t* a, const uint32_t* b) {
    asm volatile(
        "mma.sync.aligned.m16n8k16.row.col.f32.bf16.bf16.f32 "
        "{%0,%1,%2,%3}, {%4,%5,%6,%7}, {%8,%9}, {%0,%1,%2,%3};"
        : "+f"(c[0]), "+f"(c[1]), "+f"(c[2]), "+f"(c[3])
        : "r"(a[0]), "r"(a[1]), "r"(a[2]), "r"(a[3]), "r"(b[0]), "r"(b[1]));
}
__device__ __forceinline__ void split2(float v, __nv_bfloat16& h, __nv_bfloat16& l) {
    h = __float2bfloat16(v);
    l = __float2bfloat16(v - __bfloat162float(h));
}

// ---------------- fused fp32 -> bf16 hi/lo for ALL weights + bias pack ----------------
__global__ void __launch_bounds__(256)
cvt_all(const float* __restrict__ wq, const float* __restrict__ wk,
        const float* __restrict__ wv, const float* __restrict__ wg,
        const float* __restrict__ wo, const float* __restrict__ hw,
        const float* __restrict__ bq, const float* __restrict__ bk,
        const float* __restrict__ bv, const float* __restrict__ bg,
        __nv_bfloat16* __restrict__ wch, __nv_bfloat16* __restrict__ wcl,
        __nv_bfloat16* __restrict__ woh, __nv_bfloat16* __restrict__ wol,
        __nv_bfloat16* __restrict__ hwh, __nv_bfloat16* __restrict__ hwl,
        float* __restrict__ bcat)
{
    constexpr int PC4 = D_ * D_ / 4;
    constexpr int WC4 = L_ * 4 * PC4;
    constexpr int WO4 = L_ * PC4;
    constexpr int HW4 = VOCAB_ * D_ / 4;
    constexpr int BC4 = L_ * 4 * D_ / 4;
    int idx = blockIdx.x * 256 + threadIdx.x;
    const float4* src;
    __nv_bfloat16 *dh, *dl;
    int d4;
    if (idx < WC4) {
        int q   = idx >> 18;
        int p   = q & 3;
        int off = idx & (PC4 - 1);
        int l   = q >> 2;
        const float* s = (p == 0) ? wq : (p == 1) ? wk : (p == 2) ? wv : wg;
        src = reinterpret_cast<const float4*>(s) + (size_t)l * PC4 + off;
        dh = wch; dl = wcl; d4 = idx;
    } else if (idx < WC4 + WO4) {
        int j = idx - WC4;
        src = reinterpret_cast<const float4*>(wo) + j;
        dh = woh; dl = wol; d4 = j;
    } else if (idx < WC4 + WO4 + HW4) {
        int j = idx - WC4 - WO4;
        src = reinterpret_cast<const float4*>(hw) + j;
        dh = hwh; dl = hwl; d4 = j;
    } else if (idx < WC4 + WO4 + HW4 + BC4) {
        int j  = idx - WC4 - WO4 - HW4;
        int p4 = j & 255;
        int p  = (j >> 8) & 3;
        int l  = j >> 10;
        const float* s = (p == 0) ? bq : (p == 1) ? bk : (p == 2) ? bv : bg;
        float4 v = reinterpret_cast<const float4*>(s + (size_t)l * D_)[p4];
        reinterpret_cast<float4*>(bcat)[j] = v;
        return;
    } else return;

    float4 v = *src;
    __nv_bfloat16 h[4], l[4];
    split2(v.x, h[0], l[0]); split2(v.y, h[1], l[1]);
    split2(v.z, h[2], l[2]); split2(v.w, h[3], l[3]);
    reinterpret_cast<uint2*>(dh)[d4] = *reinterpret_cast<uint2*>(h);
    reinterpret_cast<uint2*>(dl)[d4] = *reinterpret_cast<uint2*>(l);
}

// ---------------- embed ----------------
__global__ void embed_kernel(const int* __restrict__ tokens,
                             const float* __restrict__ emb,
                             const float* __restrict__ pos,
                             float* __restrict__ x)
{
    int idx = blockIdx.x * blockDim.x + threadIdx.x;
    int row = idx / (D_ / 4);
    int c4  = idx % (D_ / 4);
    int s   = row % S_;
    int tok = tokens[row];
    float4 e = reinterpret_cast<const float4*>(emb + (size_t)tok * D_)[c4];
    float4 p = reinterpret_cast<const float4*>(pos + (size_t)s   * D_)[c4];
    e.x += p.x; e.y += p.y; e.z += p.z; e.w += p.w;
    reinterpret_cast<float4*>(x)[idx] = e;
}

// ---------------- layernorm -> bf16 hi/lo ----------------
__global__ void __launch_bounds__(256)
ln_bf16_kernel(const float* __restrict__ x,
               const float* __restrict__ gw,
               const float* __restrict__ bw,
               __nv_bfloat16* __restrict__ yhi,
               __nv_bfloat16* __restrict__ ylo)
{
    int row = blockIdx.x;
    int t   = threadIdx.x;
    float4 xv = reinterpret_cast<const float4*>(x + (size_t)row * D_)[t];

    float s  = xv.x + xv.y + xv.z + xv.w;
    float ss = xv.x*xv.x + xv.y*xv.y + xv.z*xv.z + xv.w*xv.w;
    #pragma unroll
    for (int o = 16; o; o >>= 1) {
        s  += __shfl_xor_sync(0xffffffffu, s,  o);
        ss += __shfl_xor_sync(0xffffffffu, ss, o);
    }
    __shared__ float sh_s[8], sh_ss[8];
    int w = t >> 5;
    if ((t & 31) == 0) { sh_s[w] = s; sh_ss[w] = ss; }
    __syncthreads();
    __shared__ float s_mean, s_inv;
    if (w == 0) {
        s  = (t < 8) ? sh_s[t]  : 0.f;
        ss = (t < 8) ? sh_ss[t] : 0.f;
        #pragma unroll
        for (int o = 4; o; o >>= 1) {
            s  += __shfl_xor_sync(0xffffffffu, s,  o);
            ss += __shfl_xor_sync(0xffffffffu, ss, o);
        }
        if (t == 0) {
            float mean = s * (1.f / D_);
            float var  = ss * (1.f / D_) - mean * mean;
            s_mean = mean;
            s_inv  = rsqrtf(var + 1e-5f);
        }
    }
    __syncthreads();
    float mean = s_mean, inv = s_inv;

    float4 gv = reinterpret_cast<const float4*>(gw)[t];
    float4 bv = reinterpret_cast<const float4*>(bw)[t];
    float o0 = (xv.x - mean) * inv * gv.x + bv.x;
    float o1 = (xv.y - mean) * inv * gv.y + bv.y;
    float o2 = (xv.z - mean) * inv * gv.z + bv.z;
    float o3 = (xv.w - mean) * inv * gv.w + bv.w;

    __nv_bfloat16 h[4], l[4];
    split2(o0, h[0], l[0]); split2(o1, h[1], l[1]);
    split2(o2, h[2], l[2]); split2(o3, h[3], l[3]);
    reinterpret_cast<uint2*>(yhi + (size_t)row * D_)[t] = *reinterpret_cast<uint2*>(h);
    reinterpret_cast<uint2*>(ylo + (size_t)row * D_)[t] = *reinterpret_cast<uint2*>(l);
}

// ---------------- HMMA GEMM: C[m,n] = sum_k A[m,k]*W[n,k] + bias (+res) ----
// 256 threads (8 warps = 2m x 4n), BM=128, BN=128, warp tile 64x32.
// 3-stage cp.async pipeline (96KB smem) -> 2 CTAs/SM for cross-CTA overlap.
__global__ void __launch_bounds__(256, 2)
gemm_mma(const __nv_bfloat16* __restrict__ Ahi, const __nv_bfloat16* __restrict__ Alo,
         const __nv_bfloat16* __restrict__ Whi, const __nv_bfloat16* __restrict__ Wlo,
         const float* __restrict__ bias, const float* __restrict__ res,
         float* __restrict__ C, int Nn)
{
    constexpr int STAGE = 2 * 128 * 128;   // 32KB: A 16KB + W 16KB
    extern __shared__ char smem[];
    const uint32_t sb = smem_u32(smem);

    const int tid  = threadIdx.x;
    const int lane = tid & 31;
    const int wid  = tid >> 5;
    const int wm   = wid & 1;      // 2 m-warps (64 rows)
    const int wn   = wid >> 1;     // 4 n-warps (32 cols)
    const int bm   = blockIdx.y * 128;
    const int bn   = blockIdx.x * 128;

    auto load_stage = [&](int s, int k0) {
        const uint32_t base = sb + (uint32_t)((s % 3) * STAGE);
        #pragma unroll
        for (int i = 0; i < 8; i++) {
            const int g   = tid + i * 256;
            const bool isA = (g < 1024);
            const int cid = isA ? g : g - 1024;
            const int r   = cid >> 3;
            const int c   = cid & 7;
            const uint32_t dst = base +
                (uint32_t)((isA ? 0 : 16384) + r * 128 + ((c ^ (r & 7)) * 16));
            const bool hi = (c < 4);
            const int kof = (c & 3) * 8 + k0;
            const __nv_bfloat16* p = isA
                ? (hi ? Ahi : Alo) + (size_t)(bm + r) * K_ + kof
                : (hi ? Whi : Wlo) + (size_t)(bn + r) * K_ + kof;
            cp16(dst, p);
        }
    };

    float acc[4][4][4];
    #pragma unroll
    for (int i = 0; i < 4; i++)
        #pragma unroll
        for (int j = 0; j < 4; j++)
            #pragma unroll
            for (int q = 0; q < 4; q++) acc[i][j][q] = 0.f;

    const int a_row = wm * 64 + (lane & 7) + ((lane >> 3) & 1) * 8;
    const int a_chk = (lane >> 4) & 1;
    const int b_row = wn * 32 + (lane & 7) + ((lane >> 4) & 1) * 8;
    const int b_chk = (lane >> 3) & 1;

    load_stage(0, 0);    cp_commit();
    load_stage(1, BKc_); cp_commit();

    for (int s = 0; s < NS_; s++) {
        if (s + 1 < NS_) cp_wait<1>(); else cp_wait<0>();
        __syncthreads();
        if (s + 2 < NS_) { load_stage(s + 2, (s + 2) * BKc_); cp_commit(); }

        const uint32_t ab = sb + (uint32_t)((s % 3) * STAGE);
        const uint32_t wb = ab + 16384;

        #pragma unroll
        for (int kk = 0; kk < 2; kk++) {
            uint32_t ah[4][4], al[4][4];
            #pragma unroll
            for (int mt = 0; mt < 4; mt++) {
                const int row = a_row + mt * 16;
                const int ch  = kk * 2 + a_chk;
                ldsm4(ah[mt], ab + row * 128 + (( ch      ^ (row & 7)) * 16));
                ldsm4(al[mt], ab + row * 128 + (((ch + 4) ^ (row & 7)) * 16));
            }
            #pragma unroll
            for (int np = 0; np < 2; np++) {
                const int row = b_row + np * 16;
                const int ch  = kk * 2 + b_chk;
                uint32_t t0[4], t1[4];
                ldsm4(t0, wb + row * 128 + (( ch      ^ (row & 7)) * 16));
                ldsm4(t1, wb + row * 128 + (((ch + 4) ^ (row & 7)) * 16));
                uint32_t bh[2][2] = {{t0[0], t0[1]}, {t0[2], t0[3]}};
                uint32_t bl[2][2] = {{t1[0], t1[1]}, {t1[2], t1[3]}};
                // sweeps: each acc touched once per 8-MMA sweep; cross-CTA
                // overlap (2 CTAs/SM) hides the dep latency.
                #pragma unroll
                for (int q = 0; q < 2; q++)
                    #pragma unroll
                    for (int mt = 0; mt < 4; mt++)
                        mma_bf16(acc[mt][np*2+q], ah[mt], bh[q]);
                #pragma unroll
                for (int q = 0; q < 2; q++)
                    #pragma unroll
                    for (int mt = 0; mt < 4; mt++)
                        mma_bf16(acc[mt][np*2+q], ah[mt], bl[q]);
                #pragma unroll
                for (int q = 0; q < 2; q++)
                    #pragma unroll
                    for (int mt = 0; mt < 4; mt++)
                        mma_bf16(acc[mt][np*2+q], al[mt], bh[q]);
            }
        }
    }

    // ---- epilogue ----
    const int gid = lane >> 2;
    const int tig = lane & 3;
    #pragma unroll
    for (int mt = 0; mt < 4; mt++) {
        const int row0 = bm + wm * 64 + mt * 16 + gid;
        #pragma unroll
        for (int nt = 0; nt < 4; nt++) {
            const int col = bn + wn * 32 + nt * 8 + tig * 2;
            const float bx = bias[col], by = bias[col + 1];
            float c0 = acc[mt][nt][0] + bx, c1 = acc[mt][nt][1] + by;
            float c2 = acc[mt][nt][2] + bx, c3 = acc[mt][nt][3] + by;
            if (res) {
                float2 r0 = *reinterpret_cast<const float2*>(&res[(size_t)row0 * Nn + col]);
                float2 r1 = *reinterpret_cast<const float2*>(&res[(size_t)(row0 + 8) * Nn + col]);
                c0 += r0.x; c1 += r0.y; c2 += r1.x; c3 += r1.y;
            }
            *reinterpret_cast<float2*>(&C[(size_t)row0 * Nn + col])       = make_float2(c0, c1);
            *reinterpret_cast<float2*>(&C[(size_t)(row0 + 8) * Nn + col]) = make_float2(c2, c3);
        }
    }
}

// ---------------- chunked linear-attention scan (cp.async prefetched) ----------------
__global__ void __launch_bounds__(64)
scan_phaseA(const float* __restrict__ qkvg, const float* __restrict__ alog,
            float* __restrict__ st)
{
    const int bh = blockIdx.x, c = blockIdx.y;
    const int b = bh >> 4, h = bh & 15;
    const int j = threadIdx.x;

    __shared__ float sK[4][NST_], sV[4][DH_];

    float alpha[NST_];
    #pragma unroll
    for (int i = 0; i < NST_; i++)
        alpha[i] = 1.f / (1.f + expf(-alog[h * NST_ + i]));
    float hst[NST_];
    #pragma unroll
    for (int i = 0; i < NST_; i++) hst[i] = 0.f;

    const float* rows = qkvg + (size_t)(b * S_ + c * T_) * 4096;
    const int kcol = D_ + h * DH_;
    const int vcol = 2 * D_ + h * DH_;

    auto prefetch = [&](int t) {
        const float* row = rows + (size_t)t * 4096;
        const int slot = t & 3;
        if (j < 8)       cp16(smem_u32(&sK[slot][j * 4]),        row + kcol + j * 4);
        else if (j < 24) cp16(smem_u32(&sV[slot][(j - 8) * 4]),  row + vcol + (j - 8) * 4);
    };
    prefetch(0); cp_commit();
    prefetch(1); cp_commit();
    prefetch(2); cp_commit();

    for (int t = 0; t < T_; t++) {
        if (t + 3 < T_) { prefetch(t + 3); cp_commit(); }
        if      (t + 3 < T_) cp_wait<3>();
        else if (t + 2 < T_) cp_wait<2>();
        else if (t + 1 < T_) cp_wait<1>();
        else                 cp_wait<0>();
        __syncthreads();
        const int slot = t & 3;
        const float v = sV[slot][j];
        #pragma unroll
        for (int i = 0; i < NST_; i++)
            hst[i] = fmaf(alpha[i], hst[i], sK[slot][i] * v);
        __syncthreads();
    }
    float* dst = st + (((size_t)bh * P_ + c) * NST_) * DH_ + j;
    #pragma unroll
    for (int i = 0; i < NST_; i++) dst[i * DH_] = hst[i];
}

__global__ void __launch_bounds__(64)
scan_phaseB(const float* __restrict__ alog, const float* __restrict__ st,
            float* __restrict__ hin)
{
    const int bh = blockIdx.x;
    const int h = bh & 15;
    const int j = threadIdx.x;

    float aT[NST_];
    #pragma unroll
    for (int i = 0; i < NST_; i++) {
        float a = 1.f / (1.f + expf(-alog[h * NST_ + i]));
        aT[i] = powf(a, (float)T_);
    }
    float Hin[NST_];
    #pragma unroll
    for (int i = 0; i < NST_; i++) Hin[i] = 0.f;

    for (int c = 0; c < P_; c++) {
        float* dst = hin + (((size_t)bh * P_ + c) * NST_) * DH_ + j;
        #pragma unroll
        for (int i = 0; i < NST_; i++) dst[i * DH_] = Hin[i];
        if (c < P_ - 1) {
            const float* src = st + (((size_t)bh * P_ + c) * NST_) * DH_ + j;
            #pragma unroll
            for (int i = 0; i < NST_; i++)
                Hin[i] = fmaf(aT[i], Hin[i], src[i * DH_]);
        }
    }
}

__global__ void __launch_bounds__(64)
scan_phaseC(const float* __restrict__ qkvg, const float* __restrict__ alog,
            const float* __restrict__ hin,
            __nv_bfloat16* __restrict__ Ohi, __nv_bfloat16* __restrict__ Olo)
{
    const int bh = blockIdx.x, c = blockIdx.y;
    const int b = bh >> 4, h = bh & 15;
    const int j = threadIdx.x;

    __shared__ float sQ[4][NST_], sK[4][NST_], sV[4][DH_], sG[4][DH_];

    float alpha[NST_];
    #pragma unroll
    for (int i = 0; i < NST_; i++)
        alpha[i] = 1.f / (1.f + expf(-alog[h * NST_ + i]));
    float hst[NST_];
    {
        const float* src = hin + (((size_t)bh * P_ + c) * NST_) * DH_ + j;
        #pragma unroll
        for (int i = 0; i < NST_; i++) hst[i] = src[i * DH_];
    }

    const int m0 = b * S_ + c * T_;
    const float* rows = qkvg + (size_t)m0 * 4096;
    const int qcol = h * DH_;
    const int kcol = D_ + h * DH_;
    const int vcol = 2 * D_ + h * DH_;
    const int gcol = 3 * D_ + h * DH_;
    __nv_bfloat16* oh = Ohi + (size_t)m0 * D_ + h * DH_ + j;
    __nv_bfloat16* ol = Olo + (size_t)m0 * D_ + h * DH_ + j;

    auto prefetch = [&](int t) {
        const float* row = rows + (size_t)t * 4096;
        const int slot = t & 3;
        if (j < 8)       cp16(smem_u32(&sQ[slot][j * 4]),         row + qcol + j * 4);
        else if (j < 16) cp16(smem_u32(&sK[slot][(j - 8)  * 4]),  row + kcol + (j - 8)  * 4);
        else if (j < 32) cp16(smem_u32(&sV[slot][(j - 16) * 4]),  row + vcol + (j - 16) * 4);
        else if (j < 48) cp16(smem_u32(&sG[slot][(j - 32) * 4]),  row + gcol + (j - 32) * 4);
    };
    prefetch(0); cp_commit();
    prefetch(1); cp_commit();
    prefetch(2); cp_commit();

    for (int t = 0; t < T_; t++) {
        if (t + 3 < T_) { prefetch(t + 3); cp_commit(); }
        if      (t + 3 < T_) cp_wait<3>();
        else if (t + 2 < T_) cp_wait<2>();
        else if (t + 1 < T_) cp_wait<1>();
        else                 cp_wait<0>();
        __syncthreads();
        const int slot = t & 3;
        const float v = sV[slot][j];
        float o0 = 0.f, o1 = 0.f, o2 = 0.f, o3 = 0.f;
        #pragma unroll
        for (int i = 0; i < NST_; i += 4) {
            hst[i]   = fmaf(alpha[i],   hst[i],   sK[slot][i]   * v); o0 = fmaf(sQ[slot][i],   hst[i],   o0);
            hst[i+1] = fmaf(alpha[i+1], hst[i+1], sK[slot][i+1] * v); o1 = fmaf(sQ[slot][i+1], hst[i+1], o1);
            hst[i+2] = fmaf(alpha[i+2], hst[i+2], sK[slot][i+2] * v); o2 = fmaf(sQ[slot][i+2], hst[i+2], o2);
            hst[i+3] = fmaf(alpha[i+3], hst[i+3], sK[slot][i+3] * v); o3 = fmaf(sQ[slot][i+3], hst[i+3], o3);
        }
        const float o = (o0 + o1) + (o2 + o3);
        const float gg = sG[slot][j];
        const float ov = o * gg / (1.f + expf(-gg));
        __nv_bfloat16 hh, ll;
        split2(ov, hh, ll);
        *oh = hh; *ol = ll;
        __syncthreads();
        oh += D_; ol += D_;
    }
}

// ---------------- launch ----------------
extern "C" void kernel_launch(void* const* d_in, const int* in_sizes, int n_in,
                              void* d_out, int out_size)
{
    const int*   tokens = (const int*)  d_in[0];
    const float* emb    = (const float*)d_in[1];
    const float* pos    = (const float*)d_in[2];
    const float* ln_g   = (const float*)d_in[3];
    const float* ln_b   = (const float*)d_in[4];
    const float* wq     = (const float*)d_in[5];
    const float* bq     = (const float*)d_in[6];
    const float* wk     = (const float*)d_in[7];
    const float* bk     = (const float*)d_in[8];
    const float* wv     = (const float*)d_in[9];
    const float* bv     = (const float*)d_in[10];
    const float* wg     = (const float*)d_in[11];
    const float* bg     = (const float*)d_in[12];
    const float* wo     = (const float*)d_in[13];
    const float* bo     = (const float*)d_in[14];
    const float* alogit = (const float*)d_in[15];
    const float* fn_g   = (const float*)d_in[16];
    const float* fn_b   = (const float*)d_in[17];
    const float* head_w = (const float*)d_in[18];
    const float* head_b = (const float*)d_in[19];
    float*       out    = (float*)d_out;

    float *px, *pqkvg, *pst, *phin, *pbcat;
    __nv_bfloat16 *pxnh, *pxnl, *poh, *pol;
    __nv_bfloat16 *wch, *wcl, *woh, *wol, *hwh, *hwl;
    cudaGetSymbolAddress((void**)&px,    g_x);
    cudaGetSymbolAddress((void**)&pqkvg, g_qkvg);
    cudaGetSymbolAddress((void**)&pst,   g_st);
    cudaGetSymbolAddress((void**)&phin,  g_hin);
    cudaGetSymbolAddress((void**)&pbcat, g_bcat);
    cudaGetSymbolAddress((void**)&pxnh,  g_xn_hi);
    cudaGetSymbolAddress((void**)&pxnl,  g_xn_lo);
    cudaGetSymbolAddress((void**)&poh,   g_o_hi);
    cudaGetSymbolAddress((void**)&pol,   g_o_lo);
    cudaGetSymbolAddress((void**)&wch,   g_wc_hi); cudaGetSymbolAddress((void**)&wcl, g_wc_lo);
    cudaGetSymbolAddress((void**)&woh,   g_wo_hi); cudaGetSymbolAddress((void**)&wol, g_wo_lo);
    cudaGetSymbolAddress((void**)&hwh,   g_hw_hi); cudaGetSymbolAddress((void**)&hwl, g_hw_lo);

    constexpr int SMEM_GEMM = 3 * 2 * 128 * 128;   // 98304 (3 stages x 32KB)
    cudaFuncSetAttribute(gemm_mma, cudaFuncAttributeMaxDynamicSharedMemorySize, SMEM_GEMM);

    // launch order: harness prepends 2 launches; ncu -s 5 profiles overall #5
    // = our #3 = the first QKVG GEMM.
    embed_kernel<<<(M_ * D_ / 4) / 256, 256>>>(tokens, emb, pos, px);            // 0
    constexpr int CVT_TOT = (L_*4*D_*D_ + L_*D_*D_ + VOCAB_*D_ + L_*4*D_) / 4;
    cvt_all<<<(CVT_TOT + 255) / 256, 256>>>(wq, wk, wv, wg, wo, head_w,
                                            bq, bk, bv, bg,
                                            wch, wcl, woh, wol, hwh, hwl, pbcat); // 1

    const dim3 qkvg_grid(4 * D_ / 128, M_ / 128);   // (32, 32) = 1024 CTAs
    const dim3 wo_grid(D_ / 128, M_ / 128);         // (8, 32)  = 256 CTAs
    const dim3 head_grid(1, M_ / 128);              // (1, 32)
    const size_t PIECE = (size_t)D_ * D_;

    for (int l = 0; l < L_; l++) {
        const size_t wOff = (size_t)l * PIECE;
        const float* alog = alogit + (size_t)l * H_ * NST_;

        ln_bf16_kernel<<<M_, 256>>>(px, ln_g + l * D_, ln_b + l * D_, pxnh, pxnl); // 2

        gemm_mma<<<qkvg_grid, 256, SMEM_GEMM>>>(pxnh, pxnl,                        // 3 <- profiled
            wch + (size_t)l * 4 * PIECE, wcl + (size_t)l * 4 * PIECE,
            pbcat + l * 4 * D_, nullptr, pqkvg, 4 * D_);

        scan_phaseA<<<dim3(B_ * H_, P_ - 1), 64>>>(pqkvg, alog, pst);
        scan_phaseB<<<B_ * H_, 64>>>(alog, pst, phin);
        scan_phaseC<<<dim3(B_ * H_, P_), 64>>>(pqkvg, alog, phin, poh, pol);

        gemm_mma<<<wo_grid, 256, SMEM_GEMM>>>(poh, pol, woh + wOff, wol + wOff,
                                              bo + l * D_, px, px, D_);
    }

    ln_bf16_kernel<<<M_, 256>>>(px, fn_g, fn_b, pxnh, pxnl);
    gemm_mma<<<head_grid, 256, SMEM_GEMM>>>(pxnh, pxnl, hwh, hwl,
                                            head_b, nullptr, out, VOCAB_);
}

// round 8
// speedup vs baseline: 3.7561x; 1.0443x over previous
#include <cuda_runtime.h>
#include <cuda_bf16.h>
#include <math.h>
#include <stdint.h>

// ---------------- problem constants ----------------
constexpr int B_    = 8;
constexpr int S_    = 512;
constexpr int D_    = 1024;
constexpr int H_    = 16;
constexpr int DH_   = 64;
constexpr int NST_  = 32;
constexpr int L_    = 2;
constexpr int VOCAB_= 128;
constexpr int M_    = B_ * S_;   // 4096
constexpr int K_    = D_;        // 1024
constexpr int BKc_  = 32;        // K per stage
constexpr int NS_   = K_ / BKc_; // 32 stages
constexpr int T_    = 64;        // scan chunk length
constexpr int P_    = S_ / T_;   // 8 chunks

// ---------------- scratch (static device globals) ----------------
__device__ float g_x   [M_ * D_];
__device__ float g_qkvg[M_ * 4 * D_];
__device__ float g_st  [B_*H_ * P_ * NST_ * DH_];
__device__ float g_hin [B_*H_ * P_ * NST_ * DH_];
__device__ float g_bcat[L_ * 4 * D_];
__device__ __nv_bfloat16 g_xn_hi[M_ * D_], g_xn_lo[M_ * D_];
__device__ __nv_bfloat16 g_o_hi [M_ * D_], g_o_lo [M_ * D_];
__device__ __nv_bfloat16 g_wc_hi[L_*4*D_*D_], g_wc_lo[L_*4*D_*D_];
__device__ __nv_bfloat16 g_wo_hi[L_*D_*D_],   g_wo_lo[L_*D_*D_];
__device__ __nv_bfloat16 g_hw_hi[VOCAB_*D_],  g_hw_lo[VOCAB_*D_];

// ---------------- PTX helpers (baseline sm_80-era ISA only) ----------------
__device__ __forceinline__ uint32_t smem_u32(const void* p) {
    uint32_t a;
    asm("{ .reg .u64 t; cvta.to.shared.u64 t, %1; cvt.u32.u64 %0, t; }" : "=r"(a) : "l"(p));
    return a;
}
__device__ __forceinline__ void cp16(uint32_t dst, const void* src) {
    asm volatile("cp.async.cg.shared.global [%0], [%1], 16;" :: "r"(dst), "l"(src));
}
__device__ __forceinline__ void cp_commit() {
    asm volatile("cp.async.commit_group;" ::: "memory");
}
template<int N>
__device__ __forceinline__ void cp_wait() {
    asm volatile("cp.async.wait_group %0;" :: "n"(N) : "memory");
}
__device__ __forceinline__ void ldsm4(uint32_t* r, uint32_t addr) {
    asm volatile("ldmatrix.sync.aligned.m8n8.x4.shared.b16 {%0,%1,%2,%3}, [%4];"
        : "=r"(r[0]), "=r"(r[1]), "=r"(r[2]), "=r"(r[3]) : "r"(addr));
}
__device__ __forceinline__ void mma_bf16(float* c, const uint32_t* a, const uint32_t* b) {
    asm volatile(
        "mma.sync.aligned.m16n8k16.row.col.f32.bf16.bf16.f32 "
        "{%0,%1,%2,%3}, {%4,%5,%6,%7}, {%8,%9}, {%0,%1,%2,%3};"
        : "+f"(c[0]), "+f"(c[1]), "+f"(c[2]), "+f"(c[3])
        : "r"(a[0]), "r"(a[1]), "r"(a[2]), "r"(a[3]), "r"(b[0]), "r"(b[1]));
}
__device__ __forceinline__ void split2(float v, __nv_bfloat16& h, __nv_bfloat16& l) {
    h = __float2bfloat16(v);
    l = __float2bfloat16(v - __bfloat162float(h));
}

// ---------------- fused fp32 -> bf16 hi/lo for ALL weights + bias pack ----------------
__global__ void __launch_bounds__(256)
cvt_all(const float* __restrict__ wq, const float* __restrict__ wk,
        const float* __restrict__ wv, const float* __restrict__ wg,
        const float* __restrict__ wo, const float* __restrict__ hw,
        const float* __restrict__ bq, const float* __restrict__ bk,
        const float* __restrict__ bv, const float* __restrict__ bg,
        __nv_bfloat16* __restrict__ wch, __nv_bfloat16* __restrict__ wcl,
        __nv_bfloat16* __restrict__ woh, __nv_bfloat16* __restrict__ wol,
        __nv_bfloat16* __restrict__ hwh, __nv_bfloat16* __restrict__ hwl,
        float* __restrict__ bcat)
{
    constexpr int PC4 = D_ * D_ / 4;
    constexpr int WC4 = L_ * 4 * PC4;
    constexpr int WO4 = L_ * PC4;
    constexpr int HW4 = VOCAB_ * D_ / 4;
    constexpr int BC4 = L_ * 4 * D_ / 4;
    int idx = blockIdx.x * 256 + threadIdx.x;
    const float4* src;
    __nv_bfloat16 *dh, *dl;
    int d4;
    if (idx < WC4) {
        int q   = idx >> 18;
        int p   = q & 3;
        int off = idx & (PC4 - 1);
        int l   = q >> 2;
        const float* s = (p == 0) ? wq : (p == 1) ? wk : (p == 2) ? wv : wg;
        src = reinterpret_cast<const float4*>(s) + (size_t)l * PC4 + off;
        dh = wch; dl = wcl; d4 = idx;
    } else if (idx < WC4 + WO4) {
        int j = idx - WC4;
        src = reinterpret_cast<const float4*>(wo) + j;
        dh = woh; dl = wol; d4 = j;
    } else if (idx < WC4 + WO4 + HW4) {
        int j = idx - WC4 - WO4;
        src = reinterpret_cast<const float4*>(hw) + j;
        dh = hwh; dl = hwl; d4 = j;
    } else if (idx < WC4 + WO4 + HW4 + BC4) {
        int j  = idx - WC4 - WO4 - HW4;
        int p4 = j & 255;
        int p  = (j >> 8) & 3;
        int l  = j >> 10;
        const float* s = (p == 0) ? bq : (p == 1) ? bk : (p == 2) ? bv : bg;
        float4 v = reinterpret_cast<const float4*>(s + (size_t)l * D_)[p4];
        reinterpret_cast<float4*>(bcat)[j] = v;
        return;
    } else return;

    float4 v = *src;
    __nv_bfloat16 h[4], l[4];
    split2(v.x, h[0], l[0]); split2(v.y, h[1], l[1]);
    split2(v.z, h[2], l[2]); split2(v.w, h[3], l[3]);
    reinterpret_cast<uint2*>(dh)[d4] = *reinterpret_cast<uint2*>(h);
    reinterpret_cast<uint2*>(dl)[d4] = *reinterpret_cast<uint2*>(l);
}

// ---------------- embed ----------------
__global__ void embed_kernel(const int* __restrict__ tokens,
                             const float* __restrict__ emb,
                             const float* __restrict__ pos,
                             float* __restrict__ x)
{
    int idx = blockIdx.x * blockDim.x + threadIdx.x;
    int row = idx / (D_ / 4);
    int c4  = idx % (D_ / 4);
    int s   = row % S_;
    int tok = tokens[row];
    float4 e = reinterpret_cast<const float4*>(emb + (size_t)tok * D_)[c4];
    float4 p = reinterpret_cast<const float4*>(pos + (size_t)s   * D_)[c4];
    e.x += p.x; e.y += p.y; e.z += p.z; e.w += p.w;
    reinterpret_cast<float4*>(x)[idx] = e;
}

// ---------------- layernorm -> bf16 hi/lo ----------------
__global__ void __launch_bounds__(256)
ln_bf16_kernel(const float* __restrict__ x,
               const float* __restrict__ gw,
               const float* __restrict__ bw,
               __nv_bfloat16* __restrict__ yhi,
               __nv_bfloat16* __restrict__ ylo)
{
    int row = blockIdx.x;
    int t   = threadIdx.x;
    float4 xv = reinterpret_cast<const float4*>(x + (size_t)row * D_)[t];

    float s  = xv.x + xv.y + xv.z + xv.w;
    float ss = xv.x*xv.x + xv.y*xv.y + xv.z*xv.z + xv.w*xv.w;
    #pragma unroll
    for (int o = 16; o; o >>= 1) {
        s  += __shfl_xor_sync(0xffffffffu, s,  o);
        ss += __shfl_xor_sync(0xffffffffu, ss, o);
    }
    __shared__ float sh_s[8], sh_ss[8];
    int w = t >> 5;
    if ((t & 31) == 0) { sh_s[w] = s; sh_ss[w] = ss; }
    __syncthreads();
    __shared__ float s_mean, s_inv;
    if (w == 0) {
        s  = (t < 8) ? sh_s[t]  : 0.f;
        ss = (t < 8) ? sh_ss[t] : 0.f;
        #pragma unroll
        for (int o = 4; o; o >>= 1) {
            s  += __shfl_xor_sync(0xffffffffu, s,  o);
            ss += __shfl_xor_sync(0xffffffffu, ss, o);
        }
        if (t == 0) {
            float mean = s * (1.f / D_);
            float var  = ss * (1.f / D_) - mean * mean;
            s_mean = mean;
            s_inv  = rsqrtf(var + 1e-5f);
        }
    }
    __syncthreads();
    float mean = s_mean, inv = s_inv;

    float4 gv = reinterpret_cast<const float4*>(gw)[t];
    float4 bv = reinterpret_cast<const float4*>(bw)[t];
    float o0 = (xv.x - mean) * inv * gv.x + bv.x;
    float o1 = (xv.y - mean) * inv * gv.y + bv.y;
    float o2 = (xv.z - mean) * inv * gv.z + bv.z;
    float o3 = (xv.w - mean) * inv * gv.w + bv.w;

    __nv_bfloat16 h[4], l[4];
    split2(o0, h[0], l[0]); split2(o1, h[1], l[1]);
    split2(o2, h[2], l[2]); split2(o3, h[3], l[3]);
    reinterpret_cast<uint2*>(yhi + (size_t)row * D_)[t] = *reinterpret_cast<uint2*>(h);
    reinterpret_cast<uint2*>(ylo + (size_t)row * D_)[t] = *reinterpret_cast<uint2*>(l);
}

// ---------------- HMMA GEMM: C[m,n] = sum_k A[m,k]*W[n,k] + bias (+res) ----
// 256 threads (8 warps = 2m x 4n), BM template (128 big / 32 head), BN=128,
// warp tile (BM/2) x 32. 3-stage cp.async pipeline, 2 CTAs/SM overlap.
template<int BM, bool RES>
__global__ void __launch_bounds__(256, 2)
gemm_mma(const __nv_bfloat16* __restrict__ Ahi, const __nv_bfloat16* __restrict__ Alo,
         const __nv_bfloat16* __restrict__ Whi, const __nv_bfloat16* __restrict__ Wlo,
         const float* __restrict__ bias, const float* __restrict__ res,
         float* __restrict__ C, int Nn)
{
    constexpr int MT    = BM / 32;               // m16 tiles per warp
    constexpr int ABYTES= BM * 128;              // A bytes per stage
    constexpr int STAGE = (BM + 128) * 128;      // bytes per stage
    constexpr int NCHNK = (BM + 128) * 8;        // 16B chunks per stage
    constexpr int PER   = NCHNK / 256;           // chunks per thread (8 / 6 / 5)

    extern __shared__ char smem[];
    const uint32_t sb = smem_u32(smem);

    const int tid  = threadIdx.x;
    const int lane = tid & 31;
    const int wid  = tid >> 5;
    const int wm   = wid & 1;      // 2 m-warps (BM/2 rows)
    const int wn   = wid >> 1;     // 4 n-warps (32 cols)
    const int bm   = blockIdx.y * BM;
    const int bn   = blockIdx.x * 128;

    auto load_stage = [&](int s, int k0) {
        const uint32_t base = sb + (uint32_t)((s % 3) * STAGE);
        #pragma unroll
        for (int i = 0; i < PER; i++) {
            const int g   = tid + i * 256;
            const bool isA = (g < BM * 8);
            const int cid = isA ? g : g - BM * 8;
            const int r   = cid >> 3;
            const int c   = cid & 7;
            const uint32_t dst = base +
                (uint32_t)((isA ? 0 : ABYTES) + r * 128 + ((c ^ (r & 7)) * 16));
            const bool hi = (c < 4);
            const int kof = (c & 3) * 8 + k0;
            const __nv_bfloat16* p = isA
                ? (hi ? Ahi : Alo) + (size_t)(bm + r) * K_ + kof
                : (hi ? Whi : Wlo) + (size_t)(bn + r) * K_ + kof;
            cp16(dst, p);
        }
    };

    float acc[MT][4][4];
    #pragma unroll
    for (int i = 0; i < MT; i++)
        #pragma unroll
        for (int j = 0; j < 4; j++)
            #pragma unroll
            for (int q = 0; q < 4; q++) acc[i][j][q] = 0.f;

    const int a_row = wm * (BM / 2) + (lane & 7) + ((lane >> 3) & 1) * 8;
    const int a_chk = (lane >> 4) & 1;
    const int b_row = wn * 32 + (lane & 7) + ((lane >> 4) & 1) * 8;
    const int b_chk = (lane >> 3) & 1;

    load_stage(0, 0);    cp_commit();
    load_stage(1, BKc_); cp_commit();

    for (int s = 0; s < NS_; s++) {
        if (s + 1 < NS_) cp_wait<1>(); else cp_wait<0>();
        __syncthreads();
        if (s + 2 < NS_) { load_stage(s + 2, (s + 2) * BKc_); cp_commit(); }

        const uint32_t ab = sb + (uint32_t)((s % 3) * STAGE);
        const uint32_t wb = ab + ABYTES;

        #pragma unroll
        for (int kk = 0; kk < 2; kk++) {
            uint32_t ah[MT][4], al[MT][4];
            #pragma unroll
            for (int mt = 0; mt < MT; mt++) {
                const int row = a_row + mt * 16;
                const int ch  = kk * 2 + a_chk;
                ldsm4(ah[mt], ab + row * 128 + (( ch      ^ (row & 7)) * 16));
                ldsm4(al[mt], ab + row * 128 + (((ch + 4) ^ (row & 7)) * 16));
            }
            #pragma unroll
            for (int np = 0; np < 2; np++) {
                const int row = b_row + np * 16;
                const int ch  = kk * 2 + b_chk;
                uint32_t t0[4], t1[4];
                ldsm4(t0, wb + row * 128 + (( ch      ^ (row & 7)) * 16));
                ldsm4(t1, wb + row * 128 + (((ch + 4) ^ (row & 7)) * 16));
                uint32_t bh[2][2] = {{t0[0], t0[1]}, {t0[2], t0[3]}};
                uint32_t bl[2][2] = {{t1[0], t1[1]}, {t1[2], t1[3]}};
                #pragma unroll
                for (int q = 0; q < 2; q++)
                    #pragma unroll
                    for (int mt = 0; mt < MT; mt++)
                        mma_bf16(acc[mt][np*2+q], ah[mt], bh[q]);
                #pragma unroll
                for (int q = 0; q < 2; q++)
                    #pragma unroll
                    for (int mt = 0; mt < MT; mt++)
                        mma_bf16(acc[mt][np*2+q], ah[mt], bl[q]);
                #pragma unroll
                for (int q = 0; q < 2; q++)
                    #pragma unroll
                    for (int mt = 0; mt < MT; mt++)
                        mma_bf16(acc[mt][np*2+q], al[mt], bh[q]);
            }
        }
    }

    // ---- epilogue ----
    const int gid = lane >> 2;
    const int tig = lane & 3;
    #pragma unroll
    for (int mt = 0; mt < MT; mt++) {
        const int row0 = bm + wm * (BM / 2) + mt * 16 + gid;
        #pragma unroll
        for (int nt = 0; nt < 4; nt++) {
            const int col = bn + wn * 32 + nt * 8 + tig * 2;
            const float bx = bias[col], by = bias[col + 1];
            float c0 = acc[mt][nt][0] + bx, c1 = acc[mt][nt][1] + by;
            float c2 = acc[mt][nt][2] + bx, c3 = acc[mt][nt][3] + by;
            if (RES) {
                float2 r0 = *reinterpret_cast<const float2*>(&res[(size_t)row0 * Nn + col]);
                float2 r1 = *reinterpret_cast<const float2*>(&res[(size_t)(row0 + 8) * Nn + col]);
                c0 += r0.x; c1 += r0.y; c2 += r1.x; c3 += r1.y;
            }
            *reinterpret_cast<float2*>(&C[(size_t)row0 * Nn + col])       = make_float2(c0, c1);
            *reinterpret_cast<float2*>(&C[(size_t)(row0 + 8) * Nn + col]) = make_float2(c2, c3);
        }
    }
}

// ---------------- chunked linear-attention scan (cp.async prefetched) ----------------
__global__ void __launch_bounds__(64)
scan_phaseA(const float* __restrict__ qkvg, const float* __restrict__ alog,
            float* __restrict__ st)
{
    const int bh = blockIdx.x, c = blockIdx.y;
    const int b = bh >> 4, h = bh & 15;
    const int j = threadIdx.x;

    __shared__ float sK[4][NST_], sV[4][DH_];

    float alpha[NST_];
    #pragma unroll
    for (int i = 0; i < NST_; i++)
        alpha[i] = 1.f / (1.f + expf(-alog[h * NST_ + i]));
    float hst[NST_];
    #pragma unroll
    for (int i = 0; i < NST_; i++) hst[i] = 0.f;

    const float* rows = qkvg + (size_t)(b * S_ + c * T_) * 4096;
    const int kcol = D_ + h * DH_;
    const int vcol = 2 * D_ + h * DH_;

    auto prefetch = [&](int t) {
        const float* row = rows + (size_t)t * 4096;
        const int slot = t & 3;
        if (j < 8)       cp16(smem_u32(&sK[slot][j * 4]),        row + kcol + j * 4);
        else if (j < 24) cp16(smem_u32(&sV[slot][(j - 8) * 4]),  row + vcol + (j - 8) * 4);
    };
    prefetch(0); cp_commit();
    prefetch(1); cp_commit();
    prefetch(2); cp_commit();

    for (int t = 0; t < T_; t++) {
        if (t + 3 < T_) { prefetch(t + 3); cp_commit(); }
        if      (t + 3 < T_) cp_wait<3>();
        else if (t + 2 < T_) cp_wait<2>();
        else if (t + 1 < T_) cp_wait<1>();
        else                 cp_wait<0>();
        __syncthreads();
        const int slot = t & 3;
        const float v = sV[slot][j];
        #pragma unroll
        for (int i = 0; i < NST_; i++)
            hst[i] = fmaf(alpha[i], hst[i], sK[slot][i] * v);
        __syncthreads();
    }
    float* dst = st + (((size_t)bh * P_ + c) * NST_) * DH_ + j;
    #pragma unroll
    for (int i = 0; i < NST_; i++) dst[i * DH_] = hst[i];
}

__global__ void __launch_bounds__(64)
scan_phaseB(const float* __restrict__ alog, const float* __restrict__ st,
            float* __restrict__ hin)
{
    const int bh = blockIdx.x;
    const int h = bh & 15;
    const int j = threadIdx.x;

    float aT[NST_];
    #pragma unroll
    for (int i = 0; i < NST_; i++) {
        float a = 1.f / (1.f + expf(-alog[h * NST_ + i]));
        aT[i] = powf(a, (float)T_);
    }
    float Hin[NST_];
    #pragma unroll
    for (int i = 0; i < NST_; i++) Hin[i] = 0.f;

    for (int c = 0; c < P_; c++) {
        float* dst = hin + (((size_t)bh * P_ + c) * NST_) * DH_ + j;
        #pragma unroll
        for (int i = 0; i < NST_; i++) dst[i * DH_] = Hin[i];
        if (c < P_ - 1) {
            const float* src = st + (((size_t)bh * P_ + c) * NST_) * DH_ + j;
            #pragma unroll
            for (int i = 0; i < NST_; i++)
                Hin[i] = fmaf(aT[i], Hin[i], src[i * DH_]);
        }
    }
}

__global__ void __launch_bounds__(64)
scan_phaseC(const float* __restrict__ qkvg, const float* __restrict__ alog,
            const float* __restrict__ hin,
            __nv_bfloat16* __restrict__ Ohi, __nv_bfloat16* __restrict__ Olo)
{
    const int bh = blockIdx.x, c = blockIdx.y;
    const int b = bh >> 4, h = bh & 15;
    const int j = threadIdx.x;

    __shared__ float sQ[4][NST_], sK[4][NST_], sV[4][DH_], sG[4][DH_];

    float alpha[NST_];
    #pragma unroll
    for (int i = 0; i < NST_; i++)
        alpha[i] = 1.f / (1.f + expf(-alog[h * NST_ + i]));
    float hst[NST_];
    {
        const float* src = hin + (((size_t)bh * P_ + c) * NST_) * DH_ + j;
        #pragma unroll
        for (int i = 0; i < NST_; i++) hst[i] = src[i * DH_];
    }

    const int m0 = b * S_ + c * T_;
    const float* rows = qkvg + (size_t)m0 * 4096;
    const int qcol = h * DH_;
    const int kcol = D_ + h * DH_;
    const int vcol = 2 * D_ + h * DH_;
    const int gcol = 3 * D_ + h * DH_;
    __nv_bfloat16* oh = Ohi + (size_t)m0 * D_ + h * DH_ + j;
    __nv_bfloat16* ol = Olo + (size_t)m0 * D_ + h * DH_ + j;

    auto prefetch = [&](int t) {
        const float* row = rows + (size_t)t * 4096;
        const int slot = t & 3;
        if (j < 8)       cp16(smem_u32(&sQ[slot][j * 4]),         row + qcol + j * 4);
        else if (j < 16) cp16(smem_u32(&sK[slot][(j - 8)  * 4]),  row + kcol + (j - 8)  * 4);
        else if (j < 32) cp16(smem_u32(&sV[slot][(j - 16) * 4]),  row + vcol + (j - 16) * 4);
        else if (j < 48) cp16(smem_u32(&sG[slot][(j - 32) * 4]),  row + gcol + (j - 32) * 4);
    };
    prefetch(0); cp_commit();
    prefetch(1); cp_commit();
    prefetch(2); cp_commit();

    for (int t = 0; t < T_; t++) {
        if (t + 3 < T_) { prefetch(t + 3); cp_commit(); }
        if      (t + 3 < T_) cp_wait<3>();
        else if (t + 2 < T_) cp_wait<2>();
        else if (t + 1 < T_) cp_wait<1>();
        else                 cp_wait<0>();
        __syncthreads();
        const int slot = t & 3;
        const float v = sV[slot][j];
        float o0 = 0.f, o1 = 0.f, o2 = 0.f, o3 = 0.f;
        #pragma unroll
        for (int i = 0; i < NST_; i += 4) {
            hst[i]   = fmaf(alpha[i],   hst[i],   sK[slot][i]   * v); o0 = fmaf(sQ[slot][i],   hst[i],   o0);
            hst[i+1] = fmaf(alpha[i+1], hst[i+1], sK[slot][i+1] * v); o1 = fmaf(sQ[slot][i+1], hst[i+1], o1);
            hst[i+2] = fmaf(alpha[i+2], hst[i+2], sK[slot][i+2] * v); o2 = fmaf(sQ[slot][i+2], hst[i+2], o2);
            hst[i+3] = fmaf(alpha[i+3], hst[i+3], sK[slot][i+3] * v); o3 = fmaf(sQ[slot][i+3], hst[i+3], o3);
        }
        const float o = (o0 + o1) + (o2 + o3);
        const float gg = sG[slot][j];
        const float ov = o * gg / (1.f + expf(-gg));
        __nv_bfloat16 hh, ll;
        split2(ov, hh, ll);
        *oh = hh; *ol = ll;
        __syncthreads();
        oh += D_; ol += D_;
    }
}

// ---------------- launch ----------------
extern "C" void kernel_launch(void* const* d_in, const int* in_sizes, int n_in,
                              void* d_out, int out_size)
{
    const int*   tokens = (const int*)  d_in[0];
    const float* emb    = (const float*)d_in[1];
    const float* pos    = (const float*)d_in[2];
    const float* ln_g   = (const float*)d_in[3];
    const float* ln_b   = (const float*)d_in[4];
    const float* wq     = (const float*)d_in[5];
    const float* bq     = (const float*)d_in[6];
    const float* wk     = (const float*)d_in[7];
    const float* bk     = (const float*)d_in[8];
    const float* wv     = (const float*)d_in[9];
    const float* bv     = (const float*)d_in[10];
    const float* wg     = (const float*)d_in[11];
    const float* bg     = (const float*)d_in[12];
    const float* wo     = (const float*)d_in[13];
    const float* bo     = (const float*)d_in[14];
    const float* alogit = (const float*)d_in[15];
    const float* fn_g   = (const float*)d_in[16];
    const float* fn_b   = (const float*)d_in[17];
    const float* head_w = (const float*)d_in[18];
    const float* head_b = (const float*)d_in[19];
    float*       out    = (float*)d_out;

    float *px, *pqkvg, *pst, *phin, *pbcat;
    __nv_bfloat16 *pxnh, *pxnl, *poh, *pol;
    __nv_bfloat16 *wch, *wcl, *woh, *wol, *hwh, *hwl;
    cudaGetSymbolAddress((void**)&px,    g_x);
    cudaGetSymbolAddress((void**)&pqkvg, g_qkvg);
    cudaGetSymbolAddress((void**)&pst,   g_st);
    cudaGetSymbolAddress((void**)&phin,  g_hin);
    cudaGetSymbolAddress((void**)&pbcat, g_bcat);
    cudaGetSymbolAddress((void**)&pxnh,  g_xn_hi);
    cudaGetSymbolAddress((void**)&pxnl,  g_xn_lo);
    cudaGetSymbolAddress((void**)&poh,   g_o_hi);
    cudaGetSymbolAddress((void**)&pol,   g_o_lo);
    cudaGetSymbolAddress((void**)&wch,   g_wc_hi); cudaGetSymbolAddress((void**)&wcl, g_wc_lo);
    cudaGetSymbolAddress((void**)&woh,   g_wo_hi); cudaGetSymbolAddress((void**)&wol, g_wo_lo);
    cudaGetSymbolAddress((void**)&hwh,   g_hw_hi); cudaGetSymbolAddress((void**)&hwl, g_hw_lo);

    constexpr int SMEM_128 = 3 * (128 + 128) * 128;   // 98304
    constexpr int SMEM_32  = 3 * (32  + 128) * 128;   // 61440
    cudaFuncSetAttribute((gemm_mma<128, false>), cudaFuncAttributeMaxDynamicSharedMemorySize, SMEM_128);
    cudaFuncSetAttribute((gemm_mma<128, true >), cudaFuncAttributeMaxDynamicSharedMemorySize, SMEM_128);
    cudaFuncSetAttribute((gemm_mma<32,  false>), cudaFuncAttributeMaxDynamicSharedMemorySize, SMEM_32);

    // launch order: harness prepends 2 launches; ncu -s 5 profiles overall #5
    // = our #3 = the first QKVG GEMM.
    embed_kernel<<<(M_ * D_ / 4) / 256, 256>>>(tokens, emb, pos, px);            // 0
    constexpr int CVT_TOT = (L_*4*D_*D_ + L_*D_*D_ + VOCAB_*D_ + L_*4*D_) / 4;
    cvt_all<<<(CVT_TOT + 255) / 256, 256>>>(wq, wk, wv, wg, wo, head_w,
                                            bq, bk, bv, bg,
                                            wch, wcl, woh, wol, hwh, hwl, pbcat); // 1

    const dim3 qkvg_grid(4 * D_ / 128, M_ / 128);   // (32, 32) = 1024 CTAs
    const dim3 wo_grid(D_ / 128, M_ / 128);         // (8, 32)  = 256 CTAs
    const dim3 head_grid(1, M_ / 32);               // (1, 128) = 128 CTAs
    const size_t PIECE = (size_t)D_ * D_;

    for (int l = 0; l < L_; l++) {
        const size_t wOff = (size_t)l * PIECE;
        const float* alog = alogit + (size_t)l * H_ * NST_;

        ln_bf16_kernel<<<M_, 256>>>(px, ln_g + l * D_, ln_b + l * D_, pxnh, pxnl); // 2

        gemm_mma<128, false><<<qkvg_grid, 256, SMEM_128>>>(pxnh, pxnl,             // 3 <- profiled
            wch + (size_t)l * 4 * PIECE, wcl + (size_t)l * 4 * PIECE,
            pbcat + l * 4 * D_, nullptr, pqkvg, 4 * D_);

        scan_phaseA<<<dim3(B_ * H_, P_ - 1), 64>>>(pqkvg, alog, pst);
        scan_phaseB<<<B_ * H_, 64>>>(alog, pst, phin);
        scan_phaseC<<<dim3(B_ * H_, P_), 64>>>(pqkvg, alog, phin, poh, pol);

        gemm_mma<128, true><<<wo_grid, 256, SMEM_128>>>(poh, pol, woh + wOff, wol + wOff,
                                                        bo + l * D_, px, px, D_);
    }

    ln_bf16_kernel<<<M_, 256>>>(px, fn_g, fn_b, pxnh, pxnl);
    gemm_mma<32, false><<<head_grid, 256, SMEM_32>>>(pxnh, pxnl, hwh, hwl,
                                                     head_b, nullptr, out, VOCAB_);
}

// round 9
// speedup vs baseline: 3.9169x; 1.0428x over previous
#include <cuda_runtime.h>
#include <cuda_bf16.h>
#include <math.h>
#include <stdint.h>

// ---------------- problem constants ----------------
constexpr int B_    = 8;
constexpr int S_    = 512;
constexpr int D_    = 1024;
constexpr int H_    = 16;
constexpr int DH_   = 64;
constexpr int NST_  = 32;
constexpr int L_    = 2;
constexpr int VOCAB_= 128;
constexpr int M_    = B_ * S_;   // 4096
constexpr int K_    = D_;        // 1024
constexpr int BKc_  = 32;        // K per stage
constexpr int NS_   = K_ / BKc_; // 32 stages
constexpr int T_    = 64;        // scan chunk length
constexpr int P_    = S_ / T_;   // 8 chunks

// ---------------- scratch (static device globals) ----------------
__device__ float g_x   [M_ * D_];
__device__ float g_qkvg[M_ * 4 * D_];
__device__ float g_st  [B_*H_ * P_ * NST_ * DH_];
__device__ int   g_flags[L_ * B_*H_ * P_];
__device__ float g_bcat[L_ * 4 * D_];
__device__ __nv_bfloat16 g_xn_hi[M_ * D_], g_xn_lo[M_ * D_];
__device__ __nv_bfloat16 g_o_hi [M_ * D_], g_o_lo [M_ * D_];
__device__ __nv_bfloat16 g_wc_hi[L_*4*D_*D_], g_wc_lo[L_*4*D_*D_];
__device__ __nv_bfloat16 g_wo_hi[L_*D_*D_],   g_wo_lo[L_*D_*D_];
__device__ __nv_bfloat16 g_hw_hi[VOCAB_*D_],  g_hw_lo[VOCAB_*D_];

// ---------------- PTX helpers (baseline sm_80-era ISA only) ----------------
__device__ __forceinline__ uint32_t smem_u32(const void* p) {
    uint32_t a;
    asm("{ .reg .u64 t; cvta.to.shared.u64 t, %1; cvt.u32.u64 %0, t; }" : "=r"(a) : "l"(p));
    return a;
}
__device__ __forceinline__ void cp16(uint32_t dst, const void* src) {
    asm volatile("cp.async.cg.shared.global [%0], [%1], 16;" :: "r"(dst), "l"(src));
}
__device__ __forceinline__ void cp_commit() {
    asm volatile("cp.async.commit_group;" ::: "memory");
}
template<int N>
__device__ __forceinline__ void cp_wait() {
    asm volatile("cp.async.wait_group %0;" :: "n"(N) : "memory");
}
__device__ __forceinline__ void ldsm4(uint32_t* r, uint32_t addr) {
    asm volatile("ldmatrix.sync.aligned.m8n8.x4.shared.b16 {%0,%1,%2,%3}, [%4];"
        : "=r"(r[0]), "=r"(r[1]), "=r"(r[2]), "=r"(r[3]) : "r"(addr));
}
__device__ __forceinline__ void mma_bf16(float* c, const uint32_t* a, const uint32_t* b) {
    asm volatile(
        "mma.sync.aligned.m16n8k16.row.col.f32.bf16.bf16.f32 "
        "{%0,%1,%2,%3}, {%4,%5,%6,%7}, {%8,%9}, {%0,%1,%2,%3};"
        : "+f"(c[0]), "+f"(c[1]), "+f"(c[2]), "+f"(c[3])
        : "r"(a[0]), "r"(a[1]), "r"(a[2]), "r"(a[3]), "r"(b[0]), "r"(b[1]));
}
__device__ __forceinline__ void split2(float v, __nv_bfloat16& h, __nv_bfloat16& l) {
    h = __float2bfloat16(v);
    l = __float2bfloat16(v - __bfloat162float(h));
}
__device__ __forceinline__ int ld_acquire(const int* p) {
    int v;
    asm volatile("ld.global.acquire.gpu.b32 %0, [%1];" : "=r"(v) : "l"(p) : "memory");
    return v;
}

// ---------------- fused weight cvt + bias pack + embed + flag zero ----------------
__global__ void __launch_bounds__(256)
cvt_all(const float* __restrict__ wq, const float* __restrict__ wk,
        const float* __restrict__ wv, const float* __restrict__ wg,
        const float* __restrict__ wo, const float* __restrict__ hw,
        const float* __restrict__ bq, const float* __restrict__ bk,
        const float* __restrict__ bv, const float* __restrict__ bg,
        const int* __restrict__ tokens, const float* __restrict__ emb,
        const float* __restrict__ pos,
        __nv_bfloat16* __restrict__ wch, __nv_bfloat16* __restrict__ wcl,
        __nv_bfloat16* __restrict__ woh, __nv_bfloat16* __restrict__ wol,
        __nv_bfloat16* __restrict__ hwh, __nv_bfloat16* __restrict__ hwl,
        float* __restrict__ bcat, float* __restrict__ x, int* __restrict__ flags)
{
    constexpr int PC4 = D_ * D_ / 4;
    constexpr int WC4 = L_ * 4 * PC4;
    constexpr int WO4 = L_ * PC4;
    constexpr int HW4 = VOCAB_ * D_ / 4;
    constexpr int BC4 = L_ * 4 * D_ / 4;
    constexpr int EMB4= M_ * D_ / 4;
    constexpr int FLG = L_ * B_ * H_ * P_;    // 2048 ints
    int idx = blockIdx.x * 256 + threadIdx.x;
    const float4* src;
    __nv_bfloat16 *dh, *dl;
    int d4;
    if (idx < WC4) {
        int q   = idx >> 18;
        int p   = q & 3;
        int off = idx & (PC4 - 1);
        int l   = q >> 2;
        const float* s = (p == 0) ? wq : (p == 1) ? wk : (p == 2) ? wv : wg;
        src = reinterpret_cast<const float4*>(s) + (size_t)l * PC4 + off;
        dh = wch; dl = wcl; d4 = idx;
    } else if (idx < WC4 + WO4) {
        int j = idx - WC4;
        src = reinterpret_cast<const float4*>(wo) + j;
        dh = woh; dl = wol; d4 = j;
    } else if (idx < WC4 + WO4 + HW4) {
        int j = idx - WC4 - WO4;
        src = reinterpret_cast<const float4*>(hw) + j;
        dh = hwh; dl = hwl; d4 = j;
    } else if (idx < WC4 + WO4 + HW4 + BC4) {
        int j  = idx - WC4 - WO4 - HW4;
        int p4 = j & 255;
        int p  = (j >> 8) & 3;
        int l  = j >> 10;
        const float* s = (p == 0) ? bq : (p == 1) ? bk : (p == 2) ? bv : bg;
        float4 v = reinterpret_cast<const float4*>(s + (size_t)l * D_)[p4];
        reinterpret_cast<float4*>(bcat)[j] = v;
        return;
    } else if (idx < WC4 + WO4 + HW4 + BC4 + EMB4) {
        int j   = idx - WC4 - WO4 - HW4 - BC4;
        int row = j >> 8;
        int c4  = j & 255;
        int s   = row & (S_ - 1);
        int tok = tokens[row];
        float4 e = reinterpret_cast<const float4*>(emb + (size_t)tok * D_)[c4];
        float4 p = reinterpret_cast<const float4*>(pos + (size_t)s   * D_)[c4];
        e.x += p.x; e.y += p.y; e.z += p.z; e.w += p.w;
        reinterpret_cast<float4*>(x)[j] = e;
        return;
    } else if (idx < WC4 + WO4 + HW4 + BC4 + EMB4 + FLG) {
        flags[idx - WC4 - WO4 - HW4 - BC4 - EMB4] = 0;
        return;
    } else return;

    float4 v = *src;
    __nv_bfloat16 h[4], l[4];
    split2(v.x, h[0], l[0]); split2(v.y, h[1], l[1]);
    split2(v.z, h[2], l[2]); split2(v.w, h[3], l[3]);
    reinterpret_cast<uint2*>(dh)[d4] = *reinterpret_cast<uint2*>(h);
    reinterpret_cast<uint2*>(dl)[d4] = *reinterpret_cast<uint2*>(l);
}

// ---------------- layernorm -> bf16 hi/lo ----------------
__global__ void __launch_bounds__(256)
ln_bf16_kernel(const float* __restrict__ x,
               const float* __restrict__ gw,
               const float* __restrict__ bw,
               __nv_bfloat16* __restrict__ yhi,
               __nv_bfloat16* __restrict__ ylo)
{
    int row = blockIdx.x;
    int t   = threadIdx.x;
    float4 xv = reinterpret_cast<const float4*>(x + (size_t)row * D_)[t];

    float s  = xv.x + xv.y + xv.z + xv.w;
    float ss = xv.x*xv.x + xv.y*xv.y + xv.z*xv.z + xv.w*xv.w;
    #pragma unroll
    for (int o = 16; o; o >>= 1) {
        s  += __shfl_xor_sync(0xffffffffu, s,  o);
        ss += __shfl_xor_sync(0xffffffffu, ss, o);
    }
    __shared__ float sh_s[8], sh_ss[8];
    int w = t >> 5;
    if ((t & 31) == 0) { sh_s[w] = s; sh_ss[w] = ss; }
    __syncthreads();
    __shared__ float s_mean, s_inv;
    if (w == 0) {
        s  = (t < 8) ? sh_s[t]  : 0.f;
        ss = (t < 8) ? sh_ss[t] : 0.f;
        #pragma unroll
        for (int o = 4; o; o >>= 1) {
            s  += __shfl_xor_sync(0xffffffffu, s,  o);
            ss += __shfl_xor_sync(0xffffffffu, ss, o);
        }
        if (t == 0) {
            float mean = s * (1.f / D_);
            float var  = ss * (1.f / D_) - mean * mean;
            s_mean = mean;
            s_inv  = rsqrtf(var + 1e-5f);
        }
    }
    __syncthreads();
    float mean = s_mean, inv = s_inv;

    float4 gv = reinterpret_cast<const float4*>(gw)[t];
    float4 bv = reinterpret_cast<const float4*>(bw)[t];
    float o0 = (xv.x - mean) * inv * gv.x + bv.x;
    float o1 = (xv.y - mean) * inv * gv.y + bv.y;
    float o2 = (xv.z - mean) * inv * gv.z + bv.z;
    float o3 = (xv.w - mean) * inv * gv.w + bv.w;

    __nv_bfloat16 h[4], l[4];
    split2(o0, h[0], l[0]); split2(o1, h[1], l[1]);
    split2(o2, h[2], l[2]); split2(o3, h[3], l[3]);
    reinterpret_cast<uint2*>(yhi + (size_t)row * D_)[t] = *reinterpret_cast<uint2*>(h);
    reinterpret_cast<uint2*>(ylo + (size_t)row * D_)[t] = *reinterpret_cast<uint2*>(l);
}

// ---------------- HMMA GEMM: C[m,n] = sum_k A[m,k]*W[n,k] + bias (+res) ----
template<int BM, bool RES>
__global__ void __launch_bounds__(256, 2)
gemm_mma(const __nv_bfloat16* __restrict__ Ahi, const __nv_bfloat16* __restrict__ Alo,
         const __nv_bfloat16* __restrict__ Whi, const __nv_bfloat16* __restrict__ Wlo,
         const float* __restrict__ bias, const float* __restrict__ res,
         float* __restrict__ C, int Nn)
{
    constexpr int MT    = BM / 32;
    constexpr int ABYTES= BM * 128;
    constexpr int STAGE = (BM + 128) * 128;
    constexpr int NCHNK = (BM + 128) * 8;
    constexpr int PER   = NCHNK / 256;

    extern __shared__ char smem[];
    const uint32_t sb = smem_u32(smem);

    const int tid  = threadIdx.x;
    const int lane = tid & 31;
    const int wid  = tid >> 5;
    const int wm   = wid & 1;
    const int wn   = wid >> 1;
    const int bm   = blockIdx.y * BM;
    const int bn   = blockIdx.x * 128;

    auto load_stage = [&](int s, int k0) {
        const uint32_t base = sb + (uint32_t)((s % 3) * STAGE);
        #pragma unroll
        for (int i = 0; i < PER; i++) {
            const int g   = tid + i * 256;
            const bool isA = (g < BM * 8);
            const int cid = isA ? g : g - BM * 8;
            const int r   = cid >> 3;
            const int c   = cid & 7;
            const uint32_t dst = base +
                (uint32_t)((isA ? 0 : ABYTES) + r * 128 + ((c ^ (r & 7)) * 16));
            const bool hi = (c < 4);
            const int kof = (c & 3) * 8 + k0;
            const __nv_bfloat16* p = isA
                ? (hi ? Ahi : Alo) + (size_t)(bm + r) * K_ + kof
                : (hi ? Whi : Wlo) + (size_t)(bn + r) * K_ + kof;
            cp16(dst, p);
        }
    };

    float acc[MT][4][4];
    #pragma unroll
    for (int i = 0; i < MT; i++)
        #pragma unroll
        for (int j = 0; j < 4; j++)
            #pragma unroll
            for (int q = 0; q < 4; q++) acc[i][j][q] = 0.f;

    const int a_row = wm * (BM / 2) + (lane & 7) + ((lane >> 3) & 1) * 8;
    const int a_chk = (lane >> 4) & 1;
    const int b_row = wn * 32 + (lane & 7) + ((lane >> 4) & 1) * 8;
    const int b_chk = (lane >> 3) & 1;

    load_stage(0, 0);    cp_commit();
    load_stage(1, BKc_); cp_commit();

    for (int s = 0; s < NS_; s++) {
        if (s + 1 < NS_) cp_wait<1>(); else cp_wait<0>();
        __syncthreads();
        if (s + 2 < NS_) { load_stage(s + 2, (s + 2) * BKc_); cp_commit(); }

        const uint32_t ab = sb + (uint32_t)((s % 3) * STAGE);
        const uint32_t wb = ab + ABYTES;

        #pragma unroll
        for (int kk = 0; kk < 2; kk++) {
            uint32_t ah[MT][4], al[MT][4];
            #pragma unroll
            for (int mt = 0; mt < MT; mt++) {
                const int row = a_row + mt * 16;
                const int ch  = kk * 2 + a_chk;
                ldsm4(ah[mt], ab + row * 128 + (( ch      ^ (row & 7)) * 16));
                ldsm4(al[mt], ab + row * 128 + (((ch + 4) ^ (row & 7)) * 16));
            }
            #pragma unroll
            for (int np = 0; np < 2; np++) {
                const int row = b_row + np * 16;
                const int ch  = kk * 2 + b_chk;
                uint32_t t0[4], t1[4];
                ldsm4(t0, wb + row * 128 + (( ch      ^ (row & 7)) * 16));
                ldsm4(t1, wb + row * 128 + (((ch + 4) ^ (row & 7)) * 16));
                uint32_t bh[2][2] = {{t0[0], t0[1]}, {t0[2], t0[3]}};
                uint32_t bl[2][2] = {{t1[0], t1[1]}, {t1[2], t1[3]}};
                #pragma unroll
                for (int q = 0; q < 2; q++)
                    #pragma unroll
                    for (int mt = 0; mt < MT; mt++)
                        mma_bf16(acc[mt][np*2+q], ah[mt], bh[q]);
                #pragma unroll
                for (int q = 0; q < 2; q++)
                    #pragma unroll
                    for (int mt = 0; mt < MT; mt++)
                        mma_bf16(acc[mt][np*2+q], ah[mt], bl[q]);
                #pragma unroll
                for (int q = 0; q < 2; q++)
                    #pragma unroll
                    for (int mt = 0; mt < MT; mt++)
                        mma_bf16(acc[mt][np*2+q], al[mt], bh[q]);
            }
        }
    }

    const int gid = lane >> 2;
    const int tig = lane & 3;
    #pragma unroll
    for (int mt = 0; mt < MT; mt++) {
        const int row0 = bm + wm * (BM / 2) + mt * 16 + gid;
        #pragma unroll
        for (int nt = 0; nt < 4; nt++) {
            const int col = bn + wn * 32 + nt * 8 + tig * 2;
            const float bx = bias[col], by = bias[col + 1];
            float c0 = acc[mt][nt][0] + bx, c1 = acc[mt][nt][1] + by;
            float c2 = acc[mt][nt][2] + bx, c3 = acc[mt][nt][3] + by;
            if (RES) {
                float2 r0 = *reinterpret_cast<const float2*>(&res[(size_t)row0 * Nn + col]);
                float2 r1 = *reinterpret_cast<const float2*>(&res[(size_t)(row0 + 8) * Nn + col]);
                c0 += r0.x; c1 += r0.y; c2 += r1.x; c3 += r1.y;
            }
            *reinterpret_cast<float2*>(&C[(size_t)row0 * Nn + col])       = make_float2(c0, c1);
            *reinterpret_cast<float2*>(&C[(size_t)(row0 + 8) * Nn + col]) = make_float2(c2, c3);
        }
    }
}

// ---------------- fused chunked scan with decoupled lookback ----------------
// grid (BH=128, P=8), 64 threads. One kernel replaces phases A/B/C.
// Pass 1: local scan (zero init), save o_local + q to smem, publish end state.
// Lookback: fold predecessors' states into Hin (alpha is diagonal -> elementwise).
// Pass 2: propagate Hin, add correction, gate, emit bf16 hi/lo.
__global__ void __launch_bounds__(64)
scan_fused(const float* __restrict__ qkvg, const float* __restrict__ alog,
           float* __restrict__ st, int* __restrict__ flags,
           __nv_bfloat16* __restrict__ Ohi, __nv_bfloat16* __restrict__ Olo)
{
    const int bh = blockIdx.x, c = blockIdx.y;
    const int b = bh >> 4, h = bh & 15;
    const int j = threadIdx.x;

    __shared__ float sQ[4][NST_], sK[4][NST_], sV[4][DH_], sG[4][DH_];
    __shared__ float obuf[T_][DH_];    // 16KB local outputs
    __shared__ float qbuf[T_][NST_];   // 8KB  raw q per step

    float alpha[NST_];
    #pragma unroll
    for (int i = 0; i < NST_; i++)
        alpha[i] = 1.f / (1.f + expf(-alog[h * NST_ + i]));

    float hst[NST_];
    #pragma unroll
    for (int i = 0; i < NST_; i++) hst[i] = 0.f;

    const int m0 = b * S_ + c * T_;
    const float* rows = qkvg + (size_t)m0 * 4096;
    const int qcol = h * DH_;
    const int kcol = D_ + h * DH_;
    const int vcol = 2 * D_ + h * DH_;
    const int gcol = 3 * D_ + h * DH_;

    // ---- pass 1: local scan ----
    auto prefetch1 = [&](int t) {
        const float* row = rows + (size_t)t * 4096;
        const int slot = t & 3;
        if (j < 8)       cp16(smem_u32(&sQ[slot][j * 4]),        row + qcol + j * 4);
        else if (j < 16) cp16(smem_u32(&sK[slot][(j - 8) * 4]),  row + kcol + (j - 8) * 4);
        else if (j < 32) cp16(smem_u32(&sV[slot][(j - 16) * 4]), row + vcol + (j - 16) * 4);
    };
    prefetch1(0); cp_commit();
    prefetch1(1); cp_commit();
    prefetch1(2); cp_commit();

    for (int t = 0; t < T_; t++) {
        if (t + 3 < T_) { prefetch1(t + 3); cp_commit(); }
        if      (t + 3 < T_) cp_wait<3>();
        else if (t + 2 < T_) cp_wait<2>();
        else if (t + 1 < T_) cp_wait<1>();
        else                 cp_wait<0>();
        __syncthreads();
        const int slot = t & 3;
        const float v = sV[slot][j];
        float o0 = 0.f, o1 = 0.f, o2 = 0.f, o3 = 0.f;
        #pragma unroll
        for (int i = 0; i < NST_; i += 4) {
            hst[i]   = fmaf(alpha[i],   hst[i],   sK[slot][i]   * v); o0 = fmaf(sQ[slot][i],   hst[i],   o0);
            hst[i+1] = fmaf(alpha[i+1], hst[i+1], sK[slot][i+1] * v); o1 = fmaf(sQ[slot][i+1], hst[i+1], o1);
            hst[i+2] = fmaf(alpha[i+2], hst[i+2], sK[slot][i+2] * v); o2 = fmaf(sQ[slot][i+2], hst[i+2], o2);
            hst[i+3] = fmaf(alpha[i+3], hst[i+3], sK[slot][i+3] * v); o3 = fmaf(sQ[slot][i+3], hst[i+3], o3);
        }
        obuf[t][j] = (o0 + o1) + (o2 + o3);
        if (j < NST_) qbuf[t][j] = sQ[slot][j];
        __syncthreads();
    }

    // ---- publish local end state (not needed for last chunk) ----
    if (c < P_ - 1) {
        float* dst = st + (((size_t)bh * P_ + c) * NST_) * DH_ + j;
        #pragma unroll
        for (int i = 0; i < NST_; i++) dst[i * DH_] = hst[i];
        __threadfence();
        __syncthreads();
        if (j == 0) atomicExch(&flags[bh * P_ + c], 1);
    }

    // ---- lookback: Hin = sum_d aT^(c-1-d) * st_d ----
    float Hin[NST_];
    #pragma unroll
    for (int i = 0; i < NST_; i++) Hin[i] = 0.f;
    if (c > 0) {
        float aT[NST_];
        #pragma unroll
        for (int i = 0; i < NST_; i++) {
            float a2 = alpha[i];
            #pragma unroll
            for (int q = 0; q < 6; q++) a2 *= a2;   // alpha^64
            aT[i] = a2;
        }
        for (int d = 0; d < c; d++) {
            const int* fp = &flags[bh * P_ + d];
            while (ld_acquire(fp) == 0) { }
            const float* src = st + (((size_t)bh * P_ + d) * NST_) * DH_ + j;
            #pragma unroll
            for (int i = 0; i < NST_; i++)
                Hin[i] = fmaf(aT[i], Hin[i], src[i * DH_]);
        }
    }

    // ---- pass 2: propagate Hin, correct, gate, write ----
    __nv_bfloat16* oh = Ohi + (size_t)m0 * D_ + h * DH_ + j;
    __nv_bfloat16* ol = Olo + (size_t)m0 * D_ + h * DH_ + j;

    auto prefetch2 = [&](int t) {
        const float* row = rows + (size_t)t * 4096;
        const int slot = t & 3;
        if (j < 16) cp16(smem_u32(&sG[slot][j * 4]), row + gcol + j * 4);
    };
    prefetch2(0); cp_commit();
    prefetch2(1); cp_commit();
    prefetch2(2); cp_commit();

    float hp[NST_];
    #pragma unroll
    for (int i = 0; i < NST_; i++) hp[i] = Hin[i];

    for (int t = 0; t < T_; t++) {
        if (t + 3 < T_) { prefetch2(t + 3); cp_commit(); }
        if      (t + 3 < T_) cp_wait<3>();
        else if (t + 2 < T_) cp_wait<2>();
        else if (t + 1 < T_) cp_wait<1>();
        else                 cp_wait<0>();
        __syncthreads();
        const int slot = t & 3;
        float c0 = 0.f, c1 = 0.f, c2 = 0.f, c3 = 0.f;
        #pragma unroll
        for (int i = 0; i < NST_; i += 4) {
            hp[i]   *= alpha[i];   c0 = fmaf(qbuf[t][i],   hp[i],   c0);
            hp[i+1] *= alpha[i+1]; c1 = fmaf(qbuf[t][i+1], hp[i+1], c1);
            hp[i+2] *= alpha[i+2]; c2 = fmaf(qbuf[t][i+2], hp[i+2], c2);
            hp[i+3] *= alpha[i+3]; c3 = fmaf(qbuf[t][i+3], hp[i+3], c3);
        }
        const float o = obuf[t][j] + ((c0 + c1) + (c2 + c3));
        const float gg = sG[slot][j];
        const float ov = o * gg / (1.f + expf(-gg));
        __nv_bfloat16 hh, ll;
        split2(ov, hh, ll);
        *oh = hh; *ol = ll;
        __syncthreads();
        oh += D_; ol += D_;
    }
}

// ---------------- launch ----------------
extern "C" void kernel_launch(void* const* d_in, const int* in_sizes, int n_in,
                              void* d_out, int out_size)
{
    const int*   tokens = (const int*)  d_in[0];
    const float* emb    = (const float*)d_in[1];
    const float* pos    = (const float*)d_in[2];
    const float* ln_g   = (const float*)d_in[3];
    const float* ln_b   = (const float*)d_in[4];
    const float* wq     = (const float*)d_in[5];
    const float* bq     = (const float*)d_in[6];
    const float* wk     = (const float*)d_in[7];
    const float* bk     = (const float*)d_in[8];
    const float* wv     = (const float*)d_in[9];
    const float* bv     = (const float*)d_in[10];
    const float* wg     = (const float*)d_in[11];
    const float* bg     = (const float*)d_in[12];
    const float* wo     = (const float*)d_in[13];
    const float* bo     = (const float*)d_in[14];
    const float* alogit = (const float*)d_in[15];
    const float* fn_g   = (const float*)d_in[16];
    const float* fn_b   = (const float*)d_in[17];
    const float* head_w = (const float*)d_in[18];
    const float* head_b = (const float*)d_in[19];
    float*       out    = (float*)d_out;

    float *px, *pqkvg, *pst, *pbcat;
    int* pflags;
    __nv_bfloat16 *pxnh, *pxnl, *poh, *pol;
    __nv_bfloat16 *wch, *wcl, *woh, *wol, *hwh, *hwl;
    cudaGetSymbolAddress((void**)&px,    g_x);
    cudaGetSymbolAddress((void**)&pqkvg, g_qkvg);
    cudaGetSymbolAddress((void**)&pst,   g_st);
    cudaGetSymbolAddress((void**)&pflags,g_flags);
    cudaGetSymbolAddress((void**)&pbcat, g_bcat);
    cudaGetSymbolAddress((void**)&pxnh,  g_xn_hi);
    cudaGetSymbolAddress((void**)&pxnl,  g_xn_lo);
    cudaGetSymbolAddress((void**)&poh,   g_o_hi);
    cudaGetSymbolAddress((void**)&pol,   g_o_lo);
    cudaGetSymbolAddress((void**)&wch,   g_wc_hi); cudaGetSymbolAddress((void**)&wcl, g_wc_lo);
    cudaGetSymbolAddress((void**)&woh,   g_wo_hi); cudaGetSymbolAddress((void**)&wol, g_wo_lo);
    cudaGetSymbolAddress((void**)&hwh,   g_hw_hi); cudaGetSymbolAddress((void**)&hwl, g_hw_lo);

    constexpr int SMEM_128 = 3 * (128 + 128) * 128;   // 98304
    constexpr int SMEM_32  = 3 * (32  + 128) * 128;   // 61440
    cudaFuncSetAttribute((gemm_mma<128, false>), cudaFuncAttributeMaxDynamicSharedMemorySize, SMEM_128);
    cudaFuncSetAttribute((gemm_mma<128, true >), cudaFuncAttributeMaxDynamicSharedMemorySize, SMEM_128);
    cudaFuncSetAttribute((gemm_mma<32,  false>), cudaFuncAttributeMaxDynamicSharedMemorySize, SMEM_32);

    // launch order: harness prepends 2; ncu -s 5 profiles overall #5 = our #3
    // = the first scan_fused.
    constexpr int CVT_TOT = (L_*4*D_*D_ + L_*D_*D_ + VOCAB_*D_ + L_*4*D_ + M_*D_) / 4
                            + L_ * B_ * H_ * P_;
    cvt_all<<<(CVT_TOT + 255) / 256, 256>>>(wq, wk, wv, wg, wo, head_w,
                                            bq, bk, bv, bg, tokens, emb, pos,
                                            wch, wcl, woh, wol, hwh, hwl,
                                            pbcat, px, pflags);                   // 0

    const dim3 qkvg_grid(4 * D_ / 128, M_ / 128);   // (32, 32) = 1024 CTAs
    const dim3 wo_grid(D_ / 128, M_ / 128);         // (8, 32)  = 256 CTAs
    const dim3 head_grid(1, M_ / 32);               // (1, 128) = 128 CTAs
    const size_t PIECE = (size_t)D_ * D_;

    for (int l = 0; l < L_; l++) {
        const size_t wOff = (size_t)l * PIECE;
        const float* alog = alogit + (size_t)l * H_ * NST_;

        ln_bf16_kernel<<<M_, 256>>>(px, ln_g + l * D_, ln_b + l * D_, pxnh, pxnl); // 1

        gemm_mma<128, false><<<qkvg_grid, 256, SMEM_128>>>(pxnh, pxnl,             // 2
            wch + (size_t)l * 4 * PIECE, wcl + (size_t)l * 4 * PIECE,
            pbcat + l * 4 * D_, nullptr, pqkvg, 4 * D_);

        scan_fused<<<dim3(B_ * H_, P_), 64>>>(pqkvg, alog, pst,                    // 3 <- profiled
            pflags + l * B_ * H_ * P_, poh, pol);

        gemm_mma<128, true><<<wo_grid, 256, SMEM_128>>>(poh, pol, woh + wOff, wol + wOff,
                                                        bo + l * D_, px, px, D_);
    }

    ln_bf16_kernel<<<M_, 256>>>(px, fn_g, fn_b, pxnh, pxnl);
    gemm_mma<32, false><<<head_grid, 256, SMEM_32>>>(pxnh, pxnl, hwh, hwl,
                                                     head_b, nullptr, out, VOCAB_);
}